// round 2
// baseline (speedup 1.0000x reference)
#include <cuda_runtime.h>
#include <math.h>

#define NPIX 4096
#define CDIM 256
#define CBAR 32
#define BATCH 8

// ---- scratch (device globals; no runtime allocation) ----
__device__ float g_xf[BATCH * CBAR * NPIX];                  // 4 MB
__device__ float g_xg[BATCH * CBAR * NPIX];                  // 4 MB
__device__ float g_xh[BATCH * CDIM * NPIX];                  // 32 MB
__device__ float g_invl[BATCH * NPIX];                       // 128 KB
__device__ float g_p[134217728];                             // 512 MB: exp(S), [B][N][N]

// ============================================================================
// Kernel 1: projections.  y[b][o][n] = sum_c W[o][c] * x[b][c][n] + bias[o]
// mode: 0 -> g_xf (O=32), 1 -> g_xg (O=32), 2 -> g_xh (O=256)
// grid: (NPIX/128, O/32, BATCH), block 256
// ============================================================================
__global__ __launch_bounds__(256) void proj_kernel(
    const float* __restrict__ W, const float* __restrict__ bias,
    const float* __restrict__ x, int mode)
{
    __shared__ float Ws[32][33];
    __shared__ float Xs[32][132];

    float* y = (mode == 0) ? g_xf : (mode == 1) ? g_xg : g_xh;
    const int O = (mode == 2) ? CDIM : CBAR;

    const int b  = blockIdx.z;
    const int o0 = blockIdx.y * 32;
    const int n0 = blockIdx.x * 128;
    const int t  = threadIdx.x;
    const int tx = t & 31;        // n: 4 each
    const int ty = t >> 5;        // o: 4 each (8 groups * 4 = 32)

    const float* xb = x + (size_t)b * CDIM * NPIX;

    float acc[4][4] = {};

    for (int k0 = 0; k0 < CDIM; k0 += 32) {
        // W tile: 32 rows x 32 cols
        {
            int o = t >> 3, k4 = (t & 7) << 2;
            float4 w4 = *(const float4*)(W + (size_t)(o0 + o) * CDIM + k0 + k4);
            Ws[o][k4 + 0] = w4.x; Ws[o][k4 + 1] = w4.y;
            Ws[o][k4 + 2] = w4.z; Ws[o][k4 + 3] = w4.w;
        }
        // X tile: 32 rows x 128 cols
        #pragma unroll
        for (int p = 0; p < 4; p++) {
            int idx = t + p * 256;
            int r = idx >> 5, c4 = (idx & 31) << 2;
            float4 v = *(const float4*)(xb + (size_t)(k0 + r) * NPIX + n0 + c4);
            *(float4*)&Xs[r][c4] = v;
        }
        __syncthreads();

        #pragma unroll
        for (int k = 0; k < 32; k++) {
            float a0 = Ws[ty * 4 + 0][k];
            float a1 = Ws[ty * 4 + 1][k];
            float a2 = Ws[ty * 4 + 2][k];
            float a3 = Ws[ty * 4 + 3][k];
            float4 bv = *(float4*)&Xs[k][tx * 4];
            acc[0][0] += a0 * bv.x; acc[0][1] += a0 * bv.y; acc[0][2] += a0 * bv.z; acc[0][3] += a0 * bv.w;
            acc[1][0] += a1 * bv.x; acc[1][1] += a1 * bv.y; acc[1][2] += a1 * bv.z; acc[1][3] += a1 * bv.w;
            acc[2][0] += a2 * bv.x; acc[2][1] += a2 * bv.y; acc[2][2] += a2 * bv.z; acc[2][3] += a2 * bv.w;
            acc[3][0] += a3 * bv.x; acc[3][1] += a3 * bv.y; acc[3][2] += a3 * bv.z; acc[3][3] += a3 * bv.w;
        }
        __syncthreads();
    }

    #pragma unroll
    for (int i = 0; i < 4; i++) {
        int o = o0 + ty * 4 + i;
        float bb = bias[o];
        float4 r;
        r.x = acc[i][0] + bb; r.y = acc[i][1] + bb;
        r.z = acc[i][2] + bb; r.w = acc[i][3] + bb;
        *(float4*)(y + ((size_t)b * O + o) * NPIX + n0 + tx * 4) = r;
    }
}

// ============================================================================
// Kernel 2: scores.  For 64 rows i: stream all j in 64-tiles,
//   s[i][j] = sum_{c<32} xf[c][i]*xg[c][j];  p = expf(s)  -> g_p
//   l_i = sum_j p  -> g_invl = 1/l_i
// No max subtraction needed: |s| <~ 35 << 88 (fp32 exp range), mathematically
// identical to the stable softmax after normalization.
// grid: (NPIX/64, 1, BATCH), block 256 (16x16, 4x4 per thread)
// ============================================================================
__global__ __launch_bounds__(256) void score_kernel()
{
    __shared__ float fs[32][68];
    __shared__ float gs[32][68];

    const int b  = blockIdx.z;
    const int i0 = blockIdx.x * 64;
    const int t  = threadIdx.x;
    const int tx = t & 15;    // j: 4 each
    const int ty = t >> 4;    // i: 4 each

    const float* xf = g_xf + (size_t)b * CBAR * NPIX;
    const float* xg = g_xg + (size_t)b * CBAR * NPIX;
    float* pb = g_p + (size_t)b * NPIX * NPIX;

    // load xf tile [32][64] once
    #pragma unroll
    for (int p = 0; p < 2; p++) {
        int idx = t + p * 256;
        int r = idx >> 4, c4 = (idx & 15) << 2;
        *(float4*)&fs[r][c4] = *(const float4*)(xf + (size_t)r * NPIX + i0 + c4);
    }

    float lsum[4] = {0.f, 0.f, 0.f, 0.f};

    for (int j0 = 0; j0 < NPIX; j0 += 64) {
        #pragma unroll
        for (int p = 0; p < 2; p++) {
            int idx = t + p * 256;
            int r = idx >> 4, c4 = (idx & 15) << 2;
            *(float4*)&gs[r][c4] = *(const float4*)(xg + (size_t)r * NPIX + j0 + c4);
        }
        __syncthreads();

        float s[4][4] = {};
        #pragma unroll
        for (int k = 0; k < 32; k++) {
            float4 av = *(float4*)&fs[k][ty * 4];
            float4 bv = *(float4*)&gs[k][tx * 4];
            s[0][0] += av.x * bv.x; s[0][1] += av.x * bv.y; s[0][2] += av.x * bv.z; s[0][3] += av.x * bv.w;
            s[1][0] += av.y * bv.x; s[1][1] += av.y * bv.y; s[1][2] += av.y * bv.z; s[1][3] += av.y * bv.w;
            s[2][0] += av.z * bv.x; s[2][1] += av.z * bv.y; s[2][2] += av.z * bv.z; s[2][3] += av.z * bv.w;
            s[3][0] += av.w * bv.x; s[3][1] += av.w * bv.y; s[3][2] += av.w * bv.z; s[3][3] += av.w * bv.w;
        }

        #pragma unroll
        for (int i = 0; i < 4; i++) {
            float4 pv;
            pv.x = __expf(s[i][0]); pv.y = __expf(s[i][1]);
            pv.z = __expf(s[i][2]); pv.w = __expf(s[i][3]);
            lsum[i] += (pv.x + pv.y) + (pv.z + pv.w);
            *(float4*)(pb + (size_t)(i0 + ty * 4 + i) * NPIX + j0 + tx * 4) = pv;
        }
        __syncthreads();
    }

    // butterfly reduce over the 16 tx lanes (stays within warp halves)
    #pragma unroll
    for (int off = 8; off > 0; off >>= 1) {
        #pragma unroll
        for (int i = 0; i < 4; i++)
            lsum[i] += __shfl_xor_sync(0xffffffffu, lsum[i], off);
    }
    if (tx == 0) {
        #pragma unroll
        for (int i = 0; i < 4; i++)
            g_invl[b * NPIX + i0 + ty * 4 + i] = 1.0f / lsum[i];
    }
}

// ============================================================================
// Kernel 3: out[b][c][j] = x[b][c][j] + gamma * sum_i xh[c][i]*invl[i]*p[i][j]
// 128x128x8 double-buffered SGEMM, 8x8 per thread. invl folded into B load.
// grid: (NPIX/128, CDIM/128, BATCH), block 256
// ============================================================================
__global__ __launch_bounds__(256, 2) void out_gemm_kernel(
    const float* __restrict__ x, const float* __restrict__ gamma,
    float* __restrict__ out)
{
    __shared__ float As[2][8][128];   // transposed A tile: As[k][m]
    __shared__ float Bs[2][8][128];   // Bs[k][n] (pre-scaled by invl[k])

    const int b  = blockIdx.z;
    const int m0 = blockIdx.y * 128;
    const int n0 = blockIdx.x * 128;
    const int t  = threadIdx.x;
    const int tx = t & 15;    // n: quadrants tx*4 and 64+tx*4
    const int ty = t >> 4;    // m: quadrants ty*4 and 64+ty*4

    const float* A    = g_xh + (size_t)b * CDIM * NPIX;   // [256][4096]
    const float* Bm   = g_p  + (size_t)b * NPIX * NPIX;   // [4096][4096]
    const float* invl = g_invl + b * NPIX;

    const int ar  = t >> 1;          // A load: row 0..127
    const int ac4 = (t & 1) << 2;    //         col {0,4}
    const int br  = t >> 5;          // B load: row 0..7
    const int bc4 = (t & 31) << 2;   //         col 0..124

    float acc[8][8] = {};

    // preload k-tile 0 into buffer 0
    {
        float4 a4 = *(const float4*)(A + (size_t)(m0 + ar) * NPIX + ac4);
        float4 b4 = *(const float4*)(Bm + (size_t)br * NPIX + n0 + bc4);
        float sc = invl[br];
        As[0][ac4 + 0][ar] = a4.x; As[0][ac4 + 1][ar] = a4.y;
        As[0][ac4 + 2][ar] = a4.z; As[0][ac4 + 3][ar] = a4.w;
        float4 bs; bs.x = b4.x * sc; bs.y = b4.y * sc; bs.z = b4.z * sc; bs.w = b4.w * sc;
        *(float4*)&Bs[0][br][bc4] = bs;
    }
    __syncthreads();

    const int NKT = NPIX / 8;   // 512
    for (int kt = 0; kt < NKT; kt++) {
        const int cur = kt & 1;
        float4 a_pre, b_pre; float sc = 0.f;
        const bool has_next = (kt + 1 < NKT);
        if (has_next) {
            int k0n = (kt + 1) * 8;
            a_pre = *(const float4*)(A + (size_t)(m0 + ar) * NPIX + k0n + ac4);
            b_pre = *(const float4*)(Bm + (size_t)(k0n + br) * NPIX + n0 + bc4);
            sc = invl[k0n + br];
        }

        #pragma unroll
        for (int k = 0; k < 8; k++) {
            float4 a0 = *(float4*)&As[cur][k][ty * 4];
            float4 a1 = *(float4*)&As[cur][k][64 + ty * 4];
            float4 b0 = *(float4*)&Bs[cur][k][tx * 4];
            float4 b1 = *(float4*)&Bs[cur][k][64 + tx * 4];
            float av[8] = {a0.x, a0.y, a0.z, a0.w, a1.x, a1.y, a1.z, a1.w};
            float bv[8] = {b0.x, b0.y, b0.z, b0.w, b1.x, b1.y, b1.z, b1.w};
            #pragma unroll
            for (int i = 0; i < 8; i++)
                #pragma unroll
                for (int j = 0; j < 8; j++)
                    acc[i][j] += av[i] * bv[j];
        }

        if (has_next) {
            const int nb = cur ^ 1;
            As[nb][ac4 + 0][ar] = a_pre.x; As[nb][ac4 + 1][ar] = a_pre.y;
            As[nb][ac4 + 2][ar] = a_pre.z; As[nb][ac4 + 3][ar] = a_pre.w;
            float4 bs; bs.x = b_pre.x * sc; bs.y = b_pre.y * sc;
            bs.z = b_pre.z * sc; bs.w = b_pre.w * sc;
            *(float4*)&Bs[nb][br][bc4] = bs;
        }
        __syncthreads();
    }

    // epilogue: out = x + gamma * acc
    const float g = gamma[0];
    const float* xb = x   + (size_t)b * CDIM * NPIX;
    float*       ob = out + (size_t)b * CDIM * NPIX;

    #pragma unroll
    for (int qm = 0; qm < 2; qm++) {
        #pragma unroll
        for (int i = 0; i < 4; i++) {
            int m = m0 + qm * 64 + ty * 4 + i;
            int ai = qm * 4 + i;
            #pragma unroll
            for (int qn = 0; qn < 2; qn++) {
                int n = n0 + qn * 64 + tx * 4;
                int aj = qn * 4;
                float4 xv = *(const float4*)(xb + (size_t)m * NPIX + n);
                float4 r;
                r.x = xv.x + g * acc[ai][aj + 0];
                r.y = xv.y + g * acc[ai][aj + 1];
                r.z = xv.z + g * acc[ai][aj + 2];
                r.w = xv.w + g * acc[ai][aj + 3];
                *(float4*)(ob + (size_t)m * NPIX + n) = r;
            }
        }
    }
}

// ============================================================================
extern "C" void kernel_launch(void* const* d_in, const int* in_sizes, int n_in,
                              void* d_out, int out_size)
{
    const float* x     = (const float*)d_in[0];
    const float* Wf    = (const float*)d_in[1];
    const float* bf    = (const float*)d_in[2];
    const float* Wg    = (const float*)d_in[3];
    const float* bg    = (const float*)d_in[4];
    const float* Wh    = (const float*)d_in[5];
    const float* bh    = (const float*)d_in[6];
    const float* gamma = (const float*)d_in[7];
    float* out = (float*)d_out;

    (void)in_sizes; (void)n_in; (void)out_size;

    dim3 blk(256);
    // projections
    proj_kernel<<<dim3(NPIX / 128, CBAR / 32, BATCH), blk>>>(Wf, bf, x, 0);
    proj_kernel<<<dim3(NPIX / 128, CBAR / 32, BATCH), blk>>>(Wg, bg, x, 1);
    proj_kernel<<<dim3(NPIX / 128, CDIM / 32, BATCH), blk>>>(Wh, bh, x, 2);
    // scores + exp + row sums
    score_kernel<<<dim3(NPIX / 64, 1, BATCH), blk>>>();
    // output GEMM + residual
    out_gemm_kernel<<<dim3(NPIX / 128, CDIM / 128, BATCH), blk>>>(x, gamma, out);
}

// round 7
// speedup vs baseline: 1.5328x; 1.5328x over previous
#include <cuda_runtime.h>
#include <cuda_bf16.h>
#include <math.h>
#include <stdint.h>

#define NPIX 4096
#define CDIM 256
#define CBAR 32
#define BATCH 8

// ---- scratch (device globals; no runtime allocation) ----
__device__ float g_xf[BATCH * CBAR * NPIX];                    // 4 MB
__device__ float g_xg[BATCH * CBAR * NPIX];                    // 4 MB
__device__ float g_xh[BATCH * CDIM * NPIX];                    // 32 MB
__device__ float g_l[BATCH * NPIX];                            // 128 KB
__device__ __nv_bfloat16 g_ph[(size_t)BATCH * NPIX * NPIX];    // 256 MB: hi(exp(S^T))  [b][j][i]
__device__ __nv_bfloat16 g_pl[(size_t)BATCH * NPIX * NPIX];    // 256 MB: lo residual
__device__ __nv_bfloat16 g_ah[BATCH * CDIM * NPIX];            // 16 MB: hi(xh * invl)  [b][c][i]
__device__ __nv_bfloat16 g_al[BATCH * CDIM * NPIX];            // 16 MB: lo residual

// ---- base-ISA helpers (sm_80+; compile clean on sm_100 base target) ----
__device__ __forceinline__ uint32_t smem_u32(const void* p) {
    uint32_t a;
    asm("{ .reg .u64 t; cvta.to.shared.u64 t, %1; cvt.u32.u64 %0, t; }" : "=r"(a) : "l"(p));
    return a;
}
#define CPASYNC16(d, s) asm volatile("cp.async.cg.shared.global [%0], [%1], 16;" :: "r"(d), "l"(s) : "memory")
#define CPCOMMIT()      asm volatile("cp.async.commit_group;" ::: "memory")
#define CPWAIT(n)       asm volatile("cp.async.wait_group %0;" :: "n"(n) : "memory")

__device__ __forceinline__ void ldmx4(uint32_t* r, uint32_t addr) {
    asm volatile("ldmatrix.sync.aligned.m8n8.x4.shared.b16 {%0,%1,%2,%3}, [%4];"
                 : "=r"(r[0]), "=r"(r[1]), "=r"(r[2]), "=r"(r[3]) : "r"(addr));
}
__device__ __forceinline__ void mma16816(float* d, const uint32_t* a, const uint32_t* b) {
    asm volatile("mma.sync.aligned.m16n8k16.row.col.f32.bf16.bf16.f32 "
                 "{%0,%1,%2,%3}, {%4,%5,%6,%7}, {%8,%9}, {%0,%1,%2,%3};"
                 : "+f"(d[0]), "+f"(d[1]), "+f"(d[2]), "+f"(d[3])
                 : "r"(a[0]), "r"(a[1]), "r"(a[2]), "r"(a[3]), "r"(b[0]), "r"(b[1]));
}

// ============================================================================
// Kernel 1: projections.  y[b][o][n] = sum_c W[o][c] * x[b][c][n] + bias[o]
// ============================================================================
__global__ __launch_bounds__(256) void proj_kernel(
    const float* __restrict__ W, const float* __restrict__ bias,
    const float* __restrict__ x, int mode)
{
    __shared__ float Ws[32][33];
    __shared__ float Xs[32][132];

    float* y = (mode == 0) ? g_xf : (mode == 1) ? g_xg : g_xh;
    const int O = (mode == 2) ? CDIM : CBAR;

    const int b  = blockIdx.z;
    const int o0 = blockIdx.y * 32;
    const int n0 = blockIdx.x * 128;
    const int t  = threadIdx.x;
    const int tx = t & 31;
    const int ty = t >> 5;

    const float* xb = x + (size_t)b * CDIM * NPIX;

    float acc[4][4] = {};

    for (int k0 = 0; k0 < CDIM; k0 += 32) {
        {
            int o = t >> 3, k4 = (t & 7) << 2;
            float4 w4 = *(const float4*)(W + (size_t)(o0 + o) * CDIM + k0 + k4);
            Ws[o][k4 + 0] = w4.x; Ws[o][k4 + 1] = w4.y;
            Ws[o][k4 + 2] = w4.z; Ws[o][k4 + 3] = w4.w;
        }
        #pragma unroll
        for (int p = 0; p < 4; p++) {
            int idx = t + p * 256;
            int r = idx >> 5, c4 = (idx & 31) << 2;
            *(float4*)&Xs[r][c4] = *(const float4*)(xb + (size_t)(k0 + r) * NPIX + n0 + c4);
        }
        __syncthreads();

        #pragma unroll
        for (int k = 0; k < 32; k++) {
            float a0 = Ws[ty * 4 + 0][k];
            float a1 = Ws[ty * 4 + 1][k];
            float a2 = Ws[ty * 4 + 2][k];
            float a3 = Ws[ty * 4 + 3][k];
            float4 bv = *(float4*)&Xs[k][tx * 4];
            acc[0][0] += a0 * bv.x; acc[0][1] += a0 * bv.y; acc[0][2] += a0 * bv.z; acc[0][3] += a0 * bv.w;
            acc[1][0] += a1 * bv.x; acc[1][1] += a1 * bv.y; acc[1][2] += a1 * bv.z; acc[1][3] += a1 * bv.w;
            acc[2][0] += a2 * bv.x; acc[2][1] += a2 * bv.y; acc[2][2] += a2 * bv.z; acc[2][3] += a2 * bv.w;
            acc[3][0] += a3 * bv.x; acc[3][1] += a3 * bv.y; acc[3][2] += a3 * bv.z; acc[3][3] += a3 * bv.w;
        }
        __syncthreads();
    }

    #pragma unroll
    for (int i = 0; i < 4; i++) {
        int o = o0 + ty * 4 + i;
        float bb = bias[o];
        float4 r;
        r.x = acc[i][0] + bb; r.y = acc[i][1] + bb;
        r.z = acc[i][2] + bb; r.w = acc[i][3] + bb;
        *(float4*)(y + ((size_t)b * O + o) * NPIX + n0 + tx * 4) = r;
    }
}

// ============================================================================
// Kernel 2a: zero the l accumulator
// ============================================================================
__global__ void zero_l_kernel() {
    int t = blockIdx.x * blockDim.x + threadIdx.x;
    if (t < BATCH * NPIX) g_l[t] = 0.0f;
}

// ============================================================================
// Kernel 2b: scores, transposed store, bf16 hi+lo split.
//   pT[j][i] = exp( sum_c xg[c][j] * xf[c][i] );  l_i accumulated via atomics.
// No max subtraction needed: |s| <~ 35 << 88 (fp32 exp range).
// ============================================================================
__global__ __launch_bounds__(256) void score_kernel()
{
    __shared__ float gs[32][68];
    __shared__ float fs[32][68];
    __shared__ float lred[8][64];

    const int b  = blockIdx.z;
    const int j0 = blockIdx.x * 64;
    const int t  = threadIdx.x;
    const int tx = t & 15;       // i: 4 each
    const int ty = t >> 4;       // j: 4 each
    const int warp = t >> 5, lane = t & 31;

    const float* xf = g_xf + (size_t)b * CBAR * NPIX;
    const float* xg = g_xg + (size_t)b * CBAR * NPIX;
    __nv_bfloat16* ph = g_ph + (size_t)b * NPIX * NPIX;
    __nv_bfloat16* pl = g_pl + (size_t)b * NPIX * NPIX;

    #pragma unroll
    for (int p = 0; p < 2; p++) {
        int idx = t + p * 256;
        int r = idx >> 4, c4 = (idx & 15) << 2;
        *(float4*)&gs[r][c4] = *(const float4*)(xg + (size_t)r * NPIX + j0 + c4);
    }

    for (int i0 = 0; i0 < NPIX; i0 += 64) {
        #pragma unroll
        for (int p = 0; p < 2; p++) {
            int idx = t + p * 256;
            int r = idx >> 4, c4 = (idx & 15) << 2;
            *(float4*)&fs[r][c4] = *(const float4*)(xf + (size_t)r * NPIX + i0 + c4);
        }
        __syncthreads();

        float s[4][4] = {};
        #pragma unroll
        for (int k = 0; k < 32; k++) {
            float4 av = *(float4*)&gs[k][ty * 4];
            float4 bv = *(float4*)&fs[k][tx * 4];
            s[0][0] += av.x * bv.x; s[0][1] += av.x * bv.y; s[0][2] += av.x * bv.z; s[0][3] += av.x * bv.w;
            s[1][0] += av.y * bv.x; s[1][1] += av.y * bv.y; s[1][2] += av.y * bv.z; s[1][3] += av.y * bv.w;
            s[2][0] += av.z * bv.x; s[2][1] += av.z * bv.y; s[2][2] += av.z * bv.z; s[2][3] += av.z * bv.w;
            s[3][0] += av.w * bv.x; s[3][1] += av.w * bv.y; s[3][2] += av.w * bv.z; s[3][3] += av.w * bv.w;
        }

        float li[4] = {0.f, 0.f, 0.f, 0.f};
        #pragma unroll
        for (int jq = 0; jq < 4; jq++) {
            float p0 = __expf(s[jq][0]);
            float p1 = __expf(s[jq][1]);
            float p2 = __expf(s[jq][2]);
            float p3 = __expf(s[jq][3]);
            li[0] += p0; li[1] += p1; li[2] += p2; li[3] += p3;

            __nv_bfloat16 h0 = __float2bfloat16(p0), h1 = __float2bfloat16(p1);
            __nv_bfloat16 h2 = __float2bfloat16(p2), h3 = __float2bfloat16(p3);
            __nv_bfloat16 l0 = __float2bfloat16(p0 - __bfloat162float(h0));
            __nv_bfloat16 l1 = __float2bfloat16(p1 - __bfloat162float(h1));
            __nv_bfloat16 l2 = __float2bfloat16(p2 - __bfloat162float(h2));
            __nv_bfloat16 l3 = __float2bfloat16(p3 - __bfloat162float(h3));

            size_t off = (size_t)(j0 + ty * 4 + jq) * NPIX + i0 + tx * 4;
            ushort4 vh, vl;
            vh.x = __bfloat16_as_ushort(h0); vh.y = __bfloat16_as_ushort(h1);
            vh.z = __bfloat16_as_ushort(h2); vh.w = __bfloat16_as_ushort(h3);
            vl.x = __bfloat16_as_ushort(l0); vl.y = __bfloat16_as_ushort(l1);
            vl.z = __bfloat16_as_ushort(l2); vl.w = __bfloat16_as_ushort(l3);
            *(ushort4*)(ph + off) = vh;
            *(ushort4*)(pl + off) = vl;
        }

        #pragma unroll
        for (int q = 0; q < 4; q++)
            li[q] += __shfl_xor_sync(0xffffffffu, li[q], 16);
        if (lane < 16) {
            #pragma unroll
            for (int q = 0; q < 4; q++)
                lred[warp][lane * 4 + q] = li[q];
        }
        __syncthreads();
        if (t < 64) {
            float s8 = 0.f;
            #pragma unroll
            for (int w = 0; w < 8; w++) s8 += lred[w][t];
            atomicAdd(&g_l[b * NPIX + i0 + t], s8);
        }
        __syncthreads();
    }
}

// ============================================================================
// Kernel 2c: finalize.  A'[c][i] = xh[c][i] / l[i], split into bf16 hi+lo.
// ============================================================================
__global__ __launch_bounds__(256) void finalize_kernel()
{
    int idx = blockIdx.x * blockDim.x + threadIdx.x;
    int b = idx >> 12;
    int i = idx & (NPIX - 1);
    float inv = 1.0f / g_l[idx];

    const float* xh = g_xh + (size_t)b * CDIM * NPIX + i;
    __nv_bfloat16* ah = g_ah + (size_t)b * CDIM * NPIX + i;
    __nv_bfloat16* al = g_al + (size_t)b * CDIM * NPIX + i;

    #pragma unroll 4
    for (int c = 0; c < CDIM; c++) {
        float a = xh[(size_t)c * NPIX] * inv;
        __nv_bfloat16 h = __float2bfloat16(a);
        __nv_bfloat16 l = __float2bfloat16(a - __bfloat162float(h));
        ah[(size_t)c * NPIX] = h;
        al[(size_t)c * NPIX] = l;
    }
}

// ============================================================================
// Kernel 3: output GEMM via mma.sync (bf16 split precision, base sm_100 ISA).
//   D^T[j][c] = sum_i P^T[j][i]*A'[c][i];  acc += Ah*Bh + Al*Bh + Ah*Bl.
// BM=128 (j), BN=256 (all c -> P read ONCE from HBM), BK=32.
// 512 threads = 16 warps (4x4), warp tile 32x64, m16n8k16, ldmatrix, cp.async
// double buffer. 80B smem rows -> conflict-free ldmatrix (L*20 mod 32 distinct).
// Epilogue fuses out = x + gamma * D^T.
// grid: (NPIX/128, BATCH).  dyn smem = 122880 B.
// ============================================================================
#define ROWB 80
#define OFF_AH 0
#define OFF_AL 10240
#define OFF_BH 20480
#define OFF_BL 40960
#define STAGE  61440

__global__ __launch_bounds__(512, 1) void out_gemm_mma(
    const float* __restrict__ x, const float* __restrict__ gamma,
    float* __restrict__ out)
{
    extern __shared__ char smem[];
    const uint32_t sb = smem_u32(smem);

    const int b  = blockIdx.y;
    const int m0 = blockIdx.x * 128;
    const int t  = threadIdx.x;
    const int warp = t >> 5, lane = t & 31;
    const int wm = (warp & 3) * 32;      // j offset within block
    const int wn = (warp >> 2) * 64;     // c offset

    const __nv_bfloat16* ph = g_ph + (size_t)b * NPIX * NPIX;
    const __nv_bfloat16* pl = g_pl + (size_t)b * NPIX * NPIX;
    const __nv_bfloat16* ah = g_ah + (size_t)b * CDIM * NPIX;
    const __nv_bfloat16* al = g_al + (size_t)b * CDIM * NPIX;

    const int ar = t >> 2, ac = (t & 3) << 3;   // A: 512 tasks (row, 8-half col)
    float acc[2][8][4];
    #pragma unroll
    for (int i = 0; i < 2; i++)
        #pragma unroll
        for (int j = 0; j < 8; j++)
            #pragma unroll
            for (int q = 0; q < 4; q++) acc[i][j][q] = 0.f;

    // ldmatrix lane offsets
    const int a_row = lane & 15, a_k16 = (lane >> 4) << 4;   // A m16k16 frag
    const int b_row = (lane & 7) + ((lane >> 4) & 1) * 8;    // B x4 (two n8 groups)
    const int b_k16 = ((lane >> 3) & 1) * 16;

    const int NCH = NPIX / 32;   // 128 k-chunks

    // ---- prologue: load chunk 0 into stage 0 ----
    {
        const uint32_t st = sb;
        const __nv_bfloat16* gh = ph + (size_t)(m0 + ar) * NPIX + ac;
        const __nv_bfloat16* gl = pl + (size_t)(m0 + ar) * NPIX + ac;
        uint32_t d = st + ar * ROWB + ((t & 3) << 4);
        CPASYNC16(d + OFF_AH, gh);
        CPASYNC16(d + OFF_AL, gl);
        #pragma unroll
        for (int q = 0; q < 2; q++) {
            int id = t + q * 512;
            int r = id >> 2, c8 = (id & 3) << 3;
            const __nv_bfloat16* bh_ = ah + (size_t)r * NPIX + c8;
            const __nv_bfloat16* bl_ = al + (size_t)r * NPIX + c8;
            uint32_t db = st + r * ROWB + ((id & 3) << 4);
            CPASYNC16(db + OFF_BH, bh_);
            CPASYNC16(db + OFF_BL, bl_);
        }
        CPCOMMIT();
    }

    for (int kt = 0; kt < NCH; kt++) {
        const int s = kt & 1;
        if (kt + 1 < NCH) {
            // issue next chunk into the other stage
            const int i0 = (kt + 1) * 32;
            const uint32_t st = sb + (s ^ 1) * STAGE;
            const __nv_bfloat16* gh = ph + (size_t)(m0 + ar) * NPIX + i0 + ac;
            const __nv_bfloat16* gl = pl + (size_t)(m0 + ar) * NPIX + i0 + ac;
            uint32_t d = st + ar * ROWB + ((t & 3) << 4);
            CPASYNC16(d + OFF_AH, gh);
            CPASYNC16(d + OFF_AL, gl);
            #pragma unroll
            for (int q = 0; q < 2; q++) {
                int id = t + q * 512;
                int r = id >> 2, c8 = (id & 3) << 3;
                const __nv_bfloat16* bh_ = ah + (size_t)r * NPIX + i0 + c8;
                const __nv_bfloat16* bl_ = al + (size_t)r * NPIX + i0 + c8;
                uint32_t db = st + r * ROWB + ((id & 3) << 4);
                CPASYNC16(db + OFF_BH, bh_);
                CPASYNC16(db + OFF_BL, bl_);
            }
            CPCOMMIT();
            CPWAIT(1);
        } else {
            CPWAIT(0);
        }
        __syncthreads();

        const uint32_t st = sb + s * STAGE;
        #pragma unroll
        for (int ks = 0; ks < 2; ks++) {
            const int kB = ks * 32;   // 16 halves = 32 bytes
            uint32_t a_h[2][4], a_l[2][4];
            #pragma unroll
            for (int ms = 0; ms < 2; ms++) {
                uint32_t ra = st + (wm + ms * 16 + a_row) * ROWB + kB + a_k16;
                ldmx4(a_h[ms], ra + OFF_AH);
                ldmx4(a_l[ms], ra + OFF_AL);
            }
            #pragma unroll
            for (int np = 0; np < 4; np++) {
                uint32_t rb = st + (wn + np * 16 + b_row) * ROWB + kB + b_k16;
                uint32_t b_h[4], b_l[4];
                ldmx4(b_h, rb + OFF_BH);
                ldmx4(b_l, rb + OFF_BL);
                #pragma unroll
                for (int ms = 0; ms < 2; ms++) {
                    #pragma unroll
                    for (int nh = 0; nh < 2; nh++) {
                        float* d = acc[ms][np * 2 + nh];
                        mma16816(d, a_h[ms], b_h + 2 * nh);
                        mma16816(d, a_l[ms], b_h + 2 * nh);
                        mma16816(d, a_h[ms], b_l + 2 * nh);
                    }
                }
            }
        }
        __syncthreads();
    }

    // epilogue: out[c][j] = x[c][j] + g * D^T[j][c]
    const float g = gamma[0];
    const float* xb = x   + (size_t)b * CDIM * NPIX;
    float*       ob = out + (size_t)b * CDIM * NPIX;
    const int jq = lane >> 2, cq = (lane & 3) * 2;

    #pragma unroll
    for (int ms = 0; ms < 2; ms++) {
        #pragma unroll
        for (int ni = 0; ni < 8; ni++) {
            int j = m0 + wm + ms * 16 + jq;
            int c = wn + ni * 8 + cq;
            float* a4 = acc[ms][ni];
            ob[(size_t)c * NPIX + j]            = xb[(size_t)c * NPIX + j]            + g * a4[0];
            ob[(size_t)(c + 1) * NPIX + j]      = xb[(size_t)(c + 1) * NPIX + j]      + g * a4[1];
            ob[(size_t)c * NPIX + j + 8]        = xb[(size_t)c * NPIX + j + 8]        + g * a4[2];
            ob[(size_t)(c + 1) * NPIX + j + 8]  = xb[(size_t)(c + 1) * NPIX + j + 8]  + g * a4[3];
        }
    }
}

// ============================================================================
extern "C" void kernel_launch(void* const* d_in, const int* in_sizes, int n_in,
                              void* d_out, int out_size)
{
    const float* x     = (const float*)d_in[0];
    const float* Wf    = (const float*)d_in[1];
    const float* bf    = (const float*)d_in[2];
    const float* Wg    = (const float*)d_in[3];
    const float* bg    = (const float*)d_in[4];
    const float* Wh    = (const float*)d_in[5];
    const float* bh    = (const float*)d_in[6];
    const float* gamma = (const float*)d_in[7];
    float* out = (float*)d_out;

    (void)in_sizes; (void)n_in; (void)out_size;

    cudaFuncSetAttribute(out_gemm_mma, cudaFuncAttributeMaxDynamicSharedMemorySize,
                         2 * STAGE);

    dim3 blk(256);
    zero_l_kernel<<<(BATCH * NPIX + 255) / 256, blk>>>();
    proj_kernel<<<dim3(NPIX / 128, CBAR / 32, BATCH), blk>>>(Wf, bf, x, 0);
    proj_kernel<<<dim3(NPIX / 128, CBAR / 32, BATCH), blk>>>(Wg, bg, x, 1);
    proj_kernel<<<dim3(NPIX / 128, CDIM / 32, BATCH), blk>>>(Wh, bh, x, 2);
    score_kernel<<<dim3(NPIX / 64, 1, BATCH), blk>>>();
    finalize_kernel<<<BATCH * NPIX / 256, blk>>>();
    out_gemm_mma<<<dim3(NPIX / 128, BATCH), 512, 2 * STAGE>>>(x, gamma, out);
}

// round 8
// speedup vs baseline: 1.8447x; 1.2035x over previous
#include <cuda_runtime.h>
#include <cuda_bf16.h>
#include <math.h>
#include <stdint.h>

#define NPIX 4096
#define CDIM 256
#define CBAR 32
#define BATCH 8

// ---- scratch (device globals; no runtime allocation) ----
__device__ float g_xf[BATCH * CBAR * NPIX];                    // 4 MB
__device__ float g_xg[BATCH * CBAR * NPIX];                    // 4 MB
__device__ float g_xh[BATCH * CDIM * NPIX];                    // 32 MB
__device__ float g_l[BATCH * NPIX];                            // 128 KB
__device__ __nv_bfloat16 g_ph[(size_t)BATCH * NPIX * NPIX];    // 256 MB: bf16(exp(S^T)) [b][j][i]
__device__ __nv_bfloat16 g_ah[BATCH * CDIM * NPIX];            // 16 MB: hi(xh * invl)  [b][c][i]
__device__ __nv_bfloat16 g_al[BATCH * CDIM * NPIX];            // 16 MB: lo residual

// ---- base-ISA helpers (sm_80+) ----
__device__ __forceinline__ uint32_t smem_u32(const void* p) {
    uint32_t a;
    asm("{ .reg .u64 t; cvta.to.shared.u64 t, %1; cvt.u32.u64 %0, t; }" : "=r"(a) : "l"(p));
    return a;
}
#define CPASYNC16(d, s) asm volatile("cp.async.cg.shared.global [%0], [%1], 16;" :: "r"(d), "l"(s) : "memory")
#define CPCOMMIT()      asm volatile("cp.async.commit_group;" ::: "memory")
#define CPWAIT(n)       asm volatile("cp.async.wait_group %0;" :: "n"(n) : "memory")

__device__ __forceinline__ void ldmx4(uint32_t* r, uint32_t addr) {
    asm volatile("ldmatrix.sync.aligned.m8n8.x4.shared.b16 {%0,%1,%2,%3}, [%4];"
                 : "=r"(r[0]), "=r"(r[1]), "=r"(r[2]), "=r"(r[3]) : "r"(addr));
}
__device__ __forceinline__ void mma16816(float* d, const uint32_t* a, const uint32_t* b) {
    asm volatile("mma.sync.aligned.m16n8k16.row.col.f32.bf16.bf16.f32 "
                 "{%0,%1,%2,%3}, {%4,%5,%6,%7}, {%8,%9}, {%0,%1,%2,%3};"
                 : "+f"(d[0]), "+f"(d[1]), "+f"(d[2]), "+f"(d[3])
                 : "r"(a[0]), "r"(a[1]), "r"(a[2]), "r"(a[3]), "r"(b[0]), "r"(b[1]));
}

// ============================================================================
// Kernel 1: projections.  y[b][o][n] = sum_c W[o][c] * x[b][c][n] + bias[o]
// ============================================================================
__global__ __launch_bounds__(256) void proj_kernel(
    const float* __restrict__ W, const float* __restrict__ bias,
    const float* __restrict__ x, int mode)
{
    __shared__ float Ws[32][33];
    __shared__ float Xs[32][132];

    float* y = (mode == 0) ? g_xf : (mode == 1) ? g_xg : g_xh;
    const int O = (mode == 2) ? CDIM : CBAR;

    const int b  = blockIdx.z;
    const int o0 = blockIdx.y * 32;
    const int n0 = blockIdx.x * 128;
    const int t  = threadIdx.x;
    const int tx = t & 31;
    const int ty = t >> 5;

    const float* xb = x + (size_t)b * CDIM * NPIX;

    float acc[4][4] = {};

    for (int k0 = 0; k0 < CDIM; k0 += 32) {
        {
            int o = t >> 3, k4 = (t & 7) << 2;
            float4 w4 = *(const float4*)(W + (size_t)(o0 + o) * CDIM + k0 + k4);
            Ws[o][k4 + 0] = w4.x; Ws[o][k4 + 1] = w4.y;
            Ws[o][k4 + 2] = w4.z; Ws[o][k4 + 3] = w4.w;
        }
        #pragma unroll
        for (int p = 0; p < 4; p++) {
            int idx = t + p * 256;
            int r = idx >> 5, c4 = (idx & 31) << 2;
            *(float4*)&Xs[r][c4] = *(const float4*)(xb + (size_t)(k0 + r) * NPIX + n0 + c4);
        }
        __syncthreads();

        #pragma unroll
        for (int k = 0; k < 32; k++) {
            float a0 = Ws[ty * 4 + 0][k];
            float a1 = Ws[ty * 4 + 1][k];
            float a2 = Ws[ty * 4 + 2][k];
            float a3 = Ws[ty * 4 + 3][k];
            float4 bv = *(float4*)&Xs[k][tx * 4];
            acc[0][0] += a0 * bv.x; acc[0][1] += a0 * bv.y; acc[0][2] += a0 * bv.z; acc[0][3] += a0 * bv.w;
            acc[1][0] += a1 * bv.x; acc[1][1] += a1 * bv.y; acc[1][2] += a1 * bv.z; acc[1][3] += a1 * bv.w;
            acc[2][0] += a2 * bv.x; acc[2][1] += a2 * bv.y; acc[2][2] += a2 * bv.z; acc[2][3] += a2 * bv.w;
            acc[3][0] += a3 * bv.x; acc[3][1] += a3 * bv.y; acc[3][2] += a3 * bv.z; acc[3][3] += a3 * bv.w;
        }
        __syncthreads();
    }

    #pragma unroll
    for (int i = 0; i < 4; i++) {
        int o = o0 + ty * 4 + i;
        float bb = bias[o];
        float4 r;
        r.x = acc[i][0] + bb; r.y = acc[i][1] + bb;
        r.z = acc[i][2] + bb; r.w = acc[i][3] + bb;
        *(float4*)(y + ((size_t)b * O + o) * NPIX + n0 + tx * 4) = r;
    }
}

// ============================================================================
// Kernel 2a: zero the l accumulator
// ============================================================================
__global__ void zero_l_kernel() {
    int t = blockIdx.x * blockDim.x + threadIdx.x;
    if (t < BATCH * NPIX) g_l[t] = 0.0f;
}

// ============================================================================
// Kernel 2b: scores, transposed store, single bf16.
//   pT[j][i] = exp( sum_c xg[c][j] * xf[c][i] );  l_i accumulated (fp32) via
//   atomics BEFORE quantization, so the softmax denominator is exact.
// No max subtraction needed: |s| <~ 35 << 88 (fp32 exp range).
// ============================================================================
__global__ __launch_bounds__(256) void score_kernel()
{
    __shared__ float gs[32][68];
    __shared__ float fs[32][68];
    __shared__ float lred[8][64];

    const int b  = blockIdx.z;
    const int j0 = blockIdx.x * 64;
    const int t  = threadIdx.x;
    const int tx = t & 15;       // i: 4 each
    const int ty = t >> 4;       // j: 4 each
    const int warp = t >> 5, lane = t & 31;

    const float* xf = g_xf + (size_t)b * CBAR * NPIX;
    const float* xg = g_xg + (size_t)b * CBAR * NPIX;
    __nv_bfloat16* ph = g_ph + (size_t)b * NPIX * NPIX;

    #pragma unroll
    for (int p = 0; p < 2; p++) {
        int idx = t + p * 256;
        int r = idx >> 4, c4 = (idx & 15) << 2;
        *(float4*)&gs[r][c4] = *(const float4*)(xg + (size_t)r * NPIX + j0 + c4);
    }

    for (int i0 = 0; i0 < NPIX; i0 += 64) {
        #pragma unroll
        for (int p = 0; p < 2; p++) {
            int idx = t + p * 256;
            int r = idx >> 4, c4 = (idx & 15) << 2;
            *(float4*)&fs[r][c4] = *(const float4*)(xf + (size_t)r * NPIX + i0 + c4);
        }
        __syncthreads();

        float s[4][4] = {};
        #pragma unroll
        for (int k = 0; k < 32; k++) {
            float4 av = *(float4*)&gs[k][ty * 4];
            float4 bv = *(float4*)&fs[k][tx * 4];
            s[0][0] += av.x * bv.x; s[0][1] += av.x * bv.y; s[0][2] += av.x * bv.z; s[0][3] += av.x * bv.w;
            s[1][0] += av.y * bv.x; s[1][1] += av.y * bv.y; s[1][2] += av.y * bv.z; s[1][3] += av.y * bv.w;
            s[2][0] += av.z * bv.x; s[2][1] += av.z * bv.y; s[2][2] += av.z * bv.z; s[2][3] += av.z * bv.w;
            s[3][0] += av.w * bv.x; s[3][1] += av.w * bv.y; s[3][2] += av.w * bv.z; s[3][3] += av.w * bv.w;
        }

        float li[4] = {0.f, 0.f, 0.f, 0.f};
        #pragma unroll
        for (int jq = 0; jq < 4; jq++) {
            float p0 = __expf(s[jq][0]);
            float p1 = __expf(s[jq][1]);
            float p2 = __expf(s[jq][2]);
            float p3 = __expf(s[jq][3]);
            li[0] += p0; li[1] += p1; li[2] += p2; li[3] += p3;

            ushort4 vh;
            vh.x = __bfloat16_as_ushort(__float2bfloat16(p0));
            vh.y = __bfloat16_as_ushort(__float2bfloat16(p1));
            vh.z = __bfloat16_as_ushort(__float2bfloat16(p2));
            vh.w = __bfloat16_as_ushort(__float2bfloat16(p3));
            size_t off = (size_t)(j0 + ty * 4 + jq) * NPIX + i0 + tx * 4;
            *(ushort4*)(ph + off) = vh;
        }

        #pragma unroll
        for (int q = 0; q < 4; q++)
            li[q] += __shfl_xor_sync(0xffffffffu, li[q], 16);
        if (lane < 16) {
            #pragma unroll
            for (int q = 0; q < 4; q++)
                lred[warp][lane * 4 + q] = li[q];
        }
        __syncthreads();
        if (t < 64) {
            float s8 = 0.f;
            #pragma unroll
            for (int w = 0; w < 8; w++) s8 += lred[w][t];
            atomicAdd(&g_l[b * NPIX + i0 + t], s8);
        }
        __syncthreads();
    }
}

// ============================================================================
// Kernel 2c: finalize.  A'[c][i] = xh[c][i] / l[i], split into bf16 hi+lo.
// ============================================================================
__global__ __launch_bounds__(256) void finalize_kernel()
{
    int idx = blockIdx.x * blockDim.x + threadIdx.x;
    int b = idx >> 12;
    int i = idx & (NPIX - 1);
    float inv = 1.0f / g_l[idx];

    const float* xh = g_xh + (size_t)b * CDIM * NPIX + i;
    __nv_bfloat16* ah = g_ah + (size_t)b * CDIM * NPIX + i;
    __nv_bfloat16* al = g_al + (size_t)b * CDIM * NPIX + i;

    #pragma unroll 4
    for (int c = 0; c < CDIM; c++) {
        float a = xh[(size_t)c * NPIX] * inv;
        __nv_bfloat16 h = __float2bfloat16(a);
        __nv_bfloat16 l = __float2bfloat16(a - __bfloat162float(h));
        ah[(size_t)c * NPIX] = h;
        al[(size_t)c * NPIX] = l;
    }
}

// ============================================================================
// Kernel 3: output GEMM via mma.sync, TWO products (P single bf16):
//   D^T[j][c] = sum_i P[j][i] * (Bh[c][i] + Bl[c][i])
// BM=128 (j), BN=256 (all c -> P read ONCE), BK=32, 512 threads = 16 warps,
// warp tile 32x64, double-buffered cp.async, 80B rows (conflict-free ldmatrix).
// Epilogue fuses out = x + gamma * D^T.  dyn smem = 102400 B.
// ============================================================================
#define ROWB 80
#define OFF_AH 0
#define OFF_BH 10240
#define OFF_BL 30720
#define STAGE  51200

__global__ __launch_bounds__(512, 1) void out_gemm_mma(
    const float* __restrict__ x, const float* __restrict__ gamma,
    float* __restrict__ out)
{
    extern __shared__ char smem[];
    const uint32_t sb = smem_u32(smem);

    const int b  = blockIdx.y;
    const int m0 = blockIdx.x * 128;
    const int t  = threadIdx.x;
    const int warp = t >> 5, lane = t & 31;
    const int wm = (warp & 3) * 32;      // j offset
    const int wn = (warp >> 2) * 64;     // c offset

    const __nv_bfloat16* ph = g_ph + (size_t)b * NPIX * NPIX;
    const __nv_bfloat16* ah = g_ah + (size_t)b * CDIM * NPIX;
    const __nv_bfloat16* al = g_al + (size_t)b * CDIM * NPIX;

    const int ar = t >> 2, ac = (t & 3) << 3;
    float acc[2][8][4];
    #pragma unroll
    for (int i = 0; i < 2; i++)
        #pragma unroll
        for (int j = 0; j < 8; j++)
            #pragma unroll
            for (int q = 0; q < 4; q++) acc[i][j][q] = 0.f;

    const int a_row = lane & 15, a_k16 = (lane >> 4) << 4;
    const int b_row = (lane & 7) + ((lane >> 4) & 1) * 8;
    const int b_k16 = ((lane >> 3) & 1) * 16;

    const int NCH = NPIX / 32;   // 128 k-chunks

    // prologue: chunk 0 -> stage 0
    {
        const uint32_t st = sb;
        const __nv_bfloat16* gh = ph + (size_t)(m0 + ar) * NPIX + ac;
        CPASYNC16(st + ar * ROWB + ((t & 3) << 4) + OFF_AH, gh);
        #pragma unroll
        for (int q = 0; q < 2; q++) {
            int id = t + q * 512;
            int r = id >> 2, c8 = (id & 3) << 3;
            const __nv_bfloat16* bh_ = ah + (size_t)r * NPIX + c8;
            const __nv_bfloat16* bl_ = al + (size_t)r * NPIX + c8;
            uint32_t db = st + r * ROWB + ((id & 3) << 4);
            CPASYNC16(db + OFF_BH, bh_);
            CPASYNC16(db + OFF_BL, bl_);
        }
        CPCOMMIT();
    }

    for (int kt = 0; kt < NCH; kt++) {
        const int s = kt & 1;
        if (kt + 1 < NCH) {
            const int i0 = (kt + 1) * 32;
            const uint32_t st = sb + (s ^ 1) * STAGE;
            const __nv_bfloat16* gh = ph + (size_t)(m0 + ar) * NPIX + i0 + ac;
            CPASYNC16(st + ar * ROWB + ((t & 3) << 4) + OFF_AH, gh);
            #pragma unroll
            for (int q = 0; q < 2; q++) {
                int id = t + q * 512;
                int r = id >> 2, c8 = (id & 3) << 3;
                const __nv_bfloat16* bh_ = ah + (size_t)r * NPIX + i0 + c8;
                const __nv_bfloat16* bl_ = al + (size_t)r * NPIX + i0 + c8;
                uint32_t db = st + r * ROWB + ((id & 3) << 4);
                CPASYNC16(db + OFF_BH, bh_);
                CPASYNC16(db + OFF_BL, bl_);
            }
            CPCOMMIT();
            CPWAIT(1);
        } else {
            CPWAIT(0);
        }
        __syncthreads();

        const uint32_t st = sb + s * STAGE;
        #pragma unroll
        for (int ks = 0; ks < 2; ks++) {
            const int kB = ks * 32;
            uint32_t a_h[2][4];
            #pragma unroll
            for (int ms = 0; ms < 2; ms++) {
                uint32_t ra = st + (wm + ms * 16 + a_row) * ROWB + kB + a_k16;
                ldmx4(a_h[ms], ra + OFF_AH);
            }
            #pragma unroll
            for (int np = 0; np < 4; np++) {
                uint32_t rb = st + (wn + np * 16 + b_row) * ROWB + kB + b_k16;
                uint32_t b_h[4], b_l[4];
                ldmx4(b_h, rb + OFF_BH);
                ldmx4(b_l, rb + OFF_BL);
                #pragma unroll
                for (int ms = 0; ms < 2; ms++) {
                    #pragma unroll
                    for (int nh = 0; nh < 2; nh++) {
                        float* d = acc[ms][np * 2 + nh];
                        mma16816(d, a_h[ms], b_h + 2 * nh);
                        mma16816(d, a_h[ms], b_l + 2 * nh);
                    }
                }
            }
        }
        __syncthreads();
    }

    // epilogue: out[c][j] = x[c][j] + g * D^T[j][c]
    const float g = gamma[0];
    const float* xb = x   + (size_t)b * CDIM * NPIX;
    float*       ob = out + (size_t)b * CDIM * NPIX;
    const int jq = lane >> 2, cq = (lane & 3) * 2;

    #pragma unroll
    for (int ms = 0; ms < 2; ms++) {
        #pragma unroll
        for (int ni = 0; ni < 8; ni++) {
            int j = m0 + wm + ms * 16 + jq;
            int c = wn + ni * 8 + cq;
            float* a4 = acc[ms][ni];
            ob[(size_t)c * NPIX + j]            = xb[(size_t)c * NPIX + j]            + g * a4[0];
            ob[(size_t)(c + 1) * NPIX + j]      = xb[(size_t)(c + 1) * NPIX + j]      + g * a4[1];
            ob[(size_t)c * NPIX + j + 8]        = xb[(size_t)c * NPIX + j + 8]        + g * a4[2];
            ob[(size_t)(c + 1) * NPIX + j + 8]  = xb[(size_t)(c + 1) * NPIX + j + 8]  + g * a4[3];
        }
    }
}

// ============================================================================
extern "C" void kernel_launch(void* const* d_in, const int* in_sizes, int n_in,
                              void* d_out, int out_size)
{
    const float* x     = (const float*)d_in[0];
    const float* Wf    = (const float*)d_in[1];
    const float* bf    = (const float*)d_in[2];
    const float* Wg    = (const float*)d_in[3];
    const float* bg    = (const float*)d_in[4];
    const float* Wh    = (const float*)d_in[5];
    const float* bh    = (const float*)d_in[6];
    const float* gamma = (const float*)d_in[7];
    float* out = (float*)d_out;

    (void)in_sizes; (void)n_in; (void)out_size;

    cudaFuncSetAttribute(out_gemm_mma, cudaFuncAttributeMaxDynamicSharedMemorySize,
                         2 * STAGE);

    dim3 blk(256);
    zero_l_kernel<<<(BATCH * NPIX + 255) / 256, blk>>>();
    proj_kernel<<<dim3(NPIX / 128, CBAR / 32, BATCH), blk>>>(Wf, bf, x, 0);
    proj_kernel<<<dim3(NPIX / 128, CBAR / 32, BATCH), blk>>>(Wg, bg, x, 1);
    proj_kernel<<<dim3(NPIX / 128, CDIM / 32, BATCH), blk>>>(Wh, bh, x, 2);
    score_kernel<<<dim3(NPIX / 64, 1, BATCH), blk>>>();
    finalize_kernel<<<BATCH * NPIX / 256, blk>>>();
    out_gemm_mma<<<dim3(NPIX / 128, BATCH), 512, 2 * STAGE>>>(x, gamma, out);
}

// round 9
// speedup vs baseline: 2.0467x; 1.1095x over previous
#include <cuda_runtime.h>
#include <cuda_bf16.h>
#include <math.h>
#include <stdint.h>

#define NPIX 4096
#define CDIM 256
#define CBAR 32
#define BATCH 8

// ---- scratch (device globals; no runtime allocation) ----
__device__ float g_xh[BATCH * CDIM * NPIX];                    // 32 MB
__device__ float g_l[BATCH * NPIX];                            // 128 KB
__device__ __nv_bfloat16 g_xfh[BATCH * NPIX * CBAR];           // 2 MB  [b][n][c] hi
__device__ __nv_bfloat16 g_xfl[BATCH * NPIX * CBAR];           // 2 MB  lo
__device__ __nv_bfloat16 g_xgh[BATCH * NPIX * CBAR];           // 2 MB
__device__ __nv_bfloat16 g_xgl[BATCH * NPIX * CBAR];           // 2 MB
__device__ __nv_bfloat16 g_ph[(size_t)BATCH * NPIX * NPIX];    // 256 MB: bf16(exp(S^T)) [b][j][i]
__device__ __nv_bfloat16 g_ah[BATCH * CDIM * NPIX];            // 16 MB: hi(xh * invl)  [b][c][i]
__device__ __nv_bfloat16 g_al[BATCH * CDIM * NPIX];            // 16 MB: lo residual

// ---- base-ISA helpers (sm_80+) ----
__device__ __forceinline__ uint32_t smem_u32(const void* p) {
    uint32_t a;
    asm("{ .reg .u64 t; cvta.to.shared.u64 t, %1; cvt.u32.u64 %0, t; }" : "=r"(a) : "l"(p));
    return a;
}
#define CPASYNC16(d, s) asm volatile("cp.async.cg.shared.global [%0], [%1], 16;" :: "r"(d), "l"(s) : "memory")
#define CPCOMMIT()      asm volatile("cp.async.commit_group;" ::: "memory")
#define CPWAIT(n)       asm volatile("cp.async.wait_group %0;" :: "n"(n) : "memory")

__device__ __forceinline__ void ldmx4(uint32_t* r, uint32_t addr) {
    asm volatile("ldmatrix.sync.aligned.m8n8.x4.shared.b16 {%0,%1,%2,%3}, [%4];"
                 : "=r"(r[0]), "=r"(r[1]), "=r"(r[2]), "=r"(r[3]) : "r"(addr));
}
__device__ __forceinline__ void mma16816(float* d, const uint32_t* a, const uint32_t* b) {
    asm volatile("mma.sync.aligned.m16n8k16.row.col.f32.bf16.bf16.f32 "
                 "{%0,%1,%2,%3}, {%4,%5,%6,%7}, {%8,%9}, {%0,%1,%2,%3};"
                 : "+f"(d[0]), "+f"(d[1]), "+f"(d[2]), "+f"(d[3])
                 : "r"(a[0]), "r"(a[1]), "r"(a[2]), "r"(a[3]), "r"(b[0]), "r"(b[1]));
}

// ============================================================================
// Kernel 1: projections.  y[b][o][n] = sum_c W[o][c] * x[b][c][n] + bias[o]
// mode 0/1 (xf/xg): write TRANSPOSED bf16 hi/lo [b][n][32c]  (feeds score mma)
// mode 2   (xh)   : write fp32 [b][c][n]                     (feeds finalize)
// ============================================================================
__global__ __launch_bounds__(256) void proj_kernel(
    const float* __restrict__ W, const float* __restrict__ bias,
    const float* __restrict__ x, int mode)
{
    __shared__ float Ws[32][33];
    __shared__ float Xs[32][132];

    const int O = (mode == 2) ? CDIM : CBAR;

    const int b  = blockIdx.z;
    const int o0 = blockIdx.y * 32;
    const int n0 = blockIdx.x * 128;
    const int t  = threadIdx.x;
    const int tx = t & 31;
    const int ty = t >> 5;

    const float* xb = x + (size_t)b * CDIM * NPIX;

    float acc[4][4] = {};

    for (int k0 = 0; k0 < CDIM; k0 += 32) {
        {
            int o = t >> 3, k4 = (t & 7) << 2;
            float4 w4 = *(const float4*)(W + (size_t)(o0 + o) * CDIM + k0 + k4);
            Ws[o][k4 + 0] = w4.x; Ws[o][k4 + 1] = w4.y;
            Ws[o][k4 + 2] = w4.z; Ws[o][k4 + 3] = w4.w;
        }
        #pragma unroll
        for (int p = 0; p < 4; p++) {
            int idx = t + p * 256;
            int r = idx >> 5, c4 = (idx & 31) << 2;
            *(float4*)&Xs[r][c4] = *(const float4*)(xb + (size_t)(k0 + r) * NPIX + n0 + c4);
        }
        __syncthreads();

        #pragma unroll
        for (int k = 0; k < 32; k++) {
            float a0 = Ws[ty * 4 + 0][k];
            float a1 = Ws[ty * 4 + 1][k];
            float a2 = Ws[ty * 4 + 2][k];
            float a3 = Ws[ty * 4 + 3][k];
            float4 bv = *(float4*)&Xs[k][tx * 4];
            acc[0][0] += a0 * bv.x; acc[0][1] += a0 * bv.y; acc[0][2] += a0 * bv.z; acc[0][3] += a0 * bv.w;
            acc[1][0] += a1 * bv.x; acc[1][1] += a1 * bv.y; acc[1][2] += a1 * bv.z; acc[1][3] += a1 * bv.w;
            acc[2][0] += a2 * bv.x; acc[2][1] += a2 * bv.y; acc[2][2] += a2 * bv.z; acc[2][3] += a2 * bv.w;
            acc[3][0] += a3 * bv.x; acc[3][1] += a3 * bv.y; acc[3][2] += a3 * bv.z; acc[3][3] += a3 * bv.w;
        }
        __syncthreads();
    }

    if (mode == 2) {
        #pragma unroll
        for (int i = 0; i < 4; i++) {
            int o = o0 + ty * 4 + i;
            float bb = bias[o];
            float4 r;
            r.x = acc[i][0] + bb; r.y = acc[i][1] + bb;
            r.z = acc[i][2] + bb; r.w = acc[i][3] + bb;
            *(float4*)(g_xh + ((size_t)b * CDIM + o) * NPIX + n0 + tx * 4) = r;
        }
    } else {
        __nv_bfloat16* yh = (mode == 0) ? g_xfh : g_xgh;
        __nv_bfloat16* yl = (mode == 0) ? g_xfl : g_xgl;
        float bb[4];
        #pragma unroll
        for (int i = 0; i < 4; i++) bb[i] = bias[ty * 4 + i];
        #pragma unroll
        for (int j = 0; j < 4; j++) {
            int n = n0 + tx * 4 + j;
            ushort4 h4, l4;
            #pragma unroll
            for (int i = 0; i < 4; i++) {
                float a = acc[i][j] + bb[i];
                __nv_bfloat16 h = __float2bfloat16(a);
                __nv_bfloat16 l = __float2bfloat16(a - __bfloat162float(h));
                ((unsigned short*)&h4)[i] = __bfloat16_as_ushort(h);
                ((unsigned short*)&l4)[i] = __bfloat16_as_ushort(l);
            }
            size_t off = ((size_t)b * NPIX + n) * CBAR + ty * 4;
            *(ushort4*)(yh + off) = h4;
            *(ushort4*)(yl + off) = l4;
        }
    }
}

// ============================================================================
// Kernel 2a: zero the l accumulator
// ============================================================================
__global__ void zero_l_kernel() {
    int t = blockIdx.x * blockDim.x + threadIdx.x;
    if (t < BATCH * NPIX) g_l[t] = 0.0f;
}

// ============================================================================
// Kernel 2b: scores on tensor cores.
//   sT[j][i] = sum_c xg[c][j]*xf[c][i]  via mma.sync bf16 3-product
//   (hh + hl + lh; dropped ll term = O(2^-16), δs ~1e-4 abs).
//   p = __expf(s) in fp32 fragments -> bf16 store to g_ph;
//   l_i accumulated EXACT (fp32, pre-quantization) via shfl-reduce + atomics.
// Block: BM=64 j, BN=128 i per iter, K=32. 256 thr = 8 warps (2m x 4n),
// warp tile m32 x n32. A (xg) loaded once; B (xf) double-buffered cp.async.
// dyn smem = 51200 B. grid (NPIX/64, BATCH).
// ============================================================================
#define SROWB 80
#define SA_LO 5120            // A lo offset (64 rows * 80)
#define SB_LO 10240           // B lo offset within stage (128 rows * 80)
#define SB_STAGE 20480
#define SA_BYTES 10240

__global__ __launch_bounds__(256, 2) void score_kernel()
{
    extern __shared__ char smem[];
    const uint32_t sa = smem_u32(smem);           // A: 10240 B
    const uint32_t sb0 = sa + SA_BYTES;           // B stages: 2 x 20480

    const int b  = blockIdx.y;
    const int j0 = blockIdx.x * 64;
    const int t  = threadIdx.x;
    const int warp = t >> 5, lane = t & 31;
    const int wm = (warp & 1) * 32;               // j offset in block
    const int wn = (warp >> 1) * 32;              // i offset in tile

    const __nv_bfloat16* xfh = g_xfh + (size_t)b * NPIX * CBAR;
    const __nv_bfloat16* xfl = g_xfl + (size_t)b * NPIX * CBAR;
    const __nv_bfloat16* xgh = g_xgh + (size_t)b * NPIX * CBAR;
    const __nv_bfloat16* xgl = g_xgl + (size_t)b * NPIX * CBAR;
    __nv_bfloat16* ph = g_ph + (size_t)b * NPIX * NPIX;
    float* lrow = g_l + b * NPIX;

    // ---- load A (xg rows j0..j0+63, hi rows 0-63 / lo rows 64-127) ----
    #pragma unroll
    for (int q = 0; q < 2; q++) {
        int id = t + q * 256;                     // 512 tasks
        int r = id >> 2, g16 = id & 3;            // r: 0..127
        const __nv_bfloat16* src = ((r < 64) ? xgh : xgl) + ((size_t)(j0 + (r & 63))) * CBAR + g16 * 8;
        CPASYNC16(sa + r * SROWB + g16 * 16, src);
    }
    // ---- B iter 0 ----
    #pragma unroll
    for (int q = 0; q < 4; q++) {
        int id = t + q * 256;                     // 1024 tasks
        int r = id >> 2, g16 = id & 3;            // r: 0..255
        const __nv_bfloat16* src = ((r < 128) ? xfh : xfl) + ((size_t)(r & 127)) * CBAR + g16 * 8;
        CPASYNC16(sb0 + r * SROWB + g16 * 16, src);
    }
    CPCOMMIT();

    // ldmatrix lane offsets (same proven patterns as out_gemm)
    const int a_row = lane & 15, a_k16 = (lane >> 4) << 4;
    const int b_row = (lane & 7) + ((lane >> 4) & 1) * 8;
    const int b_k16 = ((lane >> 3) & 1) * 16;

    const int NIT = NPIX / 128;                   // 32 i-tiles

    for (int it = 0; it < NIT; it++) {
        const int s = it & 1;
        if (it + 1 < NIT) {
            const int i0n = (it + 1) * 128;
            const uint32_t st = sb0 + (s ^ 1) * SB_STAGE;
            #pragma unroll
            for (int q = 0; q < 4; q++) {
                int id = t + q * 256;
                int r = id >> 2, g16 = id & 3;
                const __nv_bfloat16* src = ((r < 128) ? xfh : xfl) + ((size_t)(i0n + (r & 127))) * CBAR + g16 * 8;
                CPASYNC16(st + r * SROWB + g16 * 16, src);
            }
            CPCOMMIT();
            CPWAIT(1);
        } else {
            CPWAIT(0);
        }
        __syncthreads();

        const uint32_t stg = sb0 + s * SB_STAGE;
        float sacc[2][4][4];
        #pragma unroll
        for (int m = 0; m < 2; m++)
            #pragma unroll
            for (int n = 0; n < 4; n++)
                #pragma unroll
                for (int q = 0; q < 4; q++) sacc[m][n][q] = 0.f;

        #pragma unroll
        for (int ks = 0; ks < 2; ks++) {
            const int kB = ks * 32;
            uint32_t a_h[2][4], a_l[2][4];
            #pragma unroll
            for (int ms = 0; ms < 2; ms++) {
                uint32_t ra = sa + (wm + ms * 16 + a_row) * SROWB + kB + a_k16;
                ldmx4(a_h[ms], ra);
                ldmx4(a_l[ms], ra + SA_LO);
            }
            #pragma unroll
            for (int np = 0; np < 2; np++) {
                uint32_t rb = stg + (wn + np * 16 + b_row) * SROWB + kB + b_k16;
                uint32_t b_h[4], b_l[4];
                ldmx4(b_h, rb);
                ldmx4(b_l, rb + SB_LO);
                #pragma unroll
                for (int ms = 0; ms < 2; ms++) {
                    #pragma unroll
                    for (int nh = 0; nh < 2; nh++) {
                        float* d = sacc[ms][np * 2 + nh];
                        mma16816(d, a_h[ms], b_h + 2 * nh);   // hh
                        mma16816(d, a_h[ms], b_l + 2 * nh);   // hl
                        mma16816(d, a_l[ms], b_h + 2 * nh);   // lh
                    }
                }
            }
        }

        // exp + store + l accumulation
        const int i0 = it * 128;
        #pragma unroll
        for (int nn = 0; nn < 4; nn++) {
            const int icol = i0 + wn + nn * 8 + (lane & 3) * 2;
            float cs0 = 0.f, cs1 = 0.f;
            #pragma unroll
            for (int ms = 0; ms < 2; ms++) {
                float* d = sacc[ms][nn];
                float p0 = __expf(d[0]);
                float p1 = __expf(d[1]);
                float p2 = __expf(d[2]);
                float p3 = __expf(d[3]);
                cs0 += p0 + p2; cs1 += p1 + p3;
                const int j = j0 + wm + ms * 16 + (lane >> 2);
                uint32_t pk01 = ((uint32_t)__bfloat16_as_ushort(__float2bfloat16(p1)) << 16)
                              |  (uint32_t)__bfloat16_as_ushort(__float2bfloat16(p0));
                uint32_t pk23 = ((uint32_t)__bfloat16_as_ushort(__float2bfloat16(p3)) << 16)
                              |  (uint32_t)__bfloat16_as_ushort(__float2bfloat16(p2));
                *(uint32_t*)(ph + (size_t)j * NPIX + icol)       = pk01;
                *(uint32_t*)(ph + (size_t)(j + 8) * NPIX + icol) = pk23;
            }
            // reduce over the 8 row-groups (lanes stride 4)
            #pragma unroll
            for (int off = 4; off <= 16; off <<= 1) {
                cs0 += __shfl_xor_sync(0xffffffffu, cs0, off);
                cs1 += __shfl_xor_sync(0xffffffffu, cs1, off);
            }
            if (lane < 4) {
                atomicAdd(lrow + icol, cs0);
                atomicAdd(lrow + icol + 1, cs1);
            }
        }
        __syncthreads();
    }
}

// ============================================================================
// Kernel 2c: finalize.  A'[c][i] = xh[c][i] / l[i], split into bf16 hi+lo.
// ============================================================================
__global__ __launch_bounds__(256) void finalize_kernel()
{
    int idx = blockIdx.x * blockDim.x + threadIdx.x;
    int b = idx >> 12;
    int i = idx & (NPIX - 1);
    float inv = 1.0f / g_l[idx];

    const float* xh = g_xh + (size_t)b * CDIM * NPIX + i;
    __nv_bfloat16* ah = g_ah + (size_t)b * CDIM * NPIX + i;
    __nv_bfloat16* al = g_al + (size_t)b * CDIM * NPIX + i;

    #pragma unroll 4
    for (int c = 0; c < CDIM; c++) {
        float a = xh[(size_t)c * NPIX] * inv;
        __nv_bfloat16 h = __float2bfloat16(a);
        __nv_bfloat16 l = __float2bfloat16(a - __bfloat162float(h));
        ah[(size_t)c * NPIX] = h;
        al[(size_t)c * NPIX] = l;
    }
}

// ============================================================================
// Kernel 3: output GEMM via mma.sync, TWO products (P single bf16):
//   D^T[j][c] = sum_i P[j][i] * (Bh[c][i] + Bl[c][i])
// BM=128 (j), BN=256 (all c -> P read ONCE), BK=32, 512 threads = 16 warps,
// warp tile 32x64, double-buffered cp.async, 80B rows (conflict-free ldmatrix).
// Epilogue fuses out = x + gamma * D^T.  dyn smem = 102400 B.
// ============================================================================
#define ROWB 80
#define OFF_AH 0
#define OFF_BH 10240
#define OFF_BL 30720
#define STAGE  51200

__global__ __launch_bounds__(512, 1) void out_gemm_mma(
    const float* __restrict__ x, const float* __restrict__ gamma,
    float* __restrict__ out)
{
    extern __shared__ char smem[];
    const uint32_t sb = smem_u32(smem);

    const int b  = blockIdx.y;
    const int m0 = blockIdx.x * 128;
    const int t  = threadIdx.x;
    const int warp = t >> 5, lane = t & 31;
    const int wm = (warp & 3) * 32;      // j offset
    const int wn = (warp >> 2) * 64;     // c offset

    const __nv_bfloat16* ph = g_ph + (size_t)b * NPIX * NPIX;
    const __nv_bfloat16* ah = g_ah + (size_t)b * CDIM * NPIX;
    const __nv_bfloat16* al = g_al + (size_t)b * CDIM * NPIX;

    const int ar = t >> 2, ac = (t & 3) << 3;
    float acc[2][8][4];
    #pragma unroll
    for (int i = 0; i < 2; i++)
        #pragma unroll
        for (int j = 0; j < 8; j++)
            #pragma unroll
            for (int q = 0; q < 4; q++) acc[i][j][q] = 0.f;

    const int a_row = lane & 15, a_k16 = (lane >> 4) << 4;
    const int b_row = (lane & 7) + ((lane >> 4) & 1) * 8;
    const int b_k16 = ((lane >> 3) & 1) * 16;

    const int NCH = NPIX / 32;   // 128 k-chunks

    // prologue: chunk 0 -> stage 0
    {
        const uint32_t st = sb;
        const __nv_bfloat16* gh = ph + (size_t)(m0 + ar) * NPIX + ac;
        CPASYNC16(st + ar * ROWB + ((t & 3) << 4) + OFF_AH, gh);
        #pragma unroll
        for (int q = 0; q < 2; q++) {
            int id = t + q * 512;
            int r = id >> 2, c8 = (id & 3) << 3;
            const __nv_bfloat16* bh_ = ah + (size_t)r * NPIX + c8;
            const __nv_bfloat16* bl_ = al + (size_t)r * NPIX + c8;
            uint32_t db = st + r * ROWB + ((id & 3) << 4);
            CPASYNC16(db + OFF_BH, bh_);
            CPASYNC16(db + OFF_BL, bl_);
        }
        CPCOMMIT();
    }

    for (int kt = 0; kt < NCH; kt++) {
        const int s = kt & 1;
        if (kt + 1 < NCH) {
            const int i0 = (kt + 1) * 32;
            const uint32_t st = sb + (s ^ 1) * STAGE;
            const __nv_bfloat16* gh = ph + (size_t)(m0 + ar) * NPIX + i0 + ac;
            CPASYNC16(st + ar * ROWB + ((t & 3) << 4) + OFF_AH, gh);
            #pragma unroll
            for (int q = 0; q < 2; q++) {
                int id = t + q * 512;
                int r = id >> 2, c8 = (id & 3) << 3;
                const __nv_bfloat16* bh_ = ah + (size_t)r * NPIX + i0 + c8;
                const __nv_bfloat16* bl_ = al + (size_t)r * NPIX + i0 + c8;
                uint32_t db = st + r * ROWB + ((id & 3) << 4);
                CPASYNC16(db + OFF_BH, bh_);
                CPASYNC16(db + OFF_BL, bl_);
            }
            CPCOMMIT();
            CPWAIT(1);
        } else {
            CPWAIT(0);
        }
        __syncthreads();

        const uint32_t st = sb + s * STAGE;
        #pragma unroll
        for (int ks = 0; ks < 2; ks++) {
            const int kB = ks * 32;
            uint32_t a_h[2][4];
            #pragma unroll
            for (int ms = 0; ms < 2; ms++) {
                uint32_t ra = st + (wm + ms * 16 + a_row) * ROWB + kB + a_k16;
                ldmx4(a_h[ms], ra + OFF_AH);
            }
            #pragma unroll
            for (int np = 0; np < 4; np++) {
                uint32_t rb = st + (wn + np * 16 + b_row) * ROWB + kB + b_k16;
                uint32_t b_h[4], b_l[4];
                ldmx4(b_h, rb + OFF_BH);
                ldmx4(b_l, rb + OFF_BL);
                #pragma unroll
                for (int ms = 0; ms < 2; ms++) {
                    #pragma unroll
                    for (int nh = 0; nh < 2; nh++) {
                        float* d = acc[ms][np * 2 + nh];
                        mma16816(d, a_h[ms], b_h + 2 * nh);
                        mma16816(d, a_h[ms], b_l + 2 * nh);
                    }
                }
            }
        }
        __syncthreads();
    }

    // epilogue: out[c][j] = x[c][j] + g * D^T[j][c]
    const float g = gamma[0];
    const float* xb = x   + (size_t)b * CDIM * NPIX;
    float*       ob = out + (size_t)b * CDIM * NPIX;
    const int jq = lane >> 2, cq = (lane & 3) * 2;

    #pragma unroll
    for (int ms = 0; ms < 2; ms++) {
        #pragma unroll
        for (int ni = 0; ni < 8; ni++) {
            int j = m0 + wm + ms * 16 + jq;
            int c = wn + ni * 8 + cq;
            float* a4 = acc[ms][ni];
            ob[(size_t)c * NPIX + j]            = xb[(size_t)c * NPIX + j]            + g * a4[0];
            ob[(size_t)(c + 1) * NPIX + j]      = xb[(size_t)(c + 1) * NPIX + j]      + g * a4[1];
            ob[(size_t)c * NPIX + j + 8]        = xb[(size_t)c * NPIX + j + 8]        + g * a4[2];
            ob[(size_t)(c + 1) * NPIX + j + 8]  = xb[(size_t)(c + 1) * NPIX + j + 8]  + g * a4[3];
        }
    }
}

// ============================================================================
extern "C" void kernel_launch(void* const* d_in, const int* in_sizes, int n_in,
                              void* d_out, int out_size)
{
    const float* x     = (const float*)d_in[0];
    const float* Wf    = (const float*)d_in[1];
    const float* bf    = (const float*)d_in[2];
    const float* Wg    = (const float*)d_in[3];
    const float* bg    = (const float*)d_in[4];
    const float* Wh    = (const float*)d_in[5];
    const float* bh    = (const float*)d_in[6];
    const float* gamma = (const float*)d_in[7];
    float* out = (float*)d_out;

    (void)in_sizes; (void)n_in; (void)out_size;

    cudaFuncSetAttribute(out_gemm_mma, cudaFuncAttributeMaxDynamicSharedMemorySize,
                         2 * STAGE);
    cudaFuncSetAttribute(score_kernel, cudaFuncAttributeMaxDynamicSharedMemorySize,
                         SA_BYTES + 2 * SB_STAGE);

    dim3 blk(256);
    zero_l_kernel<<<(BATCH * NPIX + 255) / 256, blk>>>();
    proj_kernel<<<dim3(NPIX / 128, CBAR / 32, BATCH), blk>>>(Wf, bf, x, 0);
    proj_kernel<<<dim3(NPIX / 128, CBAR / 32, BATCH), blk>>>(Wg, bg, x, 1);
    proj_kernel<<<dim3(NPIX / 128, CDIM / 32, BATCH), blk>>>(Wh, bh, x, 2);
    score_kernel<<<dim3(NPIX / 64, BATCH), blk, SA_BYTES + 2 * SB_STAGE>>>();
    finalize_kernel<<<BATCH * NPIX / 256, blk>>>();
    out_gemm_mma<<<dim3(NPIX / 128, BATCH), 512, 2 * STAGE>>>(x, gamma, out);
}

// round 10
// speedup vs baseline: 2.3141x; 1.1306x over previous
#include <cuda_runtime.h>
#include <cuda_bf16.h>
#include <cuda_fp16.h>
#include <math.h>
#include <stdint.h>

#define NPIX 4096
#define CDIM 256
#define CBAR 32
#define BATCH 8

// ---- scratch (device globals; no runtime allocation) ----
__device__ float g_xh[BATCH * CDIM * NPIX];                    // 32 MB
__device__ float g_l[BATCH * NPIX];                            // 128 KB
__device__ float g_invl[BATCH * NPIX];                         // 128 KB
__device__ __nv_bfloat16 g_xfh[BATCH * NPIX * CBAR];           // [b][n][c] hi
__device__ __nv_bfloat16 g_xfl[BATCH * NPIX * CBAR];
__device__ __nv_bfloat16 g_xgh[BATCH * NPIX * CBAR];
__device__ __nv_bfloat16 g_xgl[BATCH * NPIX * CBAR];
__device__ __nv_bfloat16 g_ph[(size_t)BATCH * NPIX * NPIX];    // 256 MB: bf16(exp(S^T)) [b][j][i]
__device__ __half g_beta[(size_t)BATCH * NPIX * NPIX];         // 256 MB: fp16 beta^T [b][j][i]
__device__ __half g_xh16[BATCH * CDIM * NPIX];                 // 16 MB: fp16(xh) [b][c][i]

// ---- base-ISA helpers (sm_80+) ----
__device__ __forceinline__ uint32_t smem_u32(const void* p) {
    uint32_t a;
    asm("{ .reg .u64 t; cvta.to.shared.u64 t, %1; cvt.u32.u64 %0, t; }" : "=r"(a) : "l"(p));
    return a;
}
#define CPASYNC16(d, s) asm volatile("cp.async.cg.shared.global [%0], [%1], 16;" :: "r"(d), "l"(s) : "memory")
#define CPCOMMIT()      asm volatile("cp.async.commit_group;" ::: "memory")
#define CPWAIT(n)       asm volatile("cp.async.wait_group %0;" :: "n"(n) : "memory")

__device__ __forceinline__ void ldmx4(uint32_t* r, uint32_t addr) {
    asm volatile("ldmatrix.sync.aligned.m8n8.x4.shared.b16 {%0,%1,%2,%3}, [%4];"
                 : "=r"(r[0]), "=r"(r[1]), "=r"(r[2]), "=r"(r[3]) : "r"(addr));
}
__device__ __forceinline__ void mma16816(float* d, const uint32_t* a, const uint32_t* b) {
    asm volatile("mma.sync.aligned.m16n8k16.row.col.f32.bf16.bf16.f32 "
                 "{%0,%1,%2,%3}, {%4,%5,%6,%7}, {%8,%9}, {%0,%1,%2,%3};"
                 : "+f"(d[0]), "+f"(d[1]), "+f"(d[2]), "+f"(d[3])
                 : "r"(a[0]), "r"(a[1]), "r"(a[2]), "r"(a[3]), "r"(b[0]), "r"(b[1]));
}
__device__ __forceinline__ void mma16816h(float* d, const uint32_t* a, const uint32_t* b) {
    asm volatile("mma.sync.aligned.m16n8k16.row.col.f32.f16.f16.f32 "
                 "{%0,%1,%2,%3}, {%4,%5,%6,%7}, {%8,%9}, {%0,%1,%2,%3};"
                 : "+f"(d[0]), "+f"(d[1]), "+f"(d[2]), "+f"(d[3])
                 : "r"(a[0]), "r"(a[1]), "r"(a[2]), "r"(a[3]), "r"(b[0]), "r"(b[1]));
}

// ============================================================================
// Kernel 1: projections.  y[b][o][n] = sum_c W[o][c] * x[b][c][n] + bias[o]
// mode 0/1 (xf/xg): write TRANSPOSED bf16 hi/lo [b][n][32c]  (feeds score mma)
// mode 2   (xh)   : write fp32 [b][c][n]
// ============================================================================
__global__ __launch_bounds__(256) void proj_kernel(
    const float* __restrict__ W, const float* __restrict__ bias,
    const float* __restrict__ x, int mode)
{
    __shared__ float Ws[32][33];
    __shared__ float Xs[32][132];

    const int b  = blockIdx.z;
    const int o0 = blockIdx.y * 32;
    const int n0 = blockIdx.x * 128;
    const int t  = threadIdx.x;
    const int tx = t & 31;
    const int ty = t >> 5;

    const float* xb = x + (size_t)b * CDIM * NPIX;

    float acc[4][4] = {};

    for (int k0 = 0; k0 < CDIM; k0 += 32) {
        {
            int o = t >> 3, k4 = (t & 7) << 2;
            float4 w4 = *(const float4*)(W + (size_t)(o0 + o) * CDIM + k0 + k4);
            Ws[o][k4 + 0] = w4.x; Ws[o][k4 + 1] = w4.y;
            Ws[o][k4 + 2] = w4.z; Ws[o][k4 + 3] = w4.w;
        }
        #pragma unroll
        for (int p = 0; p < 4; p++) {
            int idx = t + p * 256;
            int r = idx >> 5, c4 = (idx & 31) << 2;
            *(float4*)&Xs[r][c4] = *(const float4*)(xb + (size_t)(k0 + r) * NPIX + n0 + c4);
        }
        __syncthreads();

        #pragma unroll
        for (int k = 0; k < 32; k++) {
            float a0 = Ws[ty * 4 + 0][k];
            float a1 = Ws[ty * 4 + 1][k];
            float a2 = Ws[ty * 4 + 2][k];
            float a3 = Ws[ty * 4 + 3][k];
            float4 bv = *(float4*)&Xs[k][tx * 4];
            acc[0][0] += a0 * bv.x; acc[0][1] += a0 * bv.y; acc[0][2] += a0 * bv.z; acc[0][3] += a0 * bv.w;
            acc[1][0] += a1 * bv.x; acc[1][1] += a1 * bv.y; acc[1][2] += a1 * bv.z; acc[1][3] += a1 * bv.w;
            acc[2][0] += a2 * bv.x; acc[2][1] += a2 * bv.y; acc[2][2] += a2 * bv.z; acc[2][3] += a2 * bv.w;
            acc[3][0] += a3 * bv.x; acc[3][1] += a3 * bv.y; acc[3][2] += a3 * bv.z; acc[3][3] += a3 * bv.w;
        }
        __syncthreads();
    }

    if (mode == 2) {
        #pragma unroll
        for (int i = 0; i < 4; i++) {
            int o = o0 + ty * 4 + i;
            float bb = bias[o];
            float4 r;
            r.x = acc[i][0] + bb; r.y = acc[i][1] + bb;
            r.z = acc[i][2] + bb; r.w = acc[i][3] + bb;
            *(float4*)(g_xh + ((size_t)b * CDIM + o) * NPIX + n0 + tx * 4) = r;
        }
    } else {
        __nv_bfloat16* yh = (mode == 0) ? g_xfh : g_xgh;
        __nv_bfloat16* yl = (mode == 0) ? g_xfl : g_xgl;
        float bb[4];
        #pragma unroll
        for (int i = 0; i < 4; i++) bb[i] = bias[ty * 4 + i];
        #pragma unroll
        for (int j = 0; j < 4; j++) {
            int n = n0 + tx * 4 + j;
            ushort4 h4, l4;
            #pragma unroll
            for (int i = 0; i < 4; i++) {
                float a = acc[i][j] + bb[i];
                __nv_bfloat16 h = __float2bfloat16(a);
                __nv_bfloat16 l = __float2bfloat16(a - __bfloat162float(h));
                ((unsigned short*)&h4)[i] = __bfloat16_as_ushort(h);
                ((unsigned short*)&l4)[i] = __bfloat16_as_ushort(l);
            }
            size_t off = ((size_t)b * NPIX + n) * CBAR + ty * 4;
            *(ushort4*)(yh + off) = h4;
            *(ushort4*)(yl + off) = l4;
        }
    }
}

// ============================================================================
// Kernel 2a: zero the l accumulator
// ============================================================================
__global__ void zero_l_kernel() {
    int t = blockIdx.x * blockDim.x + threadIdx.x;
    if (t < BATCH * NPIX) g_l[t] = 0.0f;
}

// ============================================================================
// Kernel 2b: scores on tensor cores (unchanged from R9; measured correct).
// ============================================================================
#define SROWB 80
#define SA_LO 5120
#define SB_LO 10240
#define SB_STAGE 20480
#define SA_BYTES 10240

__global__ __launch_bounds__(256, 2) void score_kernel()
{
    extern __shared__ char smem[];
    const uint32_t sa = smem_u32(smem);
    const uint32_t sb0 = sa + SA_BYTES;

    const int b  = blockIdx.y;
    const int j0 = blockIdx.x * 64;
    const int t  = threadIdx.x;
    const int warp = t >> 5, lane = t & 31;
    const int wm = (warp & 1) * 32;
    const int wn = (warp >> 1) * 32;

    const __nv_bfloat16* xfh = g_xfh + (size_t)b * NPIX * CBAR;
    const __nv_bfloat16* xfl = g_xfl + (size_t)b * NPIX * CBAR;
    const __nv_bfloat16* xgh = g_xgh + (size_t)b * NPIX * CBAR;
    const __nv_bfloat16* xgl = g_xgl + (size_t)b * NPIX * CBAR;
    __nv_bfloat16* ph = g_ph + (size_t)b * NPIX * NPIX;
    float* lrow = g_l + b * NPIX;

    #pragma unroll
    for (int q = 0; q < 2; q++) {
        int id = t + q * 256;
        int r = id >> 2, g16 = id & 3;
        const __nv_bfloat16* src = ((r < 64) ? xgh : xgl) + ((size_t)(j0 + (r & 63))) * CBAR + g16 * 8;
        CPASYNC16(sa + r * SROWB + g16 * 16, src);
    }
    #pragma unroll
    for (int q = 0; q < 4; q++) {
        int id = t + q * 256;
        int r = id >> 2, g16 = id & 3;
        const __nv_bfloat16* src = ((r < 128) ? xfh : xfl) + ((size_t)(r & 127)) * CBAR + g16 * 8;
        CPASYNC16(sb0 + r * SROWB + g16 * 16, src);
    }
    CPCOMMIT();

    const int a_row = lane & 15, a_k16 = (lane >> 4) << 4;
    const int b_row = (lane & 7) + ((lane >> 4) & 1) * 8;
    const int b_k16 = ((lane >> 3) & 1) * 16;

    const int NIT = NPIX / 128;

    for (int it = 0; it < NIT; it++) {
        const int s = it & 1;
        if (it + 1 < NIT) {
            const int i0n = (it + 1) * 128;
            const uint32_t st = sb0 + (s ^ 1) * SB_STAGE;
            #pragma unroll
            for (int q = 0; q < 4; q++) {
                int id = t + q * 256;
                int r = id >> 2, g16 = id & 3;
                const __nv_bfloat16* src = ((r < 128) ? xfh : xfl) + ((size_t)(i0n + (r & 127))) * CBAR + g16 * 8;
                CPASYNC16(st + r * SROWB + g16 * 16, src);
            }
            CPCOMMIT();
            CPWAIT(1);
        } else {
            CPWAIT(0);
        }
        __syncthreads();

        const uint32_t stg = sb0 + s * SB_STAGE;
        float sacc[2][4][4];
        #pragma unroll
        for (int m = 0; m < 2; m++)
            #pragma unroll
            for (int n = 0; n < 4; n++)
                #pragma unroll
                for (int q = 0; q < 4; q++) sacc[m][n][q] = 0.f;

        #pragma unroll
        for (int ks = 0; ks < 2; ks++) {
            const int kB = ks * 32;
            uint32_t a_h[2][4], a_l[2][4];
            #pragma unroll
            for (int ms = 0; ms < 2; ms++) {
                uint32_t ra = sa + (wm + ms * 16 + a_row) * SROWB + kB + a_k16;
                ldmx4(a_h[ms], ra);
                ldmx4(a_l[ms], ra + SA_LO);
            }
            #pragma unroll
            for (int np = 0; np < 2; np++) {
                uint32_t rb = stg + (wn + np * 16 + b_row) * SROWB + kB + b_k16;
                uint32_t b_h[4], b_l[4];
                ldmx4(b_h, rb);
                ldmx4(b_l, rb + SB_LO);
                #pragma unroll
                for (int ms = 0; ms < 2; ms++) {
                    #pragma unroll
                    for (int nh = 0; nh < 2; nh++) {
                        float* d = sacc[ms][np * 2 + nh];
                        mma16816(d, a_h[ms], b_h + 2 * nh);
                        mma16816(d, a_h[ms], b_l + 2 * nh);
                        mma16816(d, a_l[ms], b_h + 2 * nh);
                    }
                }
            }
        }

        const int i0 = it * 128;
        #pragma unroll
        for (int nn = 0; nn < 4; nn++) {
            const int icol = i0 + wn + nn * 8 + (lane & 3) * 2;
            float cs0 = 0.f, cs1 = 0.f;
            #pragma unroll
            for (int ms = 0; ms < 2; ms++) {
                float* d = sacc[ms][nn];
                float p0 = __expf(d[0]);
                float p1 = __expf(d[1]);
                float p2 = __expf(d[2]);
                float p3 = __expf(d[3]);
                cs0 += p0 + p2; cs1 += p1 + p3;
                const int j = j0 + wm + ms * 16 + (lane >> 2);
                uint32_t pk01 = ((uint32_t)__bfloat16_as_ushort(__float2bfloat16(p1)) << 16)
                              |  (uint32_t)__bfloat16_as_ushort(__float2bfloat16(p0));
                uint32_t pk23 = ((uint32_t)__bfloat16_as_ushort(__float2bfloat16(p3)) << 16)
                              |  (uint32_t)__bfloat16_as_ushort(__float2bfloat16(p2));
                *(uint32_t*)(ph + (size_t)j * NPIX + icol)       = pk01;
                *(uint32_t*)(ph + (size_t)(j + 8) * NPIX + icol) = pk23;
            }
            #pragma unroll
            for (int off = 4; off <= 16; off <<= 1) {
                cs0 += __shfl_xor_sync(0xffffffffu, cs0, off);
                cs1 += __shfl_xor_sync(0xffffffffu, cs1, off);
            }
            if (lane < 4) {
                atomicAdd(lrow + icol, cs0);
                atomicAdd(lrow + icol + 1, cs1);
            }
        }
        __syncthreads();
    }
}

// ============================================================================
// Kernel 2c: finalize.  invl[i] = 1/l[i];  xh16[c][i] = fp16(xh[c][i]).
// ============================================================================
__global__ __launch_bounds__(256) void finalize_kernel()
{
    int idx = blockIdx.x * blockDim.x + threadIdx.x;
    int b = idx >> 12;
    int i = idx & (NPIX - 1);
    float inv = 1.0f / g_l[idx];
    g_invl[idx] = inv;

    const float* xh = g_xh + (size_t)b * CDIM * NPIX + i;
    __half* xh16 = g_xh16 + (size_t)b * CDIM * NPIX + i;

    #pragma unroll 4
    for (int c = 0; c < CDIM; c++)
        xh16[(size_t)c * NPIX] = __float2half_rn(xh[(size_t)c * NPIX]);
}

// ============================================================================
// Kernel 2d: beta.  beta[j][i] = fp16( bf16_P[j][i] * invl[i] ).  Streaming,
// fully coalesced (8 elems/thread along i); invl stays L2/L1 resident.
// grid: (NPIX*NPIX/2048, BATCH), block 256.
// ============================================================================
__global__ __launch_bounds__(256) void beta_kernel()
{
    const int b = blockIdx.y;
    const size_t lin = ((size_t)blockIdx.x * 256 + threadIdx.x) * 8;
    const int i = (int)(lin & (NPIX - 1));

    const __nv_bfloat16* ph = g_ph + (size_t)b * NPIX * NPIX + lin;
    __half* bo = g_beta + (size_t)b * NPIX * NPIX + lin;
    const float* invl = g_invl + b * NPIX + i;

    uint4 pv = *(const uint4*)ph;
    float4 v0 = *(const float4*)invl;
    float4 v1 = *(const float4*)(invl + 4);

    const uint32_t* pw = (const uint32_t*)&pv;
    float iv[8] = {v0.x, v0.y, v0.z, v0.w, v1.x, v1.y, v1.z, v1.w};
    uint32_t outw[4];
    #pragma unroll
    for (int q = 0; q < 4; q++) {
        float plo = __bfloat162float(__ushort_as_bfloat16((unsigned short)(pw[q] & 0xFFFF)));
        float phi = __bfloat162float(__ushort_as_bfloat16((unsigned short)(pw[q] >> 16)));
        __half h0 = __float2half_rn(plo * iv[q * 2]);
        __half h1 = __float2half_rn(phi * iv[q * 2 + 1]);
        outw[q] = ((uint32_t)__half_as_ushort(h1) << 16) | (uint32_t)__half_as_ushort(h0);
    }
    *(uint4*)bo = *(uint4*)outw;
}

// ============================================================================
// Kernel 3: output GEMM via mma.sync fp16, ONE product:
//   D^T[j][c] = sum_i beta[j][i] * xh16[c][i]
// BM=128 (j), BN=256 (all c), BK=32, 512 threads = 16 warps, warp tile 32x64,
// double-buffered cp.async, 80B rows. Epilogue: out = x + gamma*D^T.
// dyn smem = 61440 B.
// ============================================================================
#define ROWB 80
#define OFF_A 0
#define OFF_B 10240
#define STAGE  30720

__global__ __launch_bounds__(512, 1) void out_gemm_mma(
    const float* __restrict__ x, const float* __restrict__ gamma,
    float* __restrict__ out)
{
    extern __shared__ char smem[];
    const uint32_t sb = smem_u32(smem);

    const int b  = blockIdx.y;
    const int m0 = blockIdx.x * 128;
    const int t  = threadIdx.x;
    const int warp = t >> 5, lane = t & 31;
    const int wm = (warp & 3) * 32;
    const int wn = (warp >> 2) * 64;

    const __half* bt = g_beta + (size_t)b * NPIX * NPIX;
    const __half* xh = g_xh16 + (size_t)b * CDIM * NPIX;

    const int ar = t >> 2, ac = (t & 3) << 3;
    float acc[2][8][4];
    #pragma unroll
    for (int i = 0; i < 2; i++)
        #pragma unroll
        for (int j = 0; j < 8; j++)
            #pragma unroll
            for (int q = 0; q < 4; q++) acc[i][j][q] = 0.f;

    const int a_row = lane & 15, a_k16 = (lane >> 4) << 4;
    const int b_row = (lane & 7) + ((lane >> 4) & 1) * 8;
    const int b_k16 = ((lane >> 3) & 1) * 16;

    const int NCH = NPIX / 32;

    // prologue
    {
        const uint32_t st = sb;
        CPASYNC16(st + ar * ROWB + ((t & 3) << 4) + OFF_A, bt + (size_t)(m0 + ar) * NPIX + ac);
        #pragma unroll
        for (int q = 0; q < 2; q++) {
            int id = t + q * 512;
            int r = id >> 2, c8 = (id & 3) << 3;
            CPASYNC16(st + r * ROWB + ((id & 3) << 4) + OFF_B, xh + (size_t)r * NPIX + c8);
        }
        CPCOMMIT();
    }

    for (int kt = 0; kt < NCH; kt++) {
        const int s = kt & 1;
        if (kt + 1 < NCH) {
            const int i0 = (kt + 1) * 32;
            const uint32_t st = sb + (s ^ 1) * STAGE;
            CPASYNC16(st + ar * ROWB + ((t & 3) << 4) + OFF_A, bt + (size_t)(m0 + ar) * NPIX + i0 + ac);
            #pragma unroll
            for (int q = 0; q < 2; q++) {
                int id = t + q * 512;
                int r = id >> 2, c8 = (id & 3) << 3;
                CPASYNC16(st + r * ROWB + ((id & 3) << 4) + OFF_B, xh + (size_t)r * NPIX + i0 + c8);
            }
            CPCOMMIT();
            CPWAIT(1);
        } else {
            CPWAIT(0);
        }
        __syncthreads();

        const uint32_t st = sb + s * STAGE;
        #pragma unroll
        for (int ks = 0; ks < 2; ks++) {
            const int kB = ks * 32;
            uint32_t a_f[2][4];
            #pragma unroll
            for (int ms = 0; ms < 2; ms++) {
                uint32_t ra = st + (wm + ms * 16 + a_row) * ROWB + kB + a_k16;
                ldmx4(a_f[ms], ra + OFF_A);
            }
            #pragma unroll
            for (int np = 0; np < 4; np++) {
                uint32_t rb = st + (wn + np * 16 + b_row) * ROWB + kB + b_k16;
                uint32_t b_f[4];
                ldmx4(b_f, rb + OFF_B);
                #pragma unroll
                for (int ms = 0; ms < 2; ms++) {
                    #pragma unroll
                    for (int nh = 0; nh < 2; nh++) {
                        mma16816h(acc[ms][np * 2 + nh], a_f[ms], b_f + 2 * nh);
                    }
                }
            }
        }
        __syncthreads();
    }

    // epilogue: out[c][j] = x[c][j] + g * D^T[j][c]
    const float g = gamma[0];
    const float* xb = x   + (size_t)b * CDIM * NPIX;
    float*       ob = out + (size_t)b * CDIM * NPIX;
    const int jq = lane >> 2, cq = (lane & 3) * 2;

    #pragma unroll
    for (int ms = 0; ms < 2; ms++) {
        #pragma unroll
        for (int ni = 0; ni < 8; ni++) {
            int j = m0 + wm + ms * 16 + jq;
            int c = wn + ni * 8 + cq;
            float* a4 = acc[ms][ni];
            ob[(size_t)c * NPIX + j]            = xb[(size_t)c * NPIX + j]            + g * a4[0];
            ob[(size_t)(c + 1) * NPIX + j]      = xb[(size_t)(c + 1) * NPIX + j]      + g * a4[1];
            ob[(size_t)c * NPIX + j + 8]        = xb[(size_t)c * NPIX + j + 8]        + g * a4[2];
            ob[(size_t)(c + 1) * NPIX + j + 8]  = xb[(size_t)(c + 1) * NPIX + j + 8]  + g * a4[3];
        }
    }
}

// ============================================================================
extern "C" void kernel_launch(void* const* d_in, const int* in_sizes, int n_in,
                              void* d_out, int out_size)
{
    const float* x     = (const float*)d_in[0];
    const float* Wf    = (const float*)d_in[1];
    const float* bf    = (const float*)d_in[2];
    const float* Wg    = (const float*)d_in[3];
    const float* bg    = (const float*)d_in[4];
    const float* Wh    = (const float*)d_in[5];
    const float* bh    = (const float*)d_in[6];
    const float* gamma = (const float*)d_in[7];
    float* out = (float*)d_out;

    (void)in_sizes; (void)n_in; (void)out_size;

    cudaFuncSetAttribute(out_gemm_mma, cudaFuncAttributeMaxDynamicSharedMemorySize,
                         2 * STAGE);
    cudaFuncSetAttribute(score_kernel, cudaFuncAttributeMaxDynamicSharedMemorySize,
                         SA_BYTES + 2 * SB_STAGE);

    dim3 blk(256);
    zero_l_kernel<<<(BATCH * NPIX + 255) / 256, blk>>>();
    proj_kernel<<<dim3(NPIX / 128, CBAR / 32, BATCH), blk>>>(Wf, bf, x, 0);
    proj_kernel<<<dim3(NPIX / 128, CBAR / 32, BATCH), blk>>>(Wg, bg, x, 1);
    proj_kernel<<<dim3(NPIX / 128, CDIM / 32, BATCH), blk>>>(Wh, bh, x, 2);
    score_kernel<<<dim3(NPIX / 64, BATCH), blk, SA_BYTES + 2 * SB_STAGE>>>();
    finalize_kernel<<<BATCH * NPIX / 256, blk>>>();
    beta_kernel<<<dim3(NPIX * NPIX / 2048, BATCH), blk>>>();
    out_gemm_mma<<<dim3(NPIX / 128, BATCH), 512, 2 * STAGE>>>(x, gamma, out);
}

// round 12
// speedup vs baseline: 2.4980x; 1.0794x over previous
#include <cuda_runtime.h>
#include <cuda_bf16.h>
#include <cuda_fp16.h>
#include <math.h>
#include <stdint.h>

#define NPIX 4096
#define CDIM 256
#define CBAR 32
#define BATCH 8

// ---- scratch (device globals; no runtime allocation) ----
__device__ float g_xh[BATCH * CDIM * NPIX];                    // 32 MB
__device__ float g_l[BATCH * NPIX];
__device__ float g_invl[BATCH * NPIX];
__device__ __nv_bfloat16 g_xfh[BATCH * NPIX * CBAR];           // [b][n][c] hi
__device__ __nv_bfloat16 g_xfl[BATCH * NPIX * CBAR];
__device__ __nv_bfloat16 g_xgh[BATCH * NPIX * CBAR];
__device__ __nv_bfloat16 g_xgl[BATCH * NPIX * CBAR];
__device__ __nv_bfloat16 g_ph[(size_t)BATCH * NPIX * NPIX];    // 256 MB: bf16(exp(S^T)) [b][j][i]
__device__ __half g_xh16[BATCH * CDIM * NPIX];                 // 16 MB: fp16(xh) [b][c][i]

// ---- base-ISA helpers (sm_80+) ----
__device__ __forceinline__ uint32_t smem_u32(const void* p) {
    uint32_t a;
    asm("{ .reg .u64 t; cvta.to.shared.u64 t, %1; cvt.u32.u64 %0, t; }" : "=r"(a) : "l"(p));
    return a;
}
#define CPASYNC16(d, s) asm volatile("cp.async.cg.shared.global [%0], [%1], 16;" :: "r"(d), "l"(s) : "memory")
#define CPCOMMIT()      asm volatile("cp.async.commit_group;" ::: "memory")
#define CPWAIT(n)       asm volatile("cp.async.wait_group %0;" :: "n"(n) : "memory")

__device__ __forceinline__ void ldmx4(uint32_t* r, uint32_t addr) {
    asm volatile("ldmatrix.sync.aligned.m8n8.x4.shared.b16 {%0,%1,%2,%3}, [%4];"
                 : "=r"(r[0]), "=r"(r[1]), "=r"(r[2]), "=r"(r[3]) : "r"(addr));
}
__device__ __forceinline__ void mma16816(float* d, const uint32_t* a, const uint32_t* b) {
    asm volatile("mma.sync.aligned.m16n8k16.row.col.f32.bf16.bf16.f32 "
                 "{%0,%1,%2,%3}, {%4,%5,%6,%7}, {%8,%9}, {%0,%1,%2,%3};"
                 : "+f"(d[0]), "+f"(d[1]), "+f"(d[2]), "+f"(d[3])
                 : "r"(a[0]), "r"(a[1]), "r"(a[2]), "r"(a[3]), "r"(b[0]), "r"(b[1]));
}
__device__ __forceinline__ void mma16816h(float* d, const uint32_t* a, const uint32_t* b) {
    asm volatile("mma.sync.aligned.m16n8k16.row.col.f32.f16.f16.f32 "
                 "{%0,%1,%2,%3}, {%4,%5,%6,%7}, {%8,%9}, {%0,%1,%2,%3};"
                 : "+f"(d[0]), "+f"(d[1]), "+f"(d[2]), "+f"(d[3])
                 : "r"(a[0]), "r"(a[1]), "r"(a[2]), "r"(a[3]), "r"(b[0]), "r"(b[1]));
}

// ============================================================================
// Kernel 1: projections (unchanged; validated R9/R10).
// ============================================================================
__global__ __launch_bounds__(256) void proj_kernel(
    const float* __restrict__ W, const float* __restrict__ bias,
    const float* __restrict__ x, int mode)
{
    __shared__ float Ws[32][33];
    __shared__ float Xs[32][132];

    const int b  = blockIdx.z;
    const int o0 = blockIdx.y * 32;
    const int n0 = blockIdx.x * 128;
    const int t  = threadIdx.x;
    const int tx = t & 31;
    const int ty = t >> 5;

    const float* xb = x + (size_t)b * CDIM * NPIX;

    float acc[4][4] = {};

    for (int k0 = 0; k0 < CDIM; k0 += 32) {
        {
            int o = t >> 3, k4 = (t & 7) << 2;
            float4 w4 = *(const float4*)(W + (size_t)(o0 + o) * CDIM + k0 + k4);
            Ws[o][k4 + 0] = w4.x; Ws[o][k4 + 1] = w4.y;
            Ws[o][k4 + 2] = w4.z; Ws[o][k4 + 3] = w4.w;
        }
        #pragma unroll
        for (int p = 0; p < 4; p++) {
            int idx = t + p * 256;
            int r = idx >> 5, c4 = (idx & 31) << 2;
            *(float4*)&Xs[r][c4] = *(const float4*)(xb + (size_t)(k0 + r) * NPIX + n0 + c4);
        }
        __syncthreads();

        #pragma unroll
        for (int k = 0; k < 32; k++) {
            float a0 = Ws[ty * 4 + 0][k];
            float a1 = Ws[ty * 4 + 1][k];
            float a2 = Ws[ty * 4 + 2][k];
            float a3 = Ws[ty * 4 + 3][k];
            float4 bv = *(float4*)&Xs[k][tx * 4];
            acc[0][0] += a0 * bv.x; acc[0][1] += a0 * bv.y; acc[0][2] += a0 * bv.z; acc[0][3] += a0 * bv.w;
            acc[1][0] += a1 * bv.x; acc[1][1] += a1 * bv.y; acc[1][2] += a1 * bv.z; acc[1][3] += a1 * bv.w;
            acc[2][0] += a2 * bv.x; acc[2][1] += a2 * bv.y; acc[2][2] += a2 * bv.z; acc[2][3] += a2 * bv.w;
            acc[3][0] += a3 * bv.x; acc[3][1] += a3 * bv.y; acc[3][2] += a3 * bv.z; acc[3][3] += a3 * bv.w;
        }
        __syncthreads();
    }

    if (mode == 2) {
        #pragma unroll
        for (int i = 0; i < 4; i++) {
            int o = o0 + ty * 4 + i;
            float bb = bias[o];
            float4 r;
            r.x = acc[i][0] + bb; r.y = acc[i][1] + bb;
            r.z = acc[i][2] + bb; r.w = acc[i][3] + bb;
            *(float4*)(g_xh + ((size_t)b * CDIM + o) * NPIX + n0 + tx * 4) = r;
        }
    } else {
        __nv_bfloat16* yh = (mode == 0) ? g_xfh : g_xgh;
        __nv_bfloat16* yl = (mode == 0) ? g_xfl : g_xgl;
        float bb[4];
        #pragma unroll
        for (int i = 0; i < 4; i++) bb[i] = bias[ty * 4 + i];
        #pragma unroll
        for (int j = 0; j < 4; j++) {
            int n = n0 + tx * 4 + j;
            ushort4 h4, l4;
            #pragma unroll
            for (int i = 0; i < 4; i++) {
                float a = acc[i][j] + bb[i];
                __nv_bfloat16 h = __float2bfloat16(a);
                __nv_bfloat16 l = __float2bfloat16(a - __bfloat162float(h));
                ((unsigned short*)&h4)[i] = __bfloat16_as_ushort(h);
                ((unsigned short*)&l4)[i] = __bfloat16_as_ushort(l);
            }
            size_t off = ((size_t)b * NPIX + n) * CBAR + ty * 4;
            *(ushort4*)(yh + off) = h4;
            *(ushort4*)(yl + off) = l4;
        }
    }
}

// ============================================================================
// Kernel 2a: zero the l accumulator
// ============================================================================
__global__ void zero_l_kernel() {
    int t = blockIdx.x * blockDim.x + threadIdx.x;
    if (t < BATCH * NPIX) g_l[t] = 0.0f;
}

// ============================================================================
// Kernel 2b: scores on tensor cores + SMEM-STAGED coalesced p stores.
// ============================================================================
#define SROWB 80
#define SA_LO 5120
#define SB_LO 10240
#define SB_STAGE 20480
#define SA_BYTES 10240
#define PST_OFF (SA_BYTES + 2 * SB_STAGE)     // 51200
#define PST_ROWB 272                          // 128 i * 2B + 16 pad
#define SCORE_SMEM (PST_OFF + 64 * PST_ROWB)  // 68608

__global__ __launch_bounds__(256, 2) void score_kernel()
{
    extern __shared__ char smem[];
    const uint32_t sa = smem_u32(smem);
    const uint32_t sb0 = sa + SA_BYTES;
    char* pst = smem + PST_OFF;

    const int b  = blockIdx.y;
    const int j0 = blockIdx.x * 64;
    const int t  = threadIdx.x;
    const int warp = t >> 5, lane = t & 31;
    const int wm = (warp & 1) * 32;
    const int wn = (warp >> 1) * 32;

    const __nv_bfloat16* xfh = g_xfh + (size_t)b * NPIX * CBAR;
    const __nv_bfloat16* xfl = g_xfl + (size_t)b * NPIX * CBAR;
    const __nv_bfloat16* xgh = g_xgh + (size_t)b * NPIX * CBAR;
    const __nv_bfloat16* xgl = g_xgl + (size_t)b * NPIX * CBAR;
    __nv_bfloat16* ph = g_ph + (size_t)b * NPIX * NPIX;
    float* lrow = g_l + b * NPIX;

    #pragma unroll
    for (int q = 0; q < 2; q++) {
        int id = t + q * 256;
        int r = id >> 2, g16 = id & 3;
        const __nv_bfloat16* src = ((r < 64) ? xgh : xgl) + ((size_t)(j0 + (r & 63))) * CBAR + g16 * 8;
        CPASYNC16(sa + r * SROWB + g16 * 16, src);
    }
    #pragma unroll
    for (int q = 0; q < 4; q++) {
        int id = t + q * 256;
        int r = id >> 2, g16 = id & 3;
        const __nv_bfloat16* src = ((r < 128) ? xfh : xfl) + ((size_t)(r & 127)) * CBAR + g16 * 8;
        CPASYNC16(sb0 + r * SROWB + g16 * 16, src);
    }
    CPCOMMIT();

    const int a_row = lane & 15, a_k16 = (lane >> 4) << 4;
    const int b_row = (lane & 7) + ((lane >> 4) & 1) * 8;
    const int b_k16 = ((lane >> 3) & 1) * 16;

    const int NIT = NPIX / 128;

    for (int it = 0; it < NIT; it++) {
        const int s = it & 1;
        if (it + 1 < NIT) {
            const int i0n = (it + 1) * 128;
            const uint32_t st = sb0 + (s ^ 1) * SB_STAGE;
            #pragma unroll
            for (int q = 0; q < 4; q++) {
                int id = t + q * 256;
                int r = id >> 2, g16 = id & 3;
                const __nv_bfloat16* src = ((r < 128) ? xfh : xfl) + ((size_t)(i0n + (r & 127))) * CBAR + g16 * 8;
                CPASYNC16(st + r * SROWB + g16 * 16, src);
            }
            CPCOMMIT();
            CPWAIT(1);
        } else {
            CPWAIT(0);
        }
        __syncthreads();

        const uint32_t stg = sb0 + s * SB_STAGE;
        float sacc[2][4][4];
        #pragma unroll
        for (int m = 0; m < 2; m++)
            #pragma unroll
            for (int n = 0; n < 4; n++)
                #pragma unroll
                for (int q = 0; q < 4; q++) sacc[m][n][q] = 0.f;

        #pragma unroll
        for (int ks = 0; ks < 2; ks++) {
            const int kB = ks * 32;
            uint32_t a_h[2][4], a_l[2][4];
            #pragma unroll
            for (int ms = 0; ms < 2; ms++) {
                uint32_t ra = sa + (wm + ms * 16 + a_row) * SROWB + kB + a_k16;
                ldmx4(a_h[ms], ra);
                ldmx4(a_l[ms], ra + SA_LO);
            }
            #pragma unroll
            for (int np = 0; np < 2; np++) {
                uint32_t rb = stg + (wn + np * 16 + b_row) * SROWB + kB + b_k16;
                uint32_t b_h[4], b_l[4];
                ldmx4(b_h, rb);
                ldmx4(b_l, rb + SB_LO);
                #pragma unroll
                for (int ms = 0; ms < 2; ms++) {
                    #pragma unroll
                    for (int nh = 0; nh < 2; nh++) {
                        float* d = sacc[ms][np * 2 + nh];
                        mma16816(d, a_h[ms], b_h + 2 * nh);
                        mma16816(d, a_h[ms], b_l + 2 * nh);
                        mma16816(d, a_l[ms], b_h + 2 * nh);
                    }
                }
            }
        }

        const int i0 = it * 128;
        #pragma unroll
        for (int nn = 0; nn < 4; nn++) {
            const int icl = wn + nn * 8 + (lane & 3) * 2;
            float cs0 = 0.f, cs1 = 0.f;
            #pragma unroll
            for (int ms = 0; ms < 2; ms++) {
                float* d = sacc[ms][nn];
                float p0 = __expf(d[0]);
                float p1 = __expf(d[1]);
                float p2 = __expf(d[2]);
                float p3 = __expf(d[3]);
                cs0 += p0 + p2; cs1 += p1 + p3;
                const int jl = wm + ms * 16 + (lane >> 2);
                uint32_t pk01 = ((uint32_t)__bfloat16_as_ushort(__float2bfloat16(p1)) << 16)
                              |  (uint32_t)__bfloat16_as_ushort(__float2bfloat16(p0));
                uint32_t pk23 = ((uint32_t)__bfloat16_as_ushort(__float2bfloat16(p3)) << 16)
                              |  (uint32_t)__bfloat16_as_ushort(__float2bfloat16(p2));
                *(uint32_t*)(pst + jl * PST_ROWB + icl * 2)       = pk01;
                *(uint32_t*)(pst + (jl + 8) * PST_ROWB + icl * 2) = pk23;
            }
            #pragma unroll
            for (int off = 4; off <= 16; off <<= 1) {
                cs0 += __shfl_xor_sync(0xffffffffu, cs0, off);
                cs1 += __shfl_xor_sync(0xffffffffu, cs1, off);
            }
            if (lane < 4) {
                atomicAdd(lrow + i0 + icl, cs0);
                atomicAdd(lrow + i0 + icl + 1, cs1);
            }
        }
        __syncthreads();

        #pragma unroll
        for (int q = 0; q < 4; q++) {
            int id = q * 256 + t;
            int jl = id >> 4, w16 = id & 15;
            uint4 v = *(uint4*)(pst + jl * PST_ROWB + w16 * 16);
            *(uint4*)(ph + (size_t)(j0 + jl) * NPIX + i0 + w16 * 8) = v;
        }
        __syncthreads();
    }
}

// ============================================================================
// Kernel 2c: finalize.  invl[i] = 1/l[i];  xh16[c][i] = fp16(xh[c][i]).
// ============================================================================
__global__ __launch_bounds__(256) void finalize_kernel()
{
    int idx = blockIdx.x * blockDim.x + threadIdx.x;
    int b = idx >> 12;
    int i = idx & (NPIX - 1);
    float inv = 1.0f / g_l[idx];
    g_invl[idx] = inv;

    const float* xh = g_xh + (size_t)b * CDIM * NPIX + i;
    __half* xh16 = g_xh16 + (size_t)b * CDIM * NPIX + i;

    #pragma unroll 4
    for (int c = 0; c < CDIM; c++)
        xh16[(size_t)c * NPIX] = __float2half_rn(xh[(size_t)c * NPIX]);
}

// ============================================================================
// Kernel 3: output GEMM, fp16 mma, beta fused into A-path.
// ============================================================================
#define ROWB 80
#define OFF_A 0
#define OFF_B 10240
#define STAGE 30720
#define INVL_OFF (2 * STAGE)
#define GEMM_SMEM (INVL_OFF + NPIX * 4)

__global__ __launch_bounds__(512, 1) void out_gemm_mma(
    const float* __restrict__ x, const float* __restrict__ gamma,
    float* __restrict__ out)
{
    extern __shared__ char smem[];
    const uint32_t sb = smem_u32(smem);
    float* sinvl = (float*)(smem + INVL_OFF);

    const int b  = blockIdx.y;
    const int m0 = blockIdx.x * 128;
    const int t  = threadIdx.x;
    const int warp = t >> 5, lane = t & 31;
    const int wm = (warp & 3) * 32;
    const int wn = (warp >> 2) * 64;

    const __nv_bfloat16* pb = g_ph + (size_t)b * NPIX * NPIX;
    const __half* xh = g_xh16 + (size_t)b * CDIM * NPIX;
    const float* invl = g_invl + b * NPIX;

    const int ar = t >> 2, ac = (t & 3) << 3;
    float acc[2][8][4];
    #pragma unroll
    for (int i = 0; i < 2; i++)
        #pragma unroll
        for (int j = 0; j < 8; j++)
            #pragma unroll
            for (int q = 0; q < 4; q++) acc[i][j][q] = 0.f;

    const int a_row = lane & 15, a_k16 = (lane >> 4) << 4;
    const int b_row = (lane & 7) + ((lane >> 4) & 1) * 8;
    const int b_k16 = ((lane >> 3) & 1) * 16;

    const int NCH = NPIX / 32;

    // ---- prologue ----
    {
        int vi = t * 8;
        *(float4*)(sinvl + vi)     = *(const float4*)(invl + vi);
        *(float4*)(sinvl + vi + 4) = *(const float4*)(invl + vi + 4);
    }
    uint4 areg = *(const uint4*)(pb + (size_t)(m0 + ar) * NPIX + ac);
    {
        const uint32_t st = sb;
        #pragma unroll
        for (int q = 0; q < 2; q++) {
            int id = t + q * 512;
            int r = id >> 2, c8 = (id & 3) << 3;
            CPASYNC16(st + r * ROWB + ((id & 3) << 4) + OFF_B, xh + (size_t)r * NPIX + c8);
        }
        CPCOMMIT();
    }
    __syncthreads();
    {
        const uint32_t* aw = (const uint32_t*)&areg;
        float iv[8];
        #pragma unroll
        for (int k = 0; k < 8; k++) iv[k] = sinvl[ac + k];
        uint32_t w[4];
        #pragma unroll
        for (int q = 0; q < 4; q++) {
            float lo = __bfloat162float(__ushort_as_bfloat16((unsigned short)(aw[q] & 0xFFFF)));
            float hi = __bfloat162float(__ushort_as_bfloat16((unsigned short)(aw[q] >> 16)));
            __half h0 = __float2half_rn(lo * iv[q * 2]);
            __half h1 = __float2half_rn(hi * iv[q * 2 + 1]);
            w[q] = ((uint32_t)__half_as_ushort(h1) << 16) | (uint32_t)__half_as_ushort(h0);
        }
        *(uint4*)(smem + ar * ROWB + ((t & 3) << 4) + OFF_A) = *(uint4*)w;
    }

    for (int kt = 0; kt < NCH; kt++) {
        const int s = kt & 1;
        int i0n = (kt + 1) * 32;
        if (kt + 1 < NCH) {
            areg = *(const uint4*)(pb + (size_t)(m0 + ar) * NPIX + i0n + ac);
            const uint32_t st = sb + (s ^ 1) * STAGE;
            #pragma unroll
            for (int q = 0; q < 2; q++) {
                int id = t + q * 512;
                int r = id >> 2, c8 = (id & 3) << 3;
                CPASYNC16(st + r * ROWB + ((id & 3) << 4) + OFF_B, xh + (size_t)r * NPIX + i0n + c8);
            }
            CPCOMMIT();
            CPWAIT(1);
        } else {
            CPWAIT(0);
        }
        __syncthreads();

        const uint32_t st = sb + s * STAGE;
        #pragma unroll
        for (int ks = 0; ks < 2; ks++) {
            const int kB = ks * 32;
            uint32_t a_f[2][4];
            #pragma unroll
            for (int ms = 0; ms < 2; ms++) {
                uint32_t ra = st + (wm + ms * 16 + a_row) * ROWB + kB + a_k16;
                ldmx4(a_f[ms], ra + OFF_A);
            }
            #pragma unroll
            for (int np = 0; np < 4; np++) {
                uint32_t rb = st + (wn + np * 16 + b_row) * ROWB + kB + b_k16;
                uint32_t b_f[4];
                ldmx4(b_f, rb + OFF_B);
                #pragma unroll
                for (int ms = 0; ms < 2; ms++) {
                    #pragma unroll
                    for (int nh = 0; nh < 2; nh++) {
                        mma16816h(acc[ms][np * 2 + nh], a_f[ms], b_f + 2 * nh);
                    }
                }
            }
        }

        if (kt + 1 < NCH) {
            const uint32_t* aw = (const uint32_t*)&areg;
            float iv[8];
            #pragma unroll
            for (int k = 0; k < 8; k++) iv[k] = sinvl[i0n + ac + k];
            uint32_t w[4];
            #pragma unroll
            for (int q = 0; q < 4; q++) {
                float lo = __bfloat162float(__ushort_as_bfloat16((unsigned short)(aw[q] & 0xFFFF)));
                float hi = __bfloat162float(__ushort_as_bfloat16((unsigned short)(aw[q] >> 16)));
                __half h0 = __float2half_rn(lo * iv[q * 2]);
                __half h1 = __float2half_rn(hi * iv[q * 2 + 1]);
                w[q] = ((uint32_t)__half_as_ushort(h1) << 16) | (uint32_t)__half_as_ushort(h0);
            }
            *(uint4*)(smem + (s ^ 1) * STAGE + ar * ROWB + ((t & 3) << 4) + OFF_A) = *(uint4*)w;
        }
        __syncthreads();
    }

    // epilogue: out[c][j] = x[c][j] + g * D^T[j][c]
    const float g = gamma[0];
    const float* xb = x   + (size_t)b * CDIM * NPIX;
    float*       ob = out + (size_t)b * CDIM * NPIX;
    const int jq = lane >> 2, cq = (lane & 3) * 2;

    #pragma unroll
    for (int ms = 0; ms < 2; ms++) {
        #pragma unroll
        for (int ni = 0; ni < 8; ni++) {
            int j = m0 + wm + ms * 16 + jq;
            int c = wn + ni * 8 + cq;
            float* a4 = acc[ms][ni];
            ob[(size_t)c * NPIX + j]            = xb[(size_t)c * NPIX + j]            + g * a4[0];
            ob[(size_t)(c + 1) * NPIX + j]      = xb[(size_t)(c + 1) * NPIX + j]      + g * a4[1];
            ob[(size_t)c * NPIX + j + 8]        = xb[(size_t)c * NPIX + j + 8]        + g * a4[2];
            ob[(size_t)(c + 1) * NPIX + j + 8]  = xb[(size_t)(c + 1) * NPIX + j + 8]  + g * a4[3];
        }
    }
}

// ============================================================================
extern "C" void kernel_launch(void* const* d_in, const int* in_sizes, int n_in,
                              void* d_out, int out_size)
{
    const float* x     = (const float*)d_in[0];
    const float* Wf    = (const float*)d_in[1];
    const float* bf    = (const float*)d_in[2];
    const float* Wg    = (const float*)d_in[3];
    const float* bg    = (const float*)d_in[4];
    const float* Wh    = (const float*)d_in[5];
    const float* bh    = (const float*)d_in[6];
    const float* gamma = (const float*)d_in[7];
    float* out = (float*)d_out;

    (void)in_sizes; (void)n_in; (void)out_size;

    cudaFuncSetAttribute(out_gemm_mma, cudaFuncAttributeMaxDynamicSharedMemorySize,
                         GEMM_SMEM);
    cudaFuncSetAttribute(score_kernel, cudaFuncAttributeMaxDynamicSharedMemorySize,
                         SCORE_SMEM);

    dim3 blk(256);
    zero_l_kernel<<<(BATCH * NPIX + 255) / 256, blk>>>();
    proj_kernel<<<dim3(NPIX / 128, CBAR / 32, BATCH), blk>>>(Wf, bf, x, 0);
    proj_kernel<<<dim3(NPIX / 128, CBAR / 32, BATCH), blk>>>(Wg, bg, x, 1);
    proj_kernel<<<dim3(NPIX / 128, CDIM / 32, BATCH), blk>>>(Wh, bh, x, 2);
    score_kernel<<<dim3(NPIX / 64, BATCH), blk, SCORE_SMEM>>>();
    finalize_kernel<<<BATCH * NPIX / 256, blk>>>();
    out_gemm_mma<<<dim3(NPIX / 128, BATCH), 512, GEMM_SMEM>>>(x, gamma, out);
}

// round 13
// speedup vs baseline: 3.1226x; 1.2501x over previous
#include <cuda_runtime.h>
#include <cuda_bf16.h>
#include <cuda_fp16.h>
#include <math.h>
#include <stdint.h>

#define NPIX 4096
#define CDIM 256
#define CBAR 32
#define BATCH 8

// ---- scratch (device globals; no runtime allocation) ----
__device__ float g_l[BATCH * NPIX];
__device__ float g_invl[BATCH * NPIX];
__device__ __nv_bfloat16 g_xfh[BATCH * NPIX * CBAR];           // [b][n][c] hi
__device__ __nv_bfloat16 g_xfl[BATCH * NPIX * CBAR];
__device__ __nv_bfloat16 g_xgh[BATCH * NPIX * CBAR];
__device__ __nv_bfloat16 g_xgl[BATCH * NPIX * CBAR];
__device__ __nv_bfloat16 g_whh[CDIM * CDIM];                   // Wh hi [o][c]
__device__ __nv_bfloat16 g_whl[CDIM * CDIM];                   // Wh lo
__device__ __nv_bfloat16 g_xth[BATCH * NPIX * CDIM];           // 16 MB: x^T hi [b][n][c]
__device__ __nv_bfloat16 g_xtl[BATCH * NPIX * CDIM];           // 16 MB: x^T lo
__device__ __nv_bfloat16 g_ph[(size_t)BATCH * NPIX * NPIX];    // 256 MB: bf16(exp(S^T)) [b][j][i]
__device__ __half g_xh16[BATCH * CDIM * NPIX];                 // 16 MB: fp16(xh) [b][c][i]

// ---- base-ISA helpers (sm_80+) ----
__device__ __forceinline__ uint32_t smem_u32(const void* p) {
    uint32_t a;
    asm("{ .reg .u64 t; cvta.to.shared.u64 t, %1; cvt.u32.u64 %0, t; }" : "=r"(a) : "l"(p));
    return a;
}
#define CPASYNC16(d, s) asm volatile("cp.async.cg.shared.global [%0], [%1], 16;" :: "r"(d), "l"(s) : "memory")
#define CPCOMMIT()      asm volatile("cp.async.commit_group;" ::: "memory")
#define CPWAIT(n)       asm volatile("cp.async.wait_group %0;" :: "n"(n) : "memory")

__device__ __forceinline__ void ldmx4(uint32_t* r, uint32_t addr) {
    asm volatile("ldmatrix.sync.aligned.m8n8.x4.shared.b16 {%0,%1,%2,%3}, [%4];"
                 : "=r"(r[0]), "=r"(r[1]), "=r"(r[2]), "=r"(r[3]) : "r"(addr));
}
__device__ __forceinline__ void mma16816(float* d, const uint32_t* a, const uint32_t* b) {
    asm volatile("mma.sync.aligned.m16n8k16.row.col.f32.bf16.bf16.f32 "
                 "{%0,%1,%2,%3}, {%4,%5,%6,%7}, {%8,%9}, {%0,%1,%2,%3};"
                 : "+f"(d[0]), "+f"(d[1]), "+f"(d[2]), "+f"(d[3])
                 : "r"(a[0]), "r"(a[1]), "r"(a[2]), "r"(a[3]), "r"(b[0]), "r"(b[1]));
}
__device__ __forceinline__ void mma16816h(float* d, const uint32_t* a, const uint32_t* b) {
    asm volatile("mma.sync.aligned.m16n8k16.row.col.f32.f16.f16.f32 "
                 "{%0,%1,%2,%3}, {%4,%5,%6,%7}, {%8,%9}, {%0,%1,%2,%3};"
                 : "+f"(d[0]), "+f"(d[1]), "+f"(d[2]), "+f"(d[3])
                 : "r"(a[0]), "r"(a[1]), "r"(a[2]), "r"(a[3]), "r"(b[0]), "r"(b[1]));
}
__device__ __forceinline__ uint32_t pack_hilo(float v, __nv_bfloat16* hi, __nv_bfloat16* lo) {
    __nv_bfloat16 h = __float2bfloat16(v);
    *hi = h;
    *lo = __float2bfloat16(v - __bfloat162float(h));
    return 0;
}

// ============================================================================
// Kernel 0a: convert Wh -> bf16 hi/lo.  65536 elems.
// ============================================================================
__global__ __launch_bounds__(256) void conv_w_kernel(const float* __restrict__ W)
{
    int idx = (blockIdx.x * 256 + threadIdx.x) * 4;
    float4 w = *(const float4*)(W + idx);
    ushort4 h4, l4;
    float v[4] = {w.x, w.y, w.z, w.w};
    #pragma unroll
    for (int q = 0; q < 4; q++) {
        __nv_bfloat16 h, l;
        pack_hilo(v[q], &h, &l);
        ((unsigned short*)&h4)[q] = __bfloat16_as_ushort(h);
        ((unsigned short*)&l4)[q] = __bfloat16_as_ushort(l);
    }
    *(ushort4*)(g_whh + idx) = h4;
    *(ushort4*)(g_whl + idx) = l4;
}

// ============================================================================
// Kernel 0b: transpose-convert x [b][c][n] fp32 -> x^T bf16 hi/lo [b][n][c].
// Tile 32 c x 128 n, smem-staged.  grid (NPIX/128, CDIM/32, BATCH).
// ============================================================================
__global__ __launch_bounds__(256) void conv_xt_kernel(const float* __restrict__ x)
{
    __shared__ float tile[32][132];
    const int b  = blockIdx.z;
    const int c0 = blockIdx.y * 32;
    const int n0 = blockIdx.x * 128;
    const int t  = threadIdx.x;

    const float* xb = x + (size_t)b * CDIM * NPIX;
    #pragma unroll
    for (int p = 0; p < 4; p++) {
        int idx = t + p * 256;
        int r = idx >> 5, c4 = (idx & 31) << 2;
        *(float4*)&tile[r][c4] = *(const float4*)(xb + (size_t)(c0 + r) * NPIX + n0 + c4);
    }
    __syncthreads();

    #pragma unroll
    for (int p = 0; p < 4; p++) {
        int idx = t + p * 256;          // 1024 tasks: 128 n x 8 c-groups
        int n = idx & 127, cg = idx >> 7;
        ushort4 h4, l4;
        #pragma unroll
        for (int j = 0; j < 4; j++) {
            __nv_bfloat16 h, l;
            pack_hilo(tile[cg * 4 + j][n], &h, &l);
            ((unsigned short*)&h4)[j] = __bfloat16_as_ushort(h);
            ((unsigned short*)&l4)[j] = __bfloat16_as_ushort(l);
        }
        size_t off = ((size_t)b * NPIX + n0 + n) * CDIM + c0 + cg * 4;
        *(ushort4*)(g_xth + off) = h4;
        *(ushort4*)(g_xtl + off) = l4;
    }
}

// ============================================================================
// Kernel 1: f/g projections (scalar fp32, unchanged; writes [n][c] hi/lo).
// ============================================================================
__global__ __launch_bounds__(256) void proj_kernel(
    const float* __restrict__ W, const float* __restrict__ bias,
    const float* __restrict__ x, int mode)
{
    __shared__ float Ws[32][33];
    __shared__ float Xs[32][132];

    const int b  = blockIdx.z;
    const int n0 = blockIdx.x * 128;
    const int t  = threadIdx.x;
    const int tx = t & 31;
    const int ty = t >> 5;

    const float* xb = x + (size_t)b * CDIM * NPIX;

    float acc[4][4] = {};

    for (int k0 = 0; k0 < CDIM; k0 += 32) {
        {
            int o = t >> 3, k4 = (t & 7) << 2;
            float4 w4 = *(const float4*)(W + (size_t)o * CDIM + k0 + k4);
            Ws[o][k4 + 0] = w4.x; Ws[o][k4 + 1] = w4.y;
            Ws[o][k4 + 2] = w4.z; Ws[o][k4 + 3] = w4.w;
        }
        #pragma unroll
        for (int p = 0; p < 4; p++) {
            int idx = t + p * 256;
            int r = idx >> 5, c4 = (idx & 31) << 2;
            *(float4*)&Xs[r][c4] = *(const float4*)(xb + (size_t)(k0 + r) * NPIX + n0 + c4);
        }
        __syncthreads();

        #pragma unroll
        for (int k = 0; k < 32; k++) {
            float a0 = Ws[ty * 4 + 0][k];
            float a1 = Ws[ty * 4 + 1][k];
            float a2 = Ws[ty * 4 + 2][k];
            float a3 = Ws[ty * 4 + 3][k];
            float4 bv = *(float4*)&Xs[k][tx * 4];
            acc[0][0] += a0 * bv.x; acc[0][1] += a0 * bv.y; acc[0][2] += a0 * bv.z; acc[0][3] += a0 * bv.w;
            acc[1][0] += a1 * bv.x; acc[1][1] += a1 * bv.y; acc[1][2] += a1 * bv.z; acc[1][3] += a1 * bv.w;
            acc[2][0] += a2 * bv.x; acc[2][1] += a2 * bv.y; acc[2][2] += a2 * bv.z; acc[2][3] += a2 * bv.w;
            acc[3][0] += a3 * bv.x; acc[3][1] += a3 * bv.y; acc[3][2] += a3 * bv.z; acc[3][3] += a3 * bv.w;
        }
        __syncthreads();
    }

    __nv_bfloat16* yh = (mode == 0) ? g_xfh : g_xgh;
    __nv_bfloat16* yl = (mode == 0) ? g_xfl : g_xgl;
    float bb[4];
    #pragma unroll
    for (int i = 0; i < 4; i++) bb[i] = bias[ty * 4 + i];
    #pragma unroll
    for (int j = 0; j < 4; j++) {
        int n = n0 + tx * 4 + j;
        ushort4 h4, l4;
        #pragma unroll
        for (int i = 0; i < 4; i++) {
            __nv_bfloat16 h, l;
            pack_hilo(acc[i][j] + bb[i], &h, &l);
            ((unsigned short*)&h4)[i] = __bfloat16_as_ushort(h);
            ((unsigned short*)&l4)[i] = __bfloat16_as_ushort(l);
        }
        size_t off = ((size_t)b * NPIX + n) * CBAR + ty * 4;
        *(ushort4*)(yh + off) = h4;
        *(ushort4*)(yl + off) = l4;
    }
}

// ============================================================================
// Kernel 1b: h-projection on tensor cores (split-bf16, 3 products).
//   xh16[b][o][n] = fp16( sum_c Wh[o][c]*x[b][c][n] + bh[o] )
// A = Wh hi/lo [o][c], B = x^T hi/lo [b][n][c].  BM=128 (o), BN=256 (n),
// BK=32, K=256 (8 chunks).  512 thr, warp tile 32x64, double buffer.
// grid (NPIX/256, CDIM/128, BATCH).  dyn smem = 2*61440 = 122880.
// ============================================================================
#define PROWB 80
#define P_AL 10240
#define P_BH 20480
#define P_BL 40960
#define PSTAGE 61440

__global__ __launch_bounds__(512, 1) void proj_tc_kernel(const float* __restrict__ bias)
{
    extern __shared__ char smem[];
    const uint32_t sb = smem_u32(smem);

    const int b  = blockIdx.z;
    const int m0 = blockIdx.y * 128;   // o
    const int n0 = blockIdx.x * 256;   // n
    const int t  = threadIdx.x;
    const int warp = t >> 5, lane = t & 31;
    const int wm = (warp & 3) * 32;
    const int wn = (warp >> 2) * 64;

    const __nv_bfloat16* bth = g_xth + (size_t)b * NPIX * CDIM;
    const __nv_bfloat16* btl = g_xtl + (size_t)b * NPIX * CDIM;

    float acc[2][8][4];
    #pragma unroll
    for (int i = 0; i < 2; i++)
        #pragma unroll
        for (int j = 0; j < 8; j++)
            #pragma unroll
            for (int q = 0; q < 4; q++) acc[i][j][q] = 0.f;

    const int a_row = lane & 15, a_k16 = (lane >> 4) << 4;
    const int b_row = (lane & 7) + ((lane >> 4) & 1) * 8;
    const int b_k16 = ((lane >> 3) & 1) * 16;

    const int NCH = CDIM / 32;   // 8

    // issue chunk ck into stage s
    auto issue = [&](int ck, int s) {
        const uint32_t st = sb + s * PSTAGE;
        const int k0 = ck * 32;
        {   // A: 128 rows x 64B, hi+lo  (512 tasks each -> 1/thread)
            int r = t >> 2, g = t & 3;
            const __nv_bfloat16* sh = g_whh + (size_t)(m0 + r) * CDIM + k0 + g * 8;
            const __nv_bfloat16* sl = g_whl + (size_t)(m0 + r) * CDIM + k0 + g * 8;
            uint32_t d = st + r * PROWB + g * 16;
            CPASYNC16(d, sh);
            CPASYNC16(d + P_AL, sl);
        }
        #pragma unroll
        for (int q = 0; q < 2; q++) {   // B: 256 rows, hi+lo (1024 tasks each)
            int id = t + q * 512;
            int r = id >> 2, g = id & 3;
            const __nv_bfloat16* sh = bth + (size_t)(n0 + r) * CDIM + k0 + g * 8;
            const __nv_bfloat16* sl = btl + (size_t)(n0 + r) * CDIM + k0 + g * 8;
            uint32_t d = st + r * PROWB + g * 16;
            CPASYNC16(d + P_BH, sh);
            CPASYNC16(d + P_BL, sl);
        }
        CPCOMMIT();
    };

    issue(0, 0);
    for (int ck = 0; ck < NCH; ck++) {
        const int s = ck & 1;
        if (ck + 1 < NCH) { issue(ck + 1, s ^ 1); CPWAIT(1); }
        else              { CPWAIT(0); }
        __syncthreads();

        const uint32_t st = sb + s * PSTAGE;
        #pragma unroll
        for (int ks = 0; ks < 2; ks++) {
            const int kB = ks * 32;
            uint32_t a_h[2][4], a_l[2][4];
            #pragma unroll
            for (int ms = 0; ms < 2; ms++) {
                uint32_t ra = st + (wm + ms * 16 + a_row) * PROWB + kB + a_k16;
                ldmx4(a_h[ms], ra);
                ldmx4(a_l[ms], ra + P_AL);
            }
            #pragma unroll
            for (int np = 0; np < 4; np++) {
                uint32_t rb = st + (wn + np * 16 + b_row) * PROWB + kB + b_k16;
                uint32_t b_h[4], b_l[4];
                ldmx4(b_h, rb + P_BH);
                ldmx4(b_l, rb + P_BL);
                #pragma unroll
                for (int ms = 0; ms < 2; ms++) {
                    #pragma unroll
                    for (int nh = 0; nh < 2; nh++) {
                        float* d = acc[ms][np * 2 + nh];
                        mma16816(d, a_h[ms], b_h + 2 * nh);
                        mma16816(d, a_h[ms], b_l + 2 * nh);
                        mma16816(d, a_l[ms], b_h + 2 * nh);
                    }
                }
            }
        }
        __syncthreads();
    }

    // epilogue: xh16[o][n] = fp16(acc + bias[o]);  d0,d1 -> row jq; d2,d3 -> jq+8
    const int jq = lane >> 2, cq = (lane & 3) * 2;
    #pragma unroll
    for (int ms = 0; ms < 2; ms++) {
        int o0r = m0 + wm + ms * 16 + jq;
        float b0 = bias[o0r], b1 = bias[o0r + 8];
        __half* row0 = g_xh16 + ((size_t)b * CDIM + o0r) * NPIX;
        __half* row1 = g_xh16 + ((size_t)b * CDIM + o0r + 8) * NPIX;
        #pragma unroll
        for (int ni = 0; ni < 8; ni++) {
            int n = n0 + wn + ni * 8 + cq;
            float* a4 = acc[ms][ni];
            __half h00 = __float2half_rn(a4[0] + b0);
            __half h01 = __float2half_rn(a4[1] + b0);
            __half h10 = __float2half_rn(a4[2] + b1);
            __half h11 = __float2half_rn(a4[3] + b1);
            *(uint32_t*)(row0 + n) = ((uint32_t)__half_as_ushort(h01) << 16) | __half_as_ushort(h00);
            *(uint32_t*)(row1 + n) = ((uint32_t)__half_as_ushort(h11) << 16) | __half_as_ushort(h10);
        }
    }
}

// ============================================================================
// Kernel 2a: zero the l accumulator
// ============================================================================
__global__ void zero_l_kernel() {
    int t = blockIdx.x * blockDim.x + threadIdx.x;
    if (t < BATCH * NPIX) g_l[t] = 0.0f;
}

// ============================================================================
// Kernel 2b: scores on tensor cores + smem-staged coalesced p stores
// (unchanged from R12; validated).
// ============================================================================
#define SROWB 80
#define SA_LO 5120
#define SB_LO 10240
#define SB_STAGE 20480
#define SA_BYTES 10240
#define PST_OFF (SA_BYTES + 2 * SB_STAGE)
#define PST_ROWB 272
#define SCORE_SMEM (PST_OFF + 64 * PST_ROWB)

__global__ __launch_bounds__(256, 2) void score_kernel()
{
    extern __shared__ char smem[];
    const uint32_t sa = smem_u32(smem);
    const uint32_t sb0 = sa + SA_BYTES;
    char* pst = smem + PST_OFF;

    const int b  = blockIdx.y;
    const int j0 = blockIdx.x * 64;
    const int t  = threadIdx.x;
    const int warp = t >> 5, lane = t & 31;
    const int wm = (warp & 1) * 32;
    const int wn = (warp >> 1) * 32;

    const __nv_bfloat16* xfh = g_xfh + (size_t)b * NPIX * CBAR;
    const __nv_bfloat16* xfl = g_xfl + (size_t)b * NPIX * CBAR;
    const __nv_bfloat16* xgh = g_xgh + (size_t)b * NPIX * CBAR;
    const __nv_bfloat16* xgl = g_xgl + (size_t)b * NPIX * CBAR;
    __nv_bfloat16* ph = g_ph + (size_t)b * NPIX * NPIX;
    float* lrow = g_l + b * NPIX;

    #pragma unroll
    for (int q = 0; q < 2; q++) {
        int id = t + q * 256;
        int r = id >> 2, g16 = id & 3;
        const __nv_bfloat16* src = ((r < 64) ? xgh : xgl) + ((size_t)(j0 + (r & 63))) * CBAR + g16 * 8;
        CPASYNC16(sa + r * SROWB + g16 * 16, src);
    }
    #pragma unroll
    for (int q = 0; q < 4; q++) {
        int id = t + q * 256;
        int r = id >> 2, g16 = id & 3;
        const __nv_bfloat16* src = ((r < 128) ? xfh : xfl) + ((size_t)(r & 127)) * CBAR + g16 * 8;
        CPASYNC16(sb0 + r * SROWB + g16 * 16, src);
    }
    CPCOMMIT();

    const int a_row = lane & 15, a_k16 = (lane >> 4) << 4;
    const int b_row = (lane & 7) + ((lane >> 4) & 1) * 8;
    const int b_k16 = ((lane >> 3) & 1) * 16;

    const int NIT = NPIX / 128;

    for (int it = 0; it < NIT; it++) {
        const int s = it & 1;
        if (it + 1 < NIT) {
            const int i0n = (it + 1) * 128;
            const uint32_t st = sb0 + (s ^ 1) * SB_STAGE;
            #pragma unroll
            for (int q = 0; q < 4; q++) {
                int id = t + q * 256;
                int r = id >> 2, g16 = id & 3;
                const __nv_bfloat16* src = ((r < 128) ? xfh : xfl) + ((size_t)(i0n + (r & 127))) * CBAR + g16 * 8;
                CPASYNC16(st + r * SROWB + g16 * 16, src);
            }
            CPCOMMIT();
            CPWAIT(1);
        } else {
            CPWAIT(0);
        }
        __syncthreads();

        const uint32_t stg = sb0 + s * SB_STAGE;
        float sacc[2][4][4];
        #pragma unroll
        for (int m = 0; m < 2; m++)
            #pragma unroll
            for (int n = 0; n < 4; n++)
                #pragma unroll
                for (int q = 0; q < 4; q++) sacc[m][n][q] = 0.f;

        #pragma unroll
        for (int ks = 0; ks < 2; ks++) {
            const int kB = ks * 32;
            uint32_t a_h[2][4], a_l[2][4];
            #pragma unroll
            for (int ms = 0; ms < 2; ms++) {
                uint32_t ra = sa + (wm + ms * 16 + a_row) * SROWB + kB + a_k16;
                ldmx4(a_h[ms], ra);
                ldmx4(a_l[ms], ra + SA_LO);
            }
            #pragma unroll
            for (int np = 0; np < 2; np++) {
                uint32_t rb = stg + (wn + np * 16 + b_row) * SROWB + kB + b_k16;
                uint32_t b_h[4], b_l[4];
                ldmx4(b_h, rb);
                ldmx4(b_l, rb + SB_LO);
                #pragma unroll
                for (int ms = 0; ms < 2; ms++) {
                    #pragma unroll
                    for (int nh = 0; nh < 2; nh++) {
                        float* d = sacc[ms][np * 2 + nh];
                        mma16816(d, a_h[ms], b_h + 2 * nh);
                        mma16816(d, a_h[ms], b_l + 2 * nh);
                        mma16816(d, a_l[ms], b_h + 2 * nh);
                    }
                }
            }
        }

        const int i0 = it * 128;
        #pragma unroll
        for (int nn = 0; nn < 4; nn++) {
            const int icl = wn + nn * 8 + (lane & 3) * 2;
            float cs0 = 0.f, cs1 = 0.f;
            #pragma unroll
            for (int ms = 0; ms < 2; ms++) {
                float* d = sacc[ms][nn];
                float p0 = __expf(d[0]);
                float p1 = __expf(d[1]);
                float p2 = __expf(d[2]);
                float p3 = __expf(d[3]);
                cs0 += p0 + p2; cs1 += p1 + p3;
                const int jl = wm + ms * 16 + (lane >> 2);
                uint32_t pk01 = ((uint32_t)__bfloat16_as_ushort(__float2bfloat16(p1)) << 16)
                              |  (uint32_t)__bfloat16_as_ushort(__float2bfloat16(p0));
                uint32_t pk23 = ((uint32_t)__bfloat16_as_ushort(__float2bfloat16(p3)) << 16)
                              |  (uint32_t)__bfloat16_as_ushort(__float2bfloat16(p2));
                *(uint32_t*)(pst + jl * PST_ROWB + icl * 2)       = pk01;
                *(uint32_t*)(pst + (jl + 8) * PST_ROWB + icl * 2) = pk23;
            }
            #pragma unroll
            for (int off = 4; off <= 16; off <<= 1) {
                cs0 += __shfl_xor_sync(0xffffffffu, cs0, off);
                cs1 += __shfl_xor_sync(0xffffffffu, cs1, off);
            }
            if (lane < 4) {
                atomicAdd(lrow + i0 + icl, cs0);
                atomicAdd(lrow + i0 + icl + 1, cs1);
            }
        }
        __syncthreads();

        #pragma unroll
        for (int q = 0; q < 4; q++) {
            int id = q * 256 + t;
            int jl = id >> 4, w16 = id & 15;
            uint4 v = *(uint4*)(pst + jl * PST_ROWB + w16 * 16);
            *(uint4*)(ph + (size_t)(j0 + jl) * NPIX + i0 + w16 * 8) = v;
        }
        __syncthreads();
    }
}

// ============================================================================
// Kernel 2c: finalize.  invl = 1/l only (xh16 produced by proj_tc).
// ============================================================================
__global__ __launch_bounds__(256) void finalize_kernel()
{
    int idx = blockIdx.x * blockDim.x + threadIdx.x;
    if (idx < BATCH * NPIX) g_invl[idx] = 1.0f / g_l[idx];
}

// ============================================================================
// Kernel 3: output GEMM, fp16 mma, beta fused into A-path (unchanged R12).
// ============================================================================
#define ROWB 80
#define OFF_A 0
#define OFF_B 10240
#define STAGE 30720
#define INVL_OFF (2 * STAGE)
#define GEMM_SMEM (INVL_OFF + NPIX * 4)

__global__ __launch_bounds__(512, 1) void out_gemm_mma(
    const float* __restrict__ x, const float* __restrict__ gamma,
    float* __restrict__ out)
{
    extern __shared__ char smem[];
    const uint32_t sb = smem_u32(smem);
    float* sinvl = (float*)(smem + INVL_OFF);

    const int b  = blockIdx.y;
    const int m0 = blockIdx.x * 128;
    const int t  = threadIdx.x;
    const int warp = t >> 5, lane = t & 31;
    const int wm = (warp & 3) * 32;
    const int wn = (warp >> 2) * 64;

    const __nv_bfloat16* pb = g_ph + (size_t)b * NPIX * NPIX;
    const __half* xh = g_xh16 + (size_t)b * CDIM * NPIX;
    const float* invl = g_invl + b * NPIX;

    const int ar = t >> 2, ac = (t & 3) << 3;
    float acc[2][8][4];
    #pragma unroll
    for (int i = 0; i < 2; i++)
        #pragma unroll
        for (int j = 0; j < 8; j++)
            #pragma unroll
            for (int q = 0; q < 4; q++) acc[i][j][q] = 0.f;

    const int a_row = lane & 15, a_k16 = (lane >> 4) << 4;
    const int b_row = (lane & 7) + ((lane >> 4) & 1) * 8;
    const int b_k16 = ((lane >> 3) & 1) * 16;

    const int NCH = NPIX / 32;

    {
        int vi = t * 8;
        *(float4*)(sinvl + vi)     = *(const float4*)(invl + vi);
        *(float4*)(sinvl + vi + 4) = *(const float4*)(invl + vi + 4);
    }
    uint4 areg = *(const uint4*)(pb + (size_t)(m0 + ar) * NPIX + ac);
    {
        const uint32_t st = sb;
        #pragma unroll
        for (int q = 0; q < 2; q++) {
            int id = t + q * 512;
            int r = id >> 2, c8 = (id & 3) << 3;
            CPASYNC16(st + r * ROWB + ((id & 3) << 4) + OFF_B, xh + (size_t)r * NPIX + c8);
        }
        CPCOMMIT();
    }
    __syncthreads();
    {
        const uint32_t* aw = (const uint32_t*)&areg;
        float iv[8];
        #pragma unroll
        for (int k = 0; k < 8; k++) iv[k] = sinvl[ac + k];
        uint32_t w[4];
        #pragma unroll
        for (int q = 0; q < 4; q++) {
            float lo = __bfloat162float(__ushort_as_bfloat16((unsigned short)(aw[q] & 0xFFFF)));
            float hi = __bfloat162float(__ushort_as_bfloat16((unsigned short)(aw[q] >> 16)));
            __half h0 = __float2half_rn(lo * iv[q * 2]);
            __half h1 = __float2half_rn(hi * iv[q * 2 + 1]);
            w[q] = ((uint32_t)__half_as_ushort(h1) << 16) | (uint32_t)__half_as_ushort(h0);
        }
        *(uint4*)(smem + ar * ROWB + ((t & 3) << 4) + OFF_A) = *(uint4*)w;
    }

    for (int kt = 0; kt < NCH; kt++) {
        const int s = kt & 1;
        int i0n = (kt + 1) * 32;
        if (kt + 1 < NCH) {
            areg = *(const uint4*)(pb + (size_t)(m0 + ar) * NPIX + i0n + ac);
            const uint32_t st = sb + (s ^ 1) * STAGE;
            #pragma unroll
            for (int q = 0; q < 2; q++) {
                int id = t + q * 512;
                int r = id >> 2, c8 = (id & 3) << 3;
                CPASYNC16(st + r * ROWB + ((id & 3) << 4) + OFF_B, xh + (size_t)r * NPIX + i0n + c8);
            }
            CPCOMMIT();
            CPWAIT(1);
        } else {
            CPWAIT(0);
        }
        __syncthreads();

        const uint32_t st = sb + s * STAGE;
        #pragma unroll
        for (int ks = 0; ks < 2; ks++) {
            const int kB = ks * 32;
            uint32_t a_f[2][4];
            #pragma unroll
            for (int ms = 0; ms < 2; ms++) {
                uint32_t ra = st + (wm + ms * 16 + a_row) * ROWB + kB + a_k16;
                ldmx4(a_f[ms], ra + OFF_A);
            }
            #pragma unroll
            for (int np = 0; np < 4; np++) {
                uint32_t rb = st + (wn + np * 16 + b_row) * ROWB + kB + b_k16;
                uint32_t b_f[4];
                ldmx4(b_f, rb + OFF_B);
                #pragma unroll
                for (int ms = 0; ms < 2; ms++) {
                    #pragma unroll
                    for (int nh = 0; nh < 2; nh++) {
                        mma16816h(acc[ms][np * 2 + nh], a_f[ms], b_f + 2 * nh);
                    }
                }
            }
        }

        if (kt + 1 < NCH) {
            const uint32_t* aw = (const uint32_t*)&areg;
            float iv[8];
            #pragma unroll
            for (int k = 0; k < 8; k++) iv[k] = sinvl[i0n + ac + k];
            uint32_t w[4];
            #pragma unroll
            for (int q = 0; q < 4; q++) {
                float lo = __bfloat162float(__ushort_as_bfloat16((unsigned short)(aw[q] & 0xFFFF)));
                float hi = __bfloat162float(__ushort_as_bfloat16((unsigned short)(aw[q] >> 16)));
                __half h0 = __float2half_rn(lo * iv[q * 2]);
                __half h1 = __float2half_rn(hi * iv[q * 2 + 1]);
                w[q] = ((uint32_t)__half_as_ushort(h1) << 16) | (uint32_t)__half_as_ushort(h0);
            }
            *(uint4*)(smem + (s ^ 1) * STAGE + ar * ROWB + ((t & 3) << 4) + OFF_A) = *(uint4*)w;
        }
        __syncthreads();
    }

    const float g = gamma[0];
    const float* xb = x   + (size_t)b * CDIM * NPIX;
    float*       ob = out + (size_t)b * CDIM * NPIX;
    const int jq = lane >> 2, cq = (lane & 3) * 2;

    #pragma unroll
    for (int ms = 0; ms < 2; ms++) {
        #pragma unroll
        for (int ni = 0; ni < 8; ni++) {
            int j = m0 + wm + ms * 16 + jq;
            int c = wn + ni * 8 + cq;
            float* a4 = acc[ms][ni];
            ob[(size_t)c * NPIX + j]            = xb[(size_t)c * NPIX + j]            + g * a4[0];
            ob[(size_t)(c + 1) * NPIX + j]      = xb[(size_t)(c + 1) * NPIX + j]      + g * a4[1];
            ob[(size_t)c * NPIX + j + 8]        = xb[(size_t)c * NPIX + j + 8]        + g * a4[2];
            ob[(size_t)(c + 1) * NPIX + j + 8]  = xb[(size_t)(c + 1) * NPIX + j + 8]  + g * a4[3];
        }
    }
}

// ============================================================================
extern "C" void kernel_launch(void* const* d_in, const int* in_sizes, int n_in,
                              void* d_out, int out_size)
{
    const float* x     = (const float*)d_in[0];
    const float* Wf    = (const float*)d_in[1];
    const float* bf    = (const float*)d_in[2];
    const float* Wg    = (const float*)d_in[3];
    const float* bg    = (const float*)d_in[4];
    const float* Wh    = (const float*)d_in[5];
    const float* bh    = (const float*)d_in[6];
    const float* gamma = (const float*)d_in[7];
    float* out = (float*)d_out;

    (void)in_sizes; (void)n_in; (void)out_size;

    cudaFuncSetAttribute(out_gemm_mma, cudaFuncAttributeMaxDynamicSharedMemorySize,
                         GEMM_SMEM);
    cudaFuncSetAttribute(score_kernel, cudaFuncAttributeMaxDynamicSharedMemorySize,
                         SCORE_SMEM);
    cudaFuncSetAttribute(proj_tc_kernel, cudaFuncAttributeMaxDynamicSharedMemorySize,
                         2 * PSTAGE);

    dim3 blk(256);
    zero_l_kernel<<<(BATCH * NPIX + 255) / 256, blk>>>();
    conv_w_kernel<<<CDIM * CDIM / 1024, blk>>>(Wh);
    conv_xt_kernel<<<dim3(NPIX / 128, CDIM / 32, BATCH), blk>>>(x);
    proj_kernel<<<dim3(NPIX / 128, 1, BATCH), blk>>>(Wf, bf, x, 0);
    proj_kernel<<<dim3(NPIX / 128, 1, BATCH), blk>>>(Wg, bg, x, 1);
    proj_tc_kernel<<<dim3(NPIX / 256, CDIM / 128, BATCH), 512, 2 * PSTAGE>>>(bh);
    score_kernel<<<dim3(NPIX / 64, BATCH), blk, SCORE_SMEM>>>();
    finalize_kernel<<<(BATCH * NPIX + 255) / 256, blk>>>();
    out_gemm_mma<<<dim3(NPIX / 128, BATCH), 512, GEMM_SMEM>>>(x, gamma, out);
}

// round 14
// speedup vs baseline: 3.6205x; 1.1594x over previous
#include <cuda_runtime.h>
#include <cuda_bf16.h>
#include <cuda_fp16.h>
#include <math.h>
#include <stdint.h>

#define NPIX 4096
#define CDIM 256
#define CBAR 32
#define BATCH 8

// ---- scratch (device globals; no runtime allocation) ----
__device__ float g_l[BATCH * NPIX];
__device__ float g_invl[BATCH * NPIX];
__device__ __nv_bfloat16 g_xfh[BATCH * NPIX * CBAR];           // [b][n][c] hi
__device__ __nv_bfloat16 g_xfl[BATCH * NPIX * CBAR];
__device__ __nv_bfloat16 g_xgh[BATCH * NPIX * CBAR];
__device__ __nv_bfloat16 g_xgl[BATCH * NPIX * CBAR];
__device__ __nv_bfloat16 g_whh[CDIM * CDIM];                   // Wh hi [o][c]
__device__ __nv_bfloat16 g_whl[CDIM * CDIM];
__device__ __nv_bfloat16 g_xth[BATCH * NPIX * CDIM];           // x^T hi [b][n][c]
__device__ __nv_bfloat16 g_xtl[BATCH * NPIX * CDIM];
__device__ __nv_bfloat16 g_ph[(size_t)BATCH * NPIX * NPIX];    // 256 MB: bf16(exp(S^T)) [b][j][i]
__device__ __half g_xh16[BATCH * CDIM * NPIX];                 // fp16(xh) [b][c][i]

// ---- base-ISA helpers (sm_80+) ----
__device__ __forceinline__ uint32_t smem_u32(const void* p) {
    uint32_t a;
    asm("{ .reg .u64 t; cvta.to.shared.u64 t, %1; cvt.u32.u64 %0, t; }" : "=r"(a) : "l"(p));
    return a;
}
#define CPASYNC16(d, s) asm volatile("cp.async.cg.shared.global [%0], [%1], 16;" :: "r"(d), "l"(s) : "memory")
#define CPCOMMIT()      asm volatile("cp.async.commit_group;" ::: "memory")
#define CPWAIT(n)       asm volatile("cp.async.wait_group %0;" :: "n"(n) : "memory")

__device__ __forceinline__ void ldmx4(uint32_t* r, uint32_t addr) {
    asm volatile("ldmatrix.sync.aligned.m8n8.x4.shared.b16 {%0,%1,%2,%3}, [%4];"
                 : "=r"(r[0]), "=r"(r[1]), "=r"(r[2]), "=r"(r[3]) : "r"(addr));
}
__device__ __forceinline__ void mma16816(float* d, const uint32_t* a, const uint32_t* b) {
    asm volatile("mma.sync.aligned.m16n8k16.row.col.f32.bf16.bf16.f32 "
                 "{%0,%1,%2,%3}, {%4,%5,%6,%7}, {%8,%9}, {%0,%1,%2,%3};"
                 : "+f"(d[0]), "+f"(d[1]), "+f"(d[2]), "+f"(d[3])
                 : "r"(a[0]), "r"(a[1]), "r"(a[2]), "r"(a[3]), "r"(b[0]), "r"(b[1]));
}
__device__ __forceinline__ void mma16816h(float* d, const uint32_t* a, const uint32_t* b) {
    asm volatile("mma.sync.aligned.m16n8k16.row.col.f32.f16.f16.f32 "
                 "{%0,%1,%2,%3}, {%4,%5,%6,%7}, {%8,%9}, {%0,%1,%2,%3};"
                 : "+f"(d[0]), "+f"(d[1]), "+f"(d[2]), "+f"(d[3])
                 : "r"(a[0]), "r"(a[1]), "r"(a[2]), "r"(a[3]), "r"(b[0]), "r"(b[1]));
}
__device__ __forceinline__ void pack_hilo(float v, __nv_bfloat16* hi, __nv_bfloat16* lo) {
    __nv_bfloat16 h = __float2bfloat16(v);
    *hi = h;
    *lo = __float2bfloat16(v - __bfloat162float(h));
}

// ============================================================================
// Kernel 0a: Wh -> bf16 hi/lo
// ============================================================================
__global__ __launch_bounds__(256) void conv_w_kernel(const float* __restrict__ W)
{
    int idx = (blockIdx.x * 256 + threadIdx.x) * 4;
    float4 w = *(const float4*)(W + idx);
    ushort4 h4, l4;
    float v[4] = {w.x, w.y, w.z, w.w};
    #pragma unroll
    for (int q = 0; q < 4; q++) {
        __nv_bfloat16 h, l;
        pack_hilo(v[q], &h, &l);
        ((unsigned short*)&h4)[q] = __bfloat16_as_ushort(h);
        ((unsigned short*)&l4)[q] = __bfloat16_as_ushort(l);
    }
    *(ushort4*)(g_whh + idx) = h4;
    *(ushort4*)(g_whl + idx) = l4;
}

// ============================================================================
// Kernel 0b: transpose-convert x -> x^T bf16 hi/lo [b][n][c]
// ============================================================================
__global__ __launch_bounds__(256) void conv_xt_kernel(const float* __restrict__ x)
{
    __shared__ float tile[32][132];
    const int b  = blockIdx.z;
    const int c0 = blockIdx.y * 32;
    const int n0 = blockIdx.x * 128;
    const int t  = threadIdx.x;

    const float* xb = x + (size_t)b * CDIM * NPIX;
    #pragma unroll
    for (int p = 0; p < 4; p++) {
        int idx = t + p * 256;
        int r = idx >> 5, c4 = (idx & 31) << 2;
        *(float4*)&tile[r][c4] = *(const float4*)(xb + (size_t)(c0 + r) * NPIX + n0 + c4);
    }
    __syncthreads();

    #pragma unroll
    for (int p = 0; p < 4; p++) {
        int idx = t + p * 256;
        int n = idx & 127, cg = idx >> 7;
        ushort4 h4, l4;
        #pragma unroll
        for (int j = 0; j < 4; j++) {
            __nv_bfloat16 h, l;
            pack_hilo(tile[cg * 4 + j][n], &h, &l);
            ((unsigned short*)&h4)[j] = __bfloat16_as_ushort(h);
            ((unsigned short*)&l4)[j] = __bfloat16_as_ushort(l);
        }
        size_t off = ((size_t)b * NPIX + n0 + n) * CDIM + c0 + cg * 4;
        *(ushort4*)(g_xth + off) = h4;
        *(ushort4*)(g_xtl + off) = l4;
    }
}

// ============================================================================
// Kernel 1: FUSED f+g projections — x streamed ONCE, both 32-row weight
// blocks resident (Ws rows 0-31 = Wf, 32-63 = Wg).
// ============================================================================
__global__ __launch_bounds__(256) void proj_fg_kernel(
    const float* __restrict__ Wf, const float* __restrict__ bf,
    const float* __restrict__ Wg, const float* __restrict__ bg,
    const float* __restrict__ x)
{
    __shared__ float Ws[64][33];
    __shared__ float Xs[32][132];

    const int b  = blockIdx.z;
    const int n0 = blockIdx.x * 128;
    const int t  = threadIdx.x;
    const int tx = t & 31;
    const int ty = t >> 5;

    const float* xb = x + (size_t)b * CDIM * NPIX;

    float af[4][4] = {};
    float ag[4][4] = {};

    for (int k0 = 0; k0 < CDIM; k0 += 32) {
        #pragma unroll
        for (int q = 0; q < 2; q++) {
            int id = t + q * 256;
            int row = id >> 3, c4 = (id & 7) << 2;
            const float* src = (row < 32) ? (Wf + (size_t)row * CDIM)
                                          : (Wg + (size_t)(row - 32) * CDIM);
            float4 w4 = *(const float4*)(src + k0 + c4);
            Ws[row][c4 + 0] = w4.x; Ws[row][c4 + 1] = w4.y;
            Ws[row][c4 + 2] = w4.z; Ws[row][c4 + 3] = w4.w;
        }
        #pragma unroll
        for (int p = 0; p < 4; p++) {
            int idx = t + p * 256;
            int r = idx >> 5, c4 = (idx & 31) << 2;
            *(float4*)&Xs[r][c4] = *(const float4*)(xb + (size_t)(k0 + r) * NPIX + n0 + c4);
        }
        __syncthreads();

        #pragma unroll
        for (int k = 0; k < 32; k++) {
            float4 bv = *(float4*)&Xs[k][tx * 4];
            #pragma unroll
            for (int i = 0; i < 4; i++) {
                float wf = Ws[ty * 4 + i][k];
                float wg = Ws[32 + ty * 4 + i][k];
                af[i][0] += wf * bv.x; af[i][1] += wf * bv.y; af[i][2] += wf * bv.z; af[i][3] += wf * bv.w;
                ag[i][0] += wg * bv.x; ag[i][1] += wg * bv.y; ag[i][2] += wg * bv.z; ag[i][3] += wg * bv.w;
            }
        }
        __syncthreads();
    }

    float bbf[4], bbg[4];
    #pragma unroll
    for (int i = 0; i < 4; i++) { bbf[i] = bf[ty * 4 + i]; bbg[i] = bg[ty * 4 + i]; }
    #pragma unroll
    for (int j = 0; j < 4; j++) {
        int n = n0 + tx * 4 + j;
        ushort4 fh4, fl4, gh4, gl4;
        #pragma unroll
        for (int i = 0; i < 4; i++) {
            __nv_bfloat16 h, l;
            pack_hilo(af[i][j] + bbf[i], &h, &l);
            ((unsigned short*)&fh4)[i] = __bfloat16_as_ushort(h);
            ((unsigned short*)&fl4)[i] = __bfloat16_as_ushort(l);
            pack_hilo(ag[i][j] + bbg[i], &h, &l);
            ((unsigned short*)&gh4)[i] = __bfloat16_as_ushort(h);
            ((unsigned short*)&gl4)[i] = __bfloat16_as_ushort(l);
        }
        size_t off = ((size_t)b * NPIX + n) * CBAR + ty * 4;
        *(ushort4*)(g_xfh + off) = fh4;
        *(ushort4*)(g_xfl + off) = fl4;
        *(ushort4*)(g_xgh + off) = gh4;
        *(ushort4*)(g_xgl + off) = gl4;
    }
}

// ============================================================================
// Kernel 1b: h-projection on tensor cores (unchanged R13; validated).
// ============================================================================
#define PROWB 80
#define P_AL 10240
#define P_BH 20480
#define P_BL 40960
#define PSTAGE 61440

__global__ __launch_bounds__(512, 1) void proj_tc_kernel(const float* __restrict__ bias)
{
    extern __shared__ char smem[];
    const uint32_t sb = smem_u32(smem);

    const int b  = blockIdx.z;
    const int m0 = blockIdx.y * 128;
    const int n0 = blockIdx.x * 256;
    const int t  = threadIdx.x;
    const int warp = t >> 5, lane = t & 31;
    const int wm = (warp & 3) * 32;
    const int wn = (warp >> 2) * 64;

    const __nv_bfloat16* bth = g_xth + (size_t)b * NPIX * CDIM;
    const __nv_bfloat16* btl = g_xtl + (size_t)b * NPIX * CDIM;

    float acc[2][8][4];
    #pragma unroll
    for (int i = 0; i < 2; i++)
        #pragma unroll
        for (int j = 0; j < 8; j++)
            #pragma unroll
            for (int q = 0; q < 4; q++) acc[i][j][q] = 0.f;

    const int a_row = lane & 15, a_k16 = (lane >> 4) << 4;
    const int b_row = (lane & 7) + ((lane >> 4) & 1) * 8;
    const int b_k16 = ((lane >> 3) & 1) * 16;

    const int NCH = CDIM / 32;

    auto issue = [&](int ck, int s) {
        const uint32_t st = sb + s * PSTAGE;
        const int k0 = ck * 32;
        {
            int r = t >> 2, g = t & 3;
            const __nv_bfloat16* sh = g_whh + (size_t)(m0 + r) * CDIM + k0 + g * 8;
            const __nv_bfloat16* sl = g_whl + (size_t)(m0 + r) * CDIM + k0 + g * 8;
            uint32_t d = st + r * PROWB + g * 16;
            CPASYNC16(d, sh);
            CPASYNC16(d + P_AL, sl);
        }
        #pragma unroll
        for (int q = 0; q < 2; q++) {
            int id = t + q * 512;
            int r = id >> 2, g = id & 3;
            const __nv_bfloat16* sh = bth + (size_t)(n0 + r) * CDIM + k0 + g * 8;
            const __nv_bfloat16* sl = btl + (size_t)(n0 + r) * CDIM + k0 + g * 8;
            uint32_t d = st + r * PROWB + g * 16;
            CPASYNC16(d + P_BH, sh);
            CPASYNC16(d + P_BL, sl);
        }
        CPCOMMIT();
    };

    issue(0, 0);
    for (int ck = 0; ck < NCH; ck++) {
        const int s = ck & 1;
        if (ck + 1 < NCH) { issue(ck + 1, s ^ 1); CPWAIT(1); }
        else              { CPWAIT(0); }
        __syncthreads();

        const uint32_t st = sb + s * PSTAGE;
        #pragma unroll
        for (int ks = 0; ks < 2; ks++) {
            const int kB = ks * 32;
            uint32_t a_h[2][4], a_l[2][4];
            #pragma unroll
            for (int ms = 0; ms < 2; ms++) {
                uint32_t ra = st + (wm + ms * 16 + a_row) * PROWB + kB + a_k16;
                ldmx4(a_h[ms], ra);
                ldmx4(a_l[ms], ra + P_AL);
            }
            #pragma unroll
            for (int np = 0; np < 4; np++) {
                uint32_t rb = st + (wn + np * 16 + b_row) * PROWB + kB + b_k16;
                uint32_t b_h[4], b_l[4];
                ldmx4(b_h, rb + P_BH);
                ldmx4(b_l, rb + P_BL);
                #pragma unroll
                for (int ms = 0; ms < 2; ms++) {
                    #pragma unroll
                    for (int nh = 0; nh < 2; nh++) {
                        float* d = acc[ms][np * 2 + nh];
                        mma16816(d, a_h[ms], b_h + 2 * nh);
                        mma16816(d, a_h[ms], b_l + 2 * nh);
                        mma16816(d, a_l[ms], b_h + 2 * nh);
                    }
                }
            }
        }
        __syncthreads();
    }

    const int jq = lane >> 2, cq = (lane & 3) * 2;
    #pragma unroll
    for (int ms = 0; ms < 2; ms++) {
        int o0r = m0 + wm + ms * 16 + jq;
        float b0 = bias[o0r], b1 = bias[o0r + 8];
        __half* row0 = g_xh16 + ((size_t)b * CDIM + o0r) * NPIX;
        __half* row1 = g_xh16 + ((size_t)b * CDIM + o0r + 8) * NPIX;
        #pragma unroll
        for (int ni = 0; ni < 8; ni++) {
            int n = n0 + wn + ni * 8 + cq;
            float* a4 = acc[ms][ni];
            __half h00 = __float2half_rn(a4[0] + b0);
            __half h01 = __float2half_rn(a4[1] + b0);
            __half h10 = __float2half_rn(a4[2] + b1);
            __half h11 = __float2half_rn(a4[3] + b1);
            *(uint32_t*)(row0 + n) = ((uint32_t)__half_as_ushort(h01) << 16) | __half_as_ushort(h00);
            *(uint32_t*)(row1 + n) = ((uint32_t)__half_as_ushort(h11) << 16) | __half_as_ushort(h10);
        }
    }
}

// ============================================================================
// Kernel 2a: zero l
// ============================================================================
__global__ void zero_l_kernel() {
    int t = blockIdx.x * blockDim.x + threadIdx.x;
    if (t < BATCH * NPIX) g_l[t] = 0.0f;
}

// ============================================================================
// Kernel 2b: scores, BM=128 j per CTA (xf stream traffic halved).
// A (xg) 128 rows hi + 128 lo resident; B (xf) 128-i tiles double-buffered.
// smem: A 20480 + 2 B-stages 40960 + pstage 34816 = 96256 B.
// ============================================================================
#define SROWB 80
#define S2A_BYTES 20480
#define S2A_LO 10240
#define S2B_LO 10240
#define S2B_STAGE 20480
#define S2PST_OFF (S2A_BYTES + 2 * S2B_STAGE)   // 61440
#define PST_ROWB 272
#define SCORE_SMEM (S2PST_OFF + 128 * PST_ROWB) // 96256

__global__ __launch_bounds__(256, 2) void score_kernel()
{
    extern __shared__ char smem[];
    const uint32_t sa = smem_u32(smem);
    const uint32_t sb0 = sa + S2A_BYTES;
    char* pst = smem + S2PST_OFF;

    const int b  = blockIdx.y;
    const int j0 = blockIdx.x * 128;
    const int t  = threadIdx.x;
    const int warp = t >> 5, lane = t & 31;
    const int mbase = (warp & 1) * 64;
    const int wn = (warp >> 1) * 32;

    const __nv_bfloat16* xfh = g_xfh + (size_t)b * NPIX * CBAR;
    const __nv_bfloat16* xfl = g_xfl + (size_t)b * NPIX * CBAR;
    const __nv_bfloat16* xgh = g_xgh + (size_t)b * NPIX * CBAR;
    const __nv_bfloat16* xgl = g_xgl + (size_t)b * NPIX * CBAR;
    __nv_bfloat16* ph = g_ph + (size_t)b * NPIX * NPIX;
    float* lrow = g_l + b * NPIX;

    // A: 256 rows (128 hi + 128 lo) x 64B -> 1024 tasks
    #pragma unroll
    for (int q = 0; q < 4; q++) {
        int id = t + q * 256;
        int r = id >> 2, g16 = id & 3;
        const __nv_bfloat16* src = ((r < 128) ? xgh : xgl) + ((size_t)(j0 + (r & 127))) * CBAR + g16 * 8;
        CPASYNC16(sa + r * SROWB + g16 * 16, src);
    }
    // B iter 0
    #pragma unroll
    for (int q = 0; q < 4; q++) {
        int id = t + q * 256;
        int r = id >> 2, g16 = id & 3;
        const __nv_bfloat16* src = ((r < 128) ? xfh : xfl) + ((size_t)(r & 127)) * CBAR + g16 * 8;
        CPASYNC16(sb0 + r * SROWB + g16 * 16, src);
    }
    CPCOMMIT();

    const int a_row = lane & 15, a_k16 = (lane >> 4) << 4;
    const int b_row = (lane & 7) + ((lane >> 4) & 1) * 8;
    const int b_k16 = ((lane >> 3) & 1) * 16;

    const int NIT = NPIX / 128;

    for (int it = 0; it < NIT; it++) {
        const int s = it & 1;
        if (it + 1 < NIT) {
            const int i0n = (it + 1) * 128;
            const uint32_t st = sb0 + (s ^ 1) * S2B_STAGE;
            #pragma unroll
            for (int q = 0; q < 4; q++) {
                int id = t + q * 256;
                int r = id >> 2, g16 = id & 3;
                const __nv_bfloat16* src = ((r < 128) ? xfh : xfl) + ((size_t)(i0n + (r & 127))) * CBAR + g16 * 8;
                CPASYNC16(st + r * SROWB + g16 * 16, src);
            }
            CPCOMMIT();
            CPWAIT(1);
        } else {
            CPWAIT(0);
        }
        __syncthreads();

        const uint32_t stg = sb0 + s * S2B_STAGE;
        float sacc[4][4][4];
        #pragma unroll
        for (int m = 0; m < 4; m++)
            #pragma unroll
            for (int n = 0; n < 4; n++)
                #pragma unroll
                for (int q = 0; q < 4; q++) sacc[m][n][q] = 0.f;

        #pragma unroll
        for (int ks = 0; ks < 2; ks++) {
            const int kB = ks * 32;
            uint32_t a_h[4][4], a_l[4][4];
            #pragma unroll
            for (int ms = 0; ms < 4; ms++) {
                uint32_t ra = sa + (mbase + ms * 16 + a_row) * SROWB + kB + a_k16;
                ldmx4(a_h[ms], ra);
                ldmx4(a_l[ms], ra + S2A_LO);
            }
            #pragma unroll
            for (int np = 0; np < 2; np++) {
                uint32_t rb = stg + (wn + np * 16 + b_row) * SROWB + kB + b_k16;
                uint32_t b_h[4], b_l[4];
                ldmx4(b_h, rb);
                ldmx4(b_l, rb + S2B_LO);
                #pragma unroll
                for (int ms = 0; ms < 4; ms++) {
                    #pragma unroll
                    for (int nh = 0; nh < 2; nh++) {
                        float* d = sacc[ms][np * 2 + nh];
                        mma16816(d, a_h[ms], b_h + 2 * nh);
                        mma16816(d, a_h[ms], b_l + 2 * nh);
                        mma16816(d, a_l[ms], b_h + 2 * nh);
                    }
                }
            }
        }

        const int i0 = it * 128;
        #pragma unroll
        for (int nn = 0; nn < 4; nn++) {
            const int icl = wn + nn * 8 + (lane & 3) * 2;
            float cs0 = 0.f, cs1 = 0.f;
            #pragma unroll
            for (int ms = 0; ms < 4; ms++) {
                float* d = sacc[ms][nn];
                float p0 = __expf(d[0]);
                float p1 = __expf(d[1]);
                float p2 = __expf(d[2]);
                float p3 = __expf(d[3]);
                cs0 += p0 + p2; cs1 += p1 + p3;
                const int jl = mbase + ms * 16 + (lane >> 2);
                uint32_t pk01 = ((uint32_t)__bfloat16_as_ushort(__float2bfloat16(p1)) << 16)
                              |  (uint32_t)__bfloat16_as_ushort(__float2bfloat16(p0));
                uint32_t pk23 = ((uint32_t)__bfloat16_as_ushort(__float2bfloat16(p3)) << 16)
                              |  (uint32_t)__bfloat16_as_ushort(__float2bfloat16(p2));
                *(uint32_t*)(pst + jl * PST_ROWB + icl * 2)       = pk01;
                *(uint32_t*)(pst + (jl + 8) * PST_ROWB + icl * 2) = pk23;
            }
            #pragma unroll
            for (int off = 4; off <= 16; off <<= 1) {
                cs0 += __shfl_xor_sync(0xffffffffu, cs0, off);
                cs1 += __shfl_xor_sync(0xffffffffu, cs1, off);
            }
            if (lane < 4) {
                atomicAdd(lrow + i0 + icl, cs0);
                atomicAdd(lrow + i0 + icl + 1, cs1);
            }
        }
        __syncthreads();

        // coalesced store: 128 rows x 256B = 2048 tasks
        #pragma unroll
        for (int q = 0; q < 8; q++) {
            int id = q * 256 + t;
            int jl = id >> 4, w16 = id & 15;
            uint4 v = *(uint4*)(pst + jl * PST_ROWB + w16 * 16);
            *(uint4*)(ph + (size_t)(j0 + jl) * NPIX + i0 + w16 * 8) = v;
        }
        __syncthreads();
    }
}

// ============================================================================
// Kernel 2c: finalize.  invl = 1/l.
// ============================================================================
__global__ __launch_bounds__(256) void finalize_kernel()
{
    int idx = blockIdx.x * blockDim.x + threadIdx.x;
    if (idx < BATCH * NPIX) g_invl[idx] = 1.0f / g_l[idx];
}

// ============================================================================
// Kernel 3: output GEMM, fp16 mma, beta fused into A-path, BK=64
// (half the syncs vs BK=32).  144B rows: ldmatrix conflict-free.
// smem: A 18432 + B 36864 per stage, x2 + invl 16384 = 126976 B.
// ============================================================================
#define ROWB2 144
#define G_OFF_A 0
#define G_OFF_B 18432
#define G_STAGE 55296
#define G_INVL (2 * G_STAGE)
#define GEMM_SMEM (G_INVL + NPIX * 4)

__global__ __launch_bounds__(512, 1) void out_gemm_mma(
    const float* __restrict__ x, const float* __restrict__ gamma,
    float* __restrict__ out)
{
    extern __shared__ char smem[];
    const uint32_t sb = smem_u32(smem);
    float* sinvl = (float*)(smem + G_INVL);

    const int b  = blockIdx.y;
    const int m0 = blockIdx.x * 128;
    const int t  = threadIdx.x;
    const int warp = t >> 5, lane = t & 31;
    const int wm = (warp & 3) * 32;
    const int wn = (warp >> 2) * 64;

    const __nv_bfloat16* pb = g_ph + (size_t)b * NPIX * NPIX;
    const __half* xh = g_xh16 + (size_t)b * CDIM * NPIX;
    const float* invl = g_invl + b * NPIX;

    float acc[2][8][4];
    #pragma unroll
    for (int i = 0; i < 2; i++)
        #pragma unroll
        for (int j = 0; j < 8; j++)
            #pragma unroll
            for (int q = 0; q < 4; q++) acc[i][j][q] = 0.f;

    const int a_row = lane & 15, a_k16 = (lane >> 4) << 4;
    const int b_row = (lane & 7) + ((lane >> 4) & 1) * 8;
    const int b_k16 = ((lane >> 3) & 1) * 16;

    const int NCH = NPIX / 64;   // 64 chunks of 64 i

    // A load task coords: 1024 tasks (128 rows x 8 16B-groups), 2 per thread
    const int ar0 = t >> 3, ag0 = t & 7;
    const int ar1 = (t + 512) >> 3, ag1 = (t + 512) & 7;

    // convert+STS one A chunk (2 tasks) into stage st
    auto convA = [&](uint4* areg, int i0, uint32_t st) {
        #pragma unroll
        for (int q = 0; q < 2; q++) {
            int r = q ? ar1 : ar0, g = q ? ag1 : ag0;
            const uint32_t* aw = (const uint32_t*)&areg[q];
            float iv[8];
            #pragma unroll
            for (int k = 0; k < 8; k++) iv[k] = sinvl[i0 + g * 8 + k];
            uint32_t w[4];
            #pragma unroll
            for (int p = 0; p < 4; p++) {
                float lo = __bfloat162float(__ushort_as_bfloat16((unsigned short)(aw[p] & 0xFFFF)));
                float hi = __bfloat162float(__ushort_as_bfloat16((unsigned short)(aw[p] >> 16)));
                __half h0 = __float2half_rn(lo * iv[p * 2]);
                __half h1 = __float2half_rn(hi * iv[p * 2 + 1]);
                w[p] = ((uint32_t)__half_as_ushort(h1) << 16) | (uint32_t)__half_as_ushort(h0);
            }
            *(uint4*)((char*)smem + (st - smem_u32(smem)) + r * ROWB2 + g * 16 + G_OFF_A) = *(uint4*)w;
        }
    };

    // ---- prologue ----
    {
        int vi = t * 8;
        *(float4*)(sinvl + vi)     = *(const float4*)(invl + vi);
        *(float4*)(sinvl + vi + 4) = *(const float4*)(invl + vi + 4);
    }
    uint4 areg[2];
    areg[0] = *(const uint4*)(pb + (size_t)(m0 + ar0) * NPIX + ag0 * 8);
    areg[1] = *(const uint4*)(pb + (size_t)(m0 + ar1) * NPIX + ag1 * 8);
    {
        const uint32_t st = sb;
        #pragma unroll
        for (int q = 0; q < 4; q++) {   // B: 2048 tasks
            int id = t + q * 512;
            int r = id >> 3, g = id & 7;
            CPASYNC16(st + r * ROWB2 + g * 16 + G_OFF_B, xh + (size_t)r * NPIX + g * 8);
        }
        CPCOMMIT();
    }
    __syncthreads();
    convA(areg, 0, sb);

    for (int kt = 0; kt < NCH; kt++) {
        const int s = kt & 1;
        const int i0n = (kt + 1) * 64;
        if (kt + 1 < NCH) {
            areg[0] = *(const uint4*)(pb + (size_t)(m0 + ar0) * NPIX + i0n + ag0 * 8);
            areg[1] = *(const uint4*)(pb + (size_t)(m0 + ar1) * NPIX + i0n + ag1 * 8);
            const uint32_t st = sb + (s ^ 1) * G_STAGE;
            #pragma unroll
            for (int q = 0; q < 4; q++) {
                int id = t + q * 512;
                int r = id >> 3, g = id & 7;
                CPASYNC16(st + r * ROWB2 + g * 16 + G_OFF_B, xh + (size_t)r * NPIX + i0n + g * 8);
            }
            CPCOMMIT();
            CPWAIT(1);
        } else {
            CPWAIT(0);
        }
        __syncthreads();

        const uint32_t st = sb + s * G_STAGE;
        #pragma unroll
        for (int ks = 0; ks < 4; ks++) {
            const int kB = ks * 32;
            uint32_t a_f[2][4];
            #pragma unroll
            for (int ms = 0; ms < 2; ms++) {
                uint32_t ra = st + (wm + ms * 16 + a_row) * ROWB2 + kB + a_k16;
                ldmx4(a_f[ms], ra + G_OFF_A);
            }
            #pragma unroll
            for (int np = 0; np < 4; np++) {
                uint32_t rb = st + (wn + np * 16 + b_row) * ROWB2 + kB + b_k16;
                uint32_t b_f[4];
                ldmx4(b_f, rb + G_OFF_B);
                #pragma unroll
                for (int ms = 0; ms < 2; ms++) {
                    #pragma unroll
                    for (int nh = 0; nh < 2; nh++) {
                        mma16816h(acc[ms][np * 2 + nh], a_f[ms], b_f + 2 * nh);
                    }
                }
            }
        }

        if (kt + 1 < NCH) {
            convA(areg, i0n, sb + (s ^ 1) * G_STAGE);
        }
        __syncthreads();
    }

    // epilogue: out[c][j] = x[c][j] + g * D^T[j][c]
    const float g = gamma[0];
    const float* xb = x   + (size_t)b * CDIM * NPIX;
    float*       ob = out + (size_t)b * CDIM * NPIX;
    const int jq = lane >> 2, cq = (lane & 3) * 2;

    #pragma unroll
    for (int ms = 0; ms < 2; ms++) {
        #pragma unroll
        for (int ni = 0; ni < 8; ni++) {
            int j = m0 + wm + ms * 16 + jq;
            int c = wn + ni * 8 + cq;
            float* a4 = acc[ms][ni];
            ob[(size_t)c * NPIX + j]            = xb[(size_t)c * NPIX + j]            + g * a4[0];
            ob[(size_t)(c + 1) * NPIX + j]      = xb[(size_t)(c + 1) * NPIX + j]      + g * a4[1];
            ob[(size_t)c * NPIX + j + 8]        = xb[(size_t)c * NPIX + j + 8]        + g * a4[2];
            ob[(size_t)(c + 1) * NPIX + j + 8]  = xb[(size_t)(c + 1) * NPIX + j + 8]  + g * a4[3];
        }
    }
}

// ============================================================================
extern "C" void kernel_launch(void* const* d_in, const int* in_sizes, int n_in,
                              void* d_out, int out_size)
{
    const float* x     = (const float*)d_in[0];
    const float* Wf    = (const float*)d_in[1];
    const float* bf    = (const float*)d_in[2];
    const float* Wg    = (const float*)d_in[3];
    const float* bg    = (const float*)d_in[4];
    const float* Wh    = (const float*)d_in[5];
    const float* bh    = (const float*)d_in[6];
    const float* gamma = (const float*)d_in[7];
    float* out = (float*)d_out;

    (void)in_sizes; (void)n_in; (void)out_size;

    cudaFuncSetAttribute(out_gemm_mma, cudaFuncAttributeMaxDynamicSharedMemorySize,
                         GEMM_SMEM);
    cudaFuncSetAttribute(score_kernel, cudaFuncAttributeMaxDynamicSharedMemorySize,
                         SCORE_SMEM);
    cudaFuncSetAttribute(proj_tc_kernel, cudaFuncAttributeMaxDynamicSharedMemorySize,
                         2 * PSTAGE);

    dim3 blk(256);
    zero_l_kernel<<<(BATCH * NPIX + 255) / 256, blk>>>();
    conv_w_kernel<<<CDIM * CDIM / 1024, blk>>>(Wh);
    conv_xt_kernel<<<dim3(NPIX / 128, CDIM / 32, BATCH), blk>>>(x);
    proj_fg_kernel<<<dim3(NPIX / 128, 1, BATCH), blk>>>(Wf, bf, Wg, bg, x);
    proj_tc_kernel<<<dim3(NPIX / 256, CDIM / 128, BATCH), 512, 2 * PSTAGE>>>(bh);
    score_kernel<<<dim3(NPIX / 128, BATCH), blk, SCORE_SMEM>>>();
    finalize_kernel<<<(BATCH * NPIX + 255) / 256, blk>>>();
    out_gemm_mma<<<dim3(NPIX / 128, BATCH), 512, GEMM_SMEM>>>(x, gamma, out);
}

// round 15
// speedup vs baseline: 3.7187x; 1.0271x over previous
#include <cuda_runtime.h>
#include <cuda_bf16.h>
#include <cuda_fp16.h>
#include <math.h>
#include <stdint.h>

#define NPIX 4096
#define CDIM 256
#define CBAR 32
#define BATCH 8

// ---- scratch (device globals; no runtime allocation) ----
__device__ float g_l[BATCH * NPIX];
__device__ float g_invl[BATCH * NPIX];
__device__ __nv_bfloat16 g_xfh[BATCH * NPIX * CBAR];           // [b][n][c] hi
__device__ __nv_bfloat16 g_xfl[BATCH * NPIX * CBAR];
__device__ __nv_bfloat16 g_xgh[BATCH * NPIX * CBAR];
__device__ __nv_bfloat16 g_xgl[BATCH * NPIX * CBAR];
__device__ __nv_bfloat16 g_whh[CDIM * CDIM];                   // Wh hi [o][c]
__device__ __nv_bfloat16 g_whl[CDIM * CDIM];
__device__ __nv_bfloat16 g_xth[BATCH * NPIX * CDIM];           // x^T hi [b][n][c]
__device__ __nv_bfloat16 g_xtl[BATCH * NPIX * CDIM];
__device__ __nv_bfloat16 g_ph[(size_t)BATCH * NPIX * NPIX];    // 256 MB: bf16(exp(S^T)) [b][j][i]
__device__ __half g_xh16[BATCH * CDIM * NPIX];                 // fp16(xh) [b][c][i]

// ---- base-ISA helpers (sm_80+) ----
__device__ __forceinline__ uint32_t smem_u32(const void* p) {
    uint32_t a;
    asm("{ .reg .u64 t; cvta.to.shared.u64 t, %1; cvt.u32.u64 %0, t; }" : "=r"(a) : "l"(p));
    return a;
}
#define CPASYNC16(d, s) asm volatile("cp.async.cg.shared.global [%0], [%1], 16;" :: "r"(d), "l"(s) : "memory")
#define CPCOMMIT()      asm volatile("cp.async.commit_group;" ::: "memory")
#define CPWAIT(n)       asm volatile("cp.async.wait_group %0;" :: "n"(n) : "memory")

__device__ __forceinline__ void ldmx4(uint32_t* r, uint32_t addr) {
    asm volatile("ldmatrix.sync.aligned.m8n8.x4.shared.b16 {%0,%1,%2,%3}, [%4];"
                 : "=r"(r[0]), "=r"(r[1]), "=r"(r[2]), "=r"(r[3]) : "r"(addr));
}
__device__ __forceinline__ void mma16816(float* d, const uint32_t* a, const uint32_t* b) {
    asm volatile("mma.sync.aligned.m16n8k16.row.col.f32.bf16.bf16.f32 "
                 "{%0,%1,%2,%3}, {%4,%5,%6,%7}, {%8,%9}, {%0,%1,%2,%3};"
                 : "+f"(d[0]), "+f"(d[1]), "+f"(d[2]), "+f"(d[3])
                 : "r"(a[0]), "r"(a[1]), "r"(a[2]), "r"(a[3]), "r"(b[0]), "r"(b[1]));
}
__device__ __forceinline__ void mma16816h(float* d, const uint32_t* a, const uint32_t* b) {
    asm volatile("mma.sync.aligned.m16n8k16.row.col.f32.f16.f16.f32 "
                 "{%0,%1,%2,%3}, {%4,%5,%6,%7}, {%8,%9}, {%0,%1,%2,%3};"
                 : "+f"(d[0]), "+f"(d[1]), "+f"(d[2]), "+f"(d[3])
                 : "r"(a[0]), "r"(a[1]), "r"(a[2]), "r"(a[3]), "r"(b[0]), "r"(b[1]));
}
__device__ __forceinline__ void pack_hilo(float v, __nv_bfloat16* hi, __nv_bfloat16* lo) {
    __nv_bfloat16 h = __float2bfloat16(v);
    *hi = h;
    *lo = __float2bfloat16(v - __bfloat162float(h));
}

// ============================================================================
// Kernel 0: setup — zero l AND convert Wh -> bf16 hi/lo, one launch.
// ids [0, 32768): zero g_l; ids [32768, 49152): Wh 4-elem convert.
// grid 192 x 256.
// ============================================================================
__global__ __launch_bounds__(256) void setup_kernel(const float* __restrict__ W)
{
    int id = blockIdx.x * 256 + threadIdx.x;
    if (id < BATCH * NPIX) {
        g_l[id] = 0.0f;
    } else {
        int idx = (id - BATCH * NPIX) * 4;      // 0 .. 65532
        float4 w = *(const float4*)(W + idx);
        ushort4 h4, l4;
        float v[4] = {w.x, w.y, w.z, w.w};
        #pragma unroll
        for (int q = 0; q < 4; q++) {
            __nv_bfloat16 h, l;
            pack_hilo(v[q], &h, &l);
            ((unsigned short*)&h4)[q] = __bfloat16_as_ushort(h);
            ((unsigned short*)&l4)[q] = __bfloat16_as_ushort(l);
        }
        *(ushort4*)(g_whh + idx) = h4;
        *(ushort4*)(g_whl + idx) = l4;
    }
}

// ============================================================================
// Kernel 1: FUSED f+g projections + x transpose-convert.  x streamed ONCE:
// each 32c x 128n tile feeds (a) the f/g FFMA compute and (b) the x^T bf16
// hi/lo store that conv_xt used to do in a separate 128 MB pass.
// ============================================================================
__global__ __launch_bounds__(256) void proj_fg_kernel(
    const float* __restrict__ Wf, const float* __restrict__ bf,
    const float* __restrict__ Wg, const float* __restrict__ bg,
    const float* __restrict__ x)
{
    __shared__ float Ws[64][33];
    __shared__ float Xs[32][132];

    const int b  = blockIdx.z;
    const int n0 = blockIdx.x * 128;
    const int t  = threadIdx.x;
    const int tx = t & 31;
    const int ty = t >> 5;

    const float* xb = x + (size_t)b * CDIM * NPIX;

    float af[4][4] = {};
    float ag[4][4] = {};

    for (int k0 = 0; k0 < CDIM; k0 += 32) {
        #pragma unroll
        for (int q = 0; q < 2; q++) {
            int id = t + q * 256;
            int row = id >> 3, c4 = (id & 7) << 2;
            const float* src = (row < 32) ? (Wf + (size_t)row * CDIM)
                                          : (Wg + (size_t)(row - 32) * CDIM);
            float4 w4 = *(const float4*)(src + k0 + c4);
            Ws[row][c4 + 0] = w4.x; Ws[row][c4 + 1] = w4.y;
            Ws[row][c4 + 2] = w4.z; Ws[row][c4 + 3] = w4.w;
        }
        #pragma unroll
        for (int p = 0; p < 4; p++) {
            int idx = t + p * 256;
            int r = idx >> 5, c4 = (idx & 31) << 2;
            *(float4*)&Xs[r][c4] = *(const float4*)(xb + (size_t)(k0 + r) * NPIX + n0 + c4);
        }
        __syncthreads();

        // f/g FFMA
        #pragma unroll
        for (int k = 0; k < 32; k++) {
            float4 bv = *(float4*)&Xs[k][tx * 4];
            #pragma unroll
            for (int i = 0; i < 4; i++) {
                float wf = Ws[ty * 4 + i][k];
                float wg = Ws[32 + ty * 4 + i][k];
                af[i][0] += wf * bv.x; af[i][1] += wf * bv.y; af[i][2] += wf * bv.z; af[i][3] += wf * bv.w;
                ag[i][0] += wg * bv.x; ag[i][1] += wg * bv.y; ag[i][2] += wg * bv.z; ag[i][3] += wg * bv.w;
            }
        }

        // transpose-convert this c-block of x -> g_xth/g_xtl  (was conv_xt)
        #pragma unroll
        for (int p = 0; p < 4; p++) {
            int idx = t + p * 256;                 // 1024 tasks: 128 n x 8 c-groups
            int n = idx & 127, cg = idx >> 7;
            ushort4 h4, l4;
            #pragma unroll
            for (int j = 0; j < 4; j++) {
                __nv_bfloat16 h, l;
                pack_hilo(Xs[cg * 4 + j][n], &h, &l);
                ((unsigned short*)&h4)[j] = __bfloat16_as_ushort(h);
                ((unsigned short*)&l4)[j] = __bfloat16_as_ushort(l);
            }
            size_t off = ((size_t)b * NPIX + n0 + n) * CDIM + k0 + cg * 4;
            *(ushort4*)(g_xth + off) = h4;
            *(ushort4*)(g_xtl + off) = l4;
        }
        __syncthreads();
    }

    float bbf[4], bbg[4];
    #pragma unroll
    for (int i = 0; i < 4; i++) { bbf[i] = bf[ty * 4 + i]; bbg[i] = bg[ty * 4 + i]; }
    #pragma unroll
    for (int j = 0; j < 4; j++) {
        int n = n0 + tx * 4 + j;
        ushort4 fh4, fl4, gh4, gl4;
        #pragma unroll
        for (int i = 0; i < 4; i++) {
            __nv_bfloat16 h, l;
            pack_hilo(af[i][j] + bbf[i], &h, &l);
            ((unsigned short*)&fh4)[i] = __bfloat16_as_ushort(h);
            ((unsigned short*)&fl4)[i] = __bfloat16_as_ushort(l);
            pack_hilo(ag[i][j] + bbg[i], &h, &l);
            ((unsigned short*)&gh4)[i] = __bfloat16_as_ushort(h);
            ((unsigned short*)&gl4)[i] = __bfloat16_as_ushort(l);
        }
        size_t off = ((size_t)b * NPIX + n) * CBAR + ty * 4;
        *(ushort4*)(g_xfh + off) = fh4;
        *(ushort4*)(g_xfl + off) = fl4;
        *(ushort4*)(g_xgh + off) = gh4;
        *(ushort4*)(g_xgl + off) = gl4;
    }
}

// ============================================================================
// Kernel 1b: h-projection on tensor cores (unchanged; validated).
// ============================================================================
#define PROWB 80
#define P_AL 10240
#define P_BH 20480
#define P_BL 40960
#define PSTAGE 61440

__global__ __launch_bounds__(512, 1) void proj_tc_kernel(const float* __restrict__ bias)
{
    extern __shared__ char smem[];
    const uint32_t sb = smem_u32(smem);

    const int b  = blockIdx.z;
    const int m0 = blockIdx.y * 128;
    const int n0 = blockIdx.x * 256;
    const int t  = threadIdx.x;
    const int warp = t >> 5, lane = t & 31;
    const int wm = (warp & 3) * 32;
    const int wn = (warp >> 2) * 64;

    const __nv_bfloat16* bth = g_xth + (size_t)b * NPIX * CDIM;
    const __nv_bfloat16* btl = g_xtl + (size_t)b * NPIX * CDIM;

    float acc[2][8][4];
    #pragma unroll
    for (int i = 0; i < 2; i++)
        #pragma unroll
        for (int j = 0; j < 8; j++)
            #pragma unroll
            for (int q = 0; q < 4; q++) acc[i][j][q] = 0.f;

    const int a_row = lane & 15, a_k16 = (lane >> 4) << 4;
    const int b_row = (lane & 7) + ((lane >> 4) & 1) * 8;
    const int b_k16 = ((lane >> 3) & 1) * 16;

    const int NCH = CDIM / 32;

    auto issue = [&](int ck, int s) {
        const uint32_t st = sb + s * PSTAGE;
        const int k0 = ck * 32;
        {
            int r = t >> 2, g = t & 3;
            const __nv_bfloat16* sh = g_whh + (size_t)(m0 + r) * CDIM + k0 + g * 8;
            const __nv_bfloat16* sl = g_whl + (size_t)(m0 + r) * CDIM + k0 + g * 8;
            uint32_t d = st + r * PROWB + g * 16;
            CPASYNC16(d, sh);
            CPASYNC16(d + P_AL, sl);
        }
        #pragma unroll
        for (int q = 0; q < 2; q++) {
            int id = t + q * 512;
            int r = id >> 2, g = id & 3;
            const __nv_bfloat16* sh = bth + (size_t)(n0 + r) * CDIM + k0 + g * 8;
            const __nv_bfloat16* sl = btl + (size_t)(n0 + r) * CDIM + k0 + g * 8;
            uint32_t d = st + r * PROWB + g * 16;
            CPASYNC16(d + P_BH, sh);
            CPASYNC16(d + P_BL, sl);
        }
        CPCOMMIT();
    };

    issue(0, 0);
    for (int ck = 0; ck < NCH; ck++) {
        const int s = ck & 1;
        if (ck + 1 < NCH) { issue(ck + 1, s ^ 1); CPWAIT(1); }
        else              { CPWAIT(0); }
        __syncthreads();

        const uint32_t st = sb + s * PSTAGE;
        #pragma unroll
        for (int ks = 0; ks < 2; ks++) {
            const int kB = ks * 32;
            uint32_t a_h[2][4], a_l[2][4];
            #pragma unroll
            for (int ms = 0; ms < 2; ms++) {
                uint32_t ra = st + (wm + ms * 16 + a_row) * PROWB + kB + a_k16;
                ldmx4(a_h[ms], ra);
                ldmx4(a_l[ms], ra + P_AL);
            }
            #pragma unroll
            for (int np = 0; np < 4; np++) {
                uint32_t rb = st + (wn + np * 16 + b_row) * PROWB + kB + b_k16;
                uint32_t b_h[4], b_l[4];
                ldmx4(b_h, rb + P_BH);
                ldmx4(b_l, rb + P_BL);
                #pragma unroll
                for (int ms = 0; ms < 2; ms++) {
                    #pragma unroll
                    for (int nh = 0; nh < 2; nh++) {
                        float* d = acc[ms][np * 2 + nh];
                        mma16816(d, a_h[ms], b_h + 2 * nh);
                        mma16816(d, a_h[ms], b_l + 2 * nh);
                        mma16816(d, a_l[ms], b_h + 2 * nh);
                    }
                }
            }
        }
        __syncthreads();
    }

    const int jq = lane >> 2, cq = (lane & 3) * 2;
    #pragma unroll
    for (int ms = 0; ms < 2; ms++) {
        int o0r = m0 + wm + ms * 16 + jq;
        float b0 = bias[o0r], b1 = bias[o0r + 8];
        __half* row0 = g_xh16 + ((size_t)b * CDIM + o0r) * NPIX;
        __half* row1 = g_xh16 + ((size_t)b * CDIM + o0r + 8) * NPIX;
        #pragma unroll
        for (int ni = 0; ni < 8; ni++) {
            int n = n0 + wn + ni * 8 + cq;
            float* a4 = acc[ms][ni];
            __half h00 = __float2half_rn(a4[0] + b0);
            __half h01 = __float2half_rn(a4[1] + b0);
            __half h10 = __float2half_rn(a4[2] + b1);
            __half h11 = __float2half_rn(a4[3] + b1);
            *(uint32_t*)(row0 + n) = ((uint32_t)__half_as_ushort(h01) << 16) | __half_as_ushort(h00);
            *(uint32_t*)(row1 + n) = ((uint32_t)__half_as_ushort(h11) << 16) | __half_as_ushort(h10);
        }
    }
}

// ============================================================================
// Kernel 2b: scores, BM=128 (unchanged R14; validated).
// ============================================================================
#define SROWB 80
#define S2A_BYTES 20480
#define S2A_LO 10240
#define S2B_LO 10240
#define S2B_STAGE 20480
#define S2PST_OFF (S2A_BYTES + 2 * S2B_STAGE)
#define PST_ROWB 272
#define SCORE_SMEM (S2PST_OFF + 128 * PST_ROWB)

__global__ __launch_bounds__(256, 2) void score_kernel()
{
    extern __shared__ char smem[];
    const uint32_t sa = smem_u32(smem);
    const uint32_t sb0 = sa + S2A_BYTES;
    char* pst = smem + S2PST_OFF;

    const int b  = blockIdx.y;
    const int j0 = blockIdx.x * 128;
    const int t  = threadIdx.x;
    const int warp = t >> 5, lane = t & 31;
    const int mbase = (warp & 1) * 64;
    const int wn = (warp >> 1) * 32;

    const __nv_bfloat16* xfh = g_xfh + (size_t)b * NPIX * CBAR;
    const __nv_bfloat16* xfl = g_xfl + (size_t)b * NPIX * CBAR;
    const __nv_bfloat16* xgh = g_xgh + (size_t)b * NPIX * CBAR;
    const __nv_bfloat16* xgl = g_xgl + (size_t)b * NPIX * CBAR;
    __nv_bfloat16* ph = g_ph + (size_t)b * NPIX * NPIX;
    float* lrow = g_l + b * NPIX;

    #pragma unroll
    for (int q = 0; q < 4; q++) {
        int id = t + q * 256;
        int r = id >> 2, g16 = id & 3;
        const __nv_bfloat16* src = ((r < 128) ? xgh : xgl) + ((size_t)(j0 + (r & 127))) * CBAR + g16 * 8;
        CPASYNC16(sa + r * SROWB + g16 * 16, src);
    }
    #pragma unroll
    for (int q = 0; q < 4; q++) {
        int id = t + q * 256;
        int r = id >> 2, g16 = id & 3;
        const __nv_bfloat16* src = ((r < 128) ? xfh : xfl) + ((size_t)(r & 127)) * CBAR + g16 * 8;
        CPASYNC16(sb0 + r * SROWB + g16 * 16, src);
    }
    CPCOMMIT();

    const int a_row = lane & 15, a_k16 = (lane >> 4) << 4;
    const int b_row = (lane & 7) + ((lane >> 4) & 1) * 8;
    const int b_k16 = ((lane >> 3) & 1) * 16;

    const int NIT = NPIX / 128;

    for (int it = 0; it < NIT; it++) {
        const int s = it & 1;
        if (it + 1 < NIT) {
            const int i0n = (it + 1) * 128;
            const uint32_t st = sb0 + (s ^ 1) * S2B_STAGE;
            #pragma unroll
            for (int q = 0; q < 4; q++) {
                int id = t + q * 256;
                int r = id >> 2, g16 = id & 3;
                const __nv_bfloat16* src = ((r < 128) ? xfh : xfl) + ((size_t)(i0n + (r & 127))) * CBAR + g16 * 8;
                CPASYNC16(st + r * SROWB + g16 * 16, src);
            }
            CPCOMMIT();
            CPWAIT(1);
        } else {
            CPWAIT(0);
        }
        __syncthreads();

        const uint32_t stg = sb0 + s * S2B_STAGE;
        float sacc[4][4][4];
        #pragma unroll
        for (int m = 0; m < 4; m++)
            #pragma unroll
            for (int n = 0; n < 4; n++)
                #pragma unroll
                for (int q = 0; q < 4; q++) sacc[m][n][q] = 0.f;

        #pragma unroll
        for (int ks = 0; ks < 2; ks++) {
            const int kB = ks * 32;
            uint32_t a_h[4][4], a_l[4][4];
            #pragma unroll
            for (int ms = 0; ms < 4; ms++) {
                uint32_t ra = sa + (mbase + ms * 16 + a_row) * SROWB + kB + a_k16;
                ldmx4(a_h[ms], ra);
                ldmx4(a_l[ms], ra + S2A_LO);
            }
            #pragma unroll
            for (int np = 0; np < 2; np++) {
                uint32_t rb = stg + (wn + np * 16 + b_row) * SROWB + kB + b_k16;
                uint32_t b_h[4], b_l[4];
                ldmx4(b_h, rb);
                ldmx4(b_l, rb + S2B_LO);
                #pragma unroll
                for (int ms = 0; ms < 4; ms++) {
                    #pragma unroll
                    for (int nh = 0; nh < 2; nh++) {
                        float* d = sacc[ms][np * 2 + nh];
                        mma16816(d, a_h[ms], b_h + 2 * nh);
                        mma16816(d, a_h[ms], b_l + 2 * nh);
                        mma16816(d, a_l[ms], b_h + 2 * nh);
                    }
                }
            }
        }

        const int i0 = it * 128;
        #pragma unroll
        for (int nn = 0; nn < 4; nn++) {
            const int icl = wn + nn * 8 + (lane & 3) * 2;
            float cs0 = 0.f, cs1 = 0.f;
            #pragma unroll
            for (int ms = 0; ms < 4; ms++) {
                float* d = sacc[ms][nn];
                float p0 = __expf(d[0]);
                float p1 = __expf(d[1]);
                float p2 = __expf(d[2]);
                float p3 = __expf(d[3]);
                cs0 += p0 + p2; cs1 += p1 + p3;
                const int jl = mbase + ms * 16 + (lane >> 2);
                uint32_t pk01 = ((uint32_t)__bfloat16_as_ushort(__float2bfloat16(p1)) << 16)
                              |  (uint32_t)__bfloat16_as_ushort(__float2bfloat16(p0));
                uint32_t pk23 = ((uint32_t)__bfloat16_as_ushort(__float2bfloat16(p3)) << 16)
                              |  (uint32_t)__bfloat16_as_ushort(__float2bfloat16(p2));
                *(uint32_t*)(pst + jl * PST_ROWB + icl * 2)       = pk01;
                *(uint32_t*)(pst + (jl + 8) * PST_ROWB + icl * 2) = pk23;
            }
            #pragma unroll
            for (int off = 4; off <= 16; off <<= 1) {
                cs0 += __shfl_xor_sync(0xffffffffu, cs0, off);
                cs1 += __shfl_xor_sync(0xffffffffu, cs1, off);
            }
            if (lane < 4) {
                atomicAdd(lrow + i0 + icl, cs0);
                atomicAdd(lrow + i0 + icl + 1, cs1);
            }
        }
        __syncthreads();

        #pragma unroll
        for (int q = 0; q < 8; q++) {
            int id = q * 256 + t;
            int jl = id >> 4, w16 = id & 15;
            uint4 v = *(uint4*)(pst + jl * PST_ROWB + w16 * 16);
            *(uint4*)(ph + (size_t)(j0 + jl) * NPIX + i0 + w16 * 8) = v;
        }
        __syncthreads();
    }
}

// ============================================================================
// Kernel 2c: finalize.  invl = 1/l.
// ============================================================================
__global__ __launch_bounds__(256) void finalize_kernel()
{
    int idx = blockIdx.x * blockDim.x + threadIdx.x;
    if (idx < BATCH * NPIX) g_invl[idx] = 1.0f / g_l[idx];
}

// ============================================================================
// Kernel 3: output GEMM, fp16 mma, beta fused into A-path, BK=64
// (unchanged R14; validated, at MMA floor).
// ============================================================================
#define ROWB2 144
#define G_OFF_A 0
#define G_OFF_B 18432
#define G_STAGE 55296
#define G_INVL (2 * G_STAGE)
#define GEMM_SMEM (G_INVL + NPIX * 4)

__global__ __launch_bounds__(512, 1) void out_gemm_mma(
    const float* __restrict__ x, const float* __restrict__ gamma,
    float* __restrict__ out)
{
    extern __shared__ char smem[];
    const uint32_t sb = smem_u32(smem);
    float* sinvl = (float*)(smem + G_INVL);

    const int b  = blockIdx.y;
    const int m0 = blockIdx.x * 128;
    const int t  = threadIdx.x;
    const int warp = t >> 5, lane = t & 31;
    const int wm = (warp & 3) * 32;
    const int wn = (warp >> 2) * 64;

    const __nv_bfloat16* pb = g_ph + (size_t)b * NPIX * NPIX;
    const __half* xh = g_xh16 + (size_t)b * CDIM * NPIX;
    const float* invl = g_invl + b * NPIX;

    float acc[2][8][4];
    #pragma unroll
    for (int i = 0; i < 2; i++)
        #pragma unroll
        for (int j = 0; j < 8; j++)
            #pragma unroll
            for (int q = 0; q < 4; q++) acc[i][j][q] = 0.f;

    const int a_row = lane & 15, a_k16 = (lane >> 4) << 4;
    const int b_row = (lane & 7) + ((lane >> 4) & 1) * 8;
    const int b_k16 = ((lane >> 3) & 1) * 16;

    const int NCH = NPIX / 64;

    const int ar0 = t >> 3, ag0 = t & 7;
    const int ar1 = (t + 512) >> 3, ag1 = (t + 512) & 7;

    auto convA = [&](uint4* areg, int i0, uint32_t st) {
        #pragma unroll
        for (int q = 0; q < 2; q++) {
            int r = q ? ar1 : ar0, g = q ? ag1 : ag0;
            const uint32_t* aw = (const uint32_t*)&areg[q];
            float iv[8];
            #pragma unroll
            for (int k = 0; k < 8; k++) iv[k] = sinvl[i0 + g * 8 + k];
            uint32_t w[4];
            #pragma unroll
            for (int p = 0; p < 4; p++) {
                float lo = __bfloat162float(__ushort_as_bfloat16((unsigned short)(aw[p] & 0xFFFF)));
                float hi = __bfloat162float(__ushort_as_bfloat16((unsigned short)(aw[p] >> 16)));
                __half h0 = __float2half_rn(lo * iv[p * 2]);
                __half h1 = __float2half_rn(hi * iv[p * 2 + 1]);
                w[p] = ((uint32_t)__half_as_ushort(h1) << 16) | (uint32_t)__half_as_ushort(h0);
            }
            *(uint4*)((char*)smem + (st - smem_u32(smem)) + r * ROWB2 + g * 16 + G_OFF_A) = *(uint4*)w;
        }
    };

    {
        int vi = t * 8;
        *(float4*)(sinvl + vi)     = *(const float4*)(invl + vi);
        *(float4*)(sinvl + vi + 4) = *(const float4*)(invl + vi + 4);
    }
    uint4 areg[2];
    areg[0] = *(const uint4*)(pb + (size_t)(m0 + ar0) * NPIX + ag0 * 8);
    areg[1] = *(const uint4*)(pb + (size_t)(m0 + ar1) * NPIX + ag1 * 8);
    {
        const uint32_t st = sb;
        #pragma unroll
        for (int q = 0; q < 4; q++) {
            int id = t + q * 512;
            int r = id >> 3, g = id & 7;
            CPASYNC16(st + r * ROWB2 + g * 16 + G_OFF_B, xh + (size_t)r * NPIX + g * 8);
        }
        CPCOMMIT();
    }
    __syncthreads();
    convA(areg, 0, sb);

    for (int kt = 0; kt < NCH; kt++) {
        const int s = kt & 1;
        const int i0n = (kt + 1) * 64;
        if (kt + 1 < NCH) {
            areg[0] = *(const uint4*)(pb + (size_t)(m0 + ar0) * NPIX + i0n + ag0 * 8);
            areg[1] = *(const uint4*)(pb + (size_t)(m0 + ar1) * NPIX + i0n + ag1 * 8);
            const uint32_t st = sb + (s ^ 1) * G_STAGE;
            #pragma unroll
            for (int q = 0; q < 4; q++) {
                int id = t + q * 512;
                int r = id >> 3, g = id & 7;
                CPASYNC16(st + r * ROWB2 + g * 16 + G_OFF_B, xh + (size_t)r * NPIX + i0n + g * 8);
            }
            CPCOMMIT();
            CPWAIT(1);
        } else {
            CPWAIT(0);
        }
        __syncthreads();

        const uint32_t st = sb + s * G_STAGE;
        #pragma unroll
        for (int ks = 0; ks < 4; ks++) {
            const int kB = ks * 32;
            uint32_t a_f[2][4];
            #pragma unroll
            for (int ms = 0; ms < 2; ms++) {
                uint32_t ra = st + (wm + ms * 16 + a_row) * ROWB2 + kB + a_k16;
                ldmx4(a_f[ms], ra + G_OFF_A);
            }
            #pragma unroll
            for (int np = 0; np < 4; np++) {
                uint32_t rb = st + (wn + np * 16 + b_row) * ROWB2 + kB + b_k16;
                uint32_t b_f[4];
                ldmx4(b_f, rb + G_OFF_B);
                #pragma unroll
                for (int ms = 0; ms < 2; ms++) {
                    #pragma unroll
                    for (int nh = 0; nh < 2; nh++) {
                        mma16816h(acc[ms][np * 2 + nh], a_f[ms], b_f + 2 * nh);
                    }
                }
            }
        }

        if (kt + 1 < NCH) {
            convA(areg, i0n, sb + (s ^ 1) * G_STAGE);
        }
        __syncthreads();
    }

    const float g = gamma[0];
    const float* xb = x   + (size_t)b * CDIM * NPIX;
    float*       ob = out + (size_t)b * CDIM * NPIX;
    const int jq = lane >> 2, cq = (lane & 3) * 2;

    #pragma unroll
    for (int ms = 0; ms < 2; ms++) {
        #pragma unroll
        for (int ni = 0; ni < 8; ni++) {
            int j = m0 + wm + ms * 16 + jq;
            int c = wn + ni * 8 + cq;
            float* a4 = acc[ms][ni];
            ob[(size_t)c * NPIX + j]            = xb[(size_t)c * NPIX + j]            + g * a4[0];
            ob[(size_t)(c + 1) * NPIX + j]      = xb[(size_t)(c + 1) * NPIX + j]      + g * a4[1];
            ob[(size_t)c * NPIX + j + 8]        = xb[(size_t)c * NPIX + j + 8]        + g * a4[2];
            ob[(size_t)(c + 1) * NPIX + j + 8]  = xb[(size_t)(c + 1) * NPIX + j + 8]  + g * a4[3];
        }
    }
}

// ============================================================================
extern "C" void kernel_launch(void* const* d_in, const int* in_sizes, int n_in,
                              void* d_out, int out_size)
{
    const float* x     = (const float*)d_in[0];
    const float* Wf    = (const float*)d_in[1];
    const float* bf    = (const float*)d_in[2];
    const float* Wg    = (const float*)d_in[3];
    const float* bg    = (const float*)d_in[4];
    const float* Wh    = (const float*)d_in[5];
    const float* bh    = (const float*)d_in[6];
    const float* gamma = (const float*)d_in[7];
    float* out = (float*)d_out;

    (void)in_sizes; (void)n_in; (void)out_size;

    cudaFuncSetAttribute(out_gemm_mma, cudaFuncAttributeMaxDynamicSharedMemorySize,
                         GEMM_SMEM);
    cudaFuncSetAttribute(score_kernel, cudaFuncAttributeMaxDynamicSharedMemorySize,
                         SCORE_SMEM);
    cudaFuncSetAttribute(proj_tc_kernel, cudaFuncAttributeMaxDynamicSharedMemorySize,
                         2 * PSTAGE);

    dim3 blk(256);
    setup_kernel<<<(BATCH * NPIX + CDIM * CDIM / 4 + 255) / 256, blk>>>(Wh);
    proj_fg_kernel<<<dim3(NPIX / 128, 1, BATCH), blk>>>(Wf, bf, Wg, bg, x);
    proj_tc_kernel<<<dim3(NPIX / 256, CDIM / 128, BATCH), 512, 2 * PSTAGE>>>(bh);
    score_kernel<<<dim3(NPIX / 128, BATCH), blk, SCORE_SMEM>>>();
    finalize_kernel<<<(BATCH * NPIX + 255) / 256, blk>>>();
    out_gemm_mma<<<dim3(NPIX / 128, BATCH), 512, GEMM_SMEM>>>(x, gamma, out);
}